// round 2
// baseline (speedup 1.0000x reference)
#include <cuda_runtime.h>
#include <math.h>

#define N_TOK 4096
#define DIM   1024
#define NH    16
#define HD    64

// ---------------- scratch (device globals; no allocation allowed) ----------
__device__ float g_q[N_TOK * DIM];
__device__ float g_k[N_TOK * DIM];
__device__ float g_v[N_TOK * DIM];
__device__ float g_attn[N_TOK * DIM];
__device__ float g_x[N_TOK * DIM];
__device__ float g_t[N_TOK * (DIM / 2)];
__device__ float g_cw[N_TOK];
__device__ float g_relmean[N_TOK * 3];

// ---------------- generic 128x128x8 fp32 GEMM, fused epilogue --------------
// C[M,N] = A[M,K] @ B[K,N] + bias[N]  (+ res, or SiLU)
// EPI: 0 = bias, 1 = bias + residual add, 2 = bias + SiLU
template <int EPI>
__global__ __launch_bounds__(256)
void sgemm128(const float* __restrict__ A, const float* __restrict__ B,
              const float* __restrict__ bias, const float* __restrict__ res,
              float* __restrict__ C, int M, int N, int K)
{
    __shared__ float As[8][128];
    __shared__ float Bs[8][128];

    const int tid  = threadIdx.x;
    const int brow = blockIdx.y * 128;
    const int bcol = blockIdx.x * 128;

    const int trow = (tid / 16) * 8;
    const int tcol = (tid % 16) * 8;

    const int aRow = tid / 2;            // 0..127
    const int aCol = (tid % 2) * 4;      // 0 or 4
    const int bRow = tid / 32;           // 0..7
    const int bCol = (tid % 32) * 4;     // 0..124

    float acc[8][8];
#pragma unroll
    for (int i = 0; i < 8; i++)
#pragma unroll
        for (int j = 0; j < 8; j++) acc[i][j] = 0.f;

    const float* Aptr = A + (size_t)(brow + aRow) * K + aCol;
    const float* Bptr = B + (size_t)bRow * N + bcol + bCol;

    for (int k0 = 0; k0 < K; k0 += 8) {
        float4 a = *(const float4*)(Aptr + k0);
        As[aCol + 0][aRow] = a.x;
        As[aCol + 1][aRow] = a.y;
        As[aCol + 2][aRow] = a.z;
        As[aCol + 3][aRow] = a.w;
        *(float4*)&Bs[bRow][bCol] = *(const float4*)(Bptr + (size_t)k0 * N);
        __syncthreads();

#pragma unroll
        for (int kk = 0; kk < 8; kk++) {
            float ar[8], br[8];
#pragma unroll
            for (int i = 0; i < 8; i++) ar[i] = As[kk][trow + i];
#pragma unroll
            for (int j = 0; j < 8; j++) br[j] = Bs[kk][tcol + j];
#pragma unroll
            for (int i = 0; i < 8; i++)
#pragma unroll
                for (int j = 0; j < 8; j++)
                    acc[i][j] = fmaf(ar[i], br[j], acc[i][j]);
        }
        __syncthreads();
    }

#pragma unroll
    for (int i = 0; i < 8; i++) {
        const int row = brow + trow + i;
#pragma unroll
        for (int j = 0; j < 8; j += 4) {
            const int col = bcol + tcol + j;
            float4 o;
            o.x = acc[i][j + 0] + bias[col + 0];
            o.y = acc[i][j + 1] + bias[col + 1];
            o.z = acc[i][j + 2] + bias[col + 2];
            o.w = acc[i][j + 3] + bias[col + 3];
            if (EPI == 1) {
                const float4 r = *(const float4*)&res[(size_t)row * N + col];
                o.x += r.x; o.y += r.y; o.z += r.z; o.w += r.w;
            }
            if (EPI == 2) {
                o.x = o.x / (1.f + __expf(-o.x));
                o.y = o.y / (1.f + __expf(-o.y));
                o.z = o.z / (1.f + __expf(-o.z));
                o.w = o.w / (1.f + __expf(-o.w));
            }
            *(float4*)&C[(size_t)row * N + col] = o;
        }
    }
}

// ---------------- fused attention (softmax over HEADS axis) ----------------
// Block: 16 n-rows, 256 threads; thread t -> (n_local = t>>4, head = t&15).
// q row (64 f) + output acc (64 f) in registers. k/v tiles of 16 m-rows in
// smem; per-(mm,head) segment stride of 68 floats makes LDS.128 reads
// conflict-free (phase of 8 lanes hits banks 4h mod 32 = distinct quads).
#define AT_STRIDE 68                       // floats per head segment
#define AT_ROW    (NH * AT_STRIDE)         // 1088 floats per m-row
#define AT_SMEM   (2 * 16 * AT_ROW * 4)    // 139264 bytes

__global__ __launch_bounds__(256, 1)
void attn_kernel(const float* __restrict__ Q, const float* __restrict__ K,
                 const float* __restrict__ V, float* __restrict__ O)
{
    extern __shared__ float sm[];
    float* ks = sm;
    float* vs = sm + 16 * AT_ROW;

    const int tid = threadIdx.x;
    const int nl  = tid >> 4;
    const int h   = tid & 15;
    const int n   = blockIdx.x * 16 + nl;

    float qr[64], acc[64];
    const float4* qp = (const float4*)(Q + (size_t)n * DIM + h * HD);
#pragma unroll
    for (int i = 0; i < 16; i++) {
        float4 t = qp[i];
        qr[4 * i + 0] = t.x * 0.125f;   // fold 1/sqrt(HD)
        qr[4 * i + 1] = t.y * 0.125f;
        qr[4 * i + 2] = t.z * 0.125f;
        qr[4 * i + 3] = t.w * 0.125f;
        acc[4 * i + 0] = 0.f; acc[4 * i + 1] = 0.f;
        acc[4 * i + 2] = 0.f; acc[4 * i + 3] = 0.f;
    }

    for (int m0 = 0; m0 < N_TOK; m0 += 16) {
#pragma unroll
        for (int it = 0; it < 16; it++) {
            const int g   = tid + 256 * it;       // float4 index, 0..4095
            const int mm  = g >> 8;               // m-row in tile
            const int hh  = (g >> 4) & 15;        // head
            const int dd  = (g & 15) * 4;         // dim within head
            const int so  = mm * AT_ROW + hh * AT_STRIDE + dd;
            const size_t go = (size_t)(m0 + mm) * DIM + hh * HD + dd;
            *(float4*)&ks[so] = *(const float4*)&K[go];
            *(float4*)&vs[so] = *(const float4*)&V[go];
        }
        __syncthreads();

#pragma unroll 4
        for (int mm = 0; mm < 16; mm++) {
            const float4* kp = (const float4*)&ks[mm * AT_ROW + h * AT_STRIDE];
            float s = 0.f;
#pragma unroll
            for (int i = 0; i < 16; i++) {
                float4 t = kp[i];
                s = fmaf(qr[4 * i + 0], t.x, s);
                s = fmaf(qr[4 * i + 1], t.y, s);
                s = fmaf(qr[4 * i + 2], t.z, s);
                s = fmaf(qr[4 * i + 3], t.w, s);
            }
            // softmax over the 16 heads = the 16-lane group
            float mx = s;
#pragma unroll
            for (int off = 1; off < 16; off <<= 1)
                mx = fmaxf(mx, __shfl_xor_sync(0xffffffffu, mx, off));
            float e = __expf(s - mx);
            float sum = e;
#pragma unroll
            for (int off = 1; off < 16; off <<= 1)
                sum += __shfl_xor_sync(0xffffffffu, sum, off);
            const float p = e / sum;

            const float4* vp = (const float4*)&vs[mm * AT_ROW + h * AT_STRIDE];
#pragma unroll
            for (int i = 0; i < 16; i++) {
                float4 t = vp[i];
                acc[4 * i + 0] = fmaf(p, t.x, acc[4 * i + 0]);
                acc[4 * i + 1] = fmaf(p, t.y, acc[4 * i + 1]);
                acc[4 * i + 2] = fmaf(p, t.z, acc[4 * i + 2]);
                acc[4 * i + 3] = fmaf(p, t.w, acc[4 * i + 3]);
            }
        }
        __syncthreads();
    }

    float4* op = (float4*)(O + (size_t)n * DIM + h * HD);
#pragma unroll
    for (int i = 0; i < 16; i++)
        op[i] = make_float4(acc[4 * i], acc[4 * i + 1], acc[4 * i + 2], acc[4 * i + 3]);
}

// ---------------- LayerNorm: one block per row ------------------------------
__global__ __launch_bounds__(256)
void ln_kernel(const float* __restrict__ X, const float* __restrict__ w,
               const float* __restrict__ b, float* __restrict__ out)
{
    const int n   = blockIdx.x;
    const int tid = threadIdx.x;
    const float4 x = ((const float4*)(X + (size_t)n * DIM))[tid];

    float s  = x.x + x.y + x.z + x.w;
    float ss = x.x * x.x + x.y * x.y + x.z * x.z + x.w * x.w;
#pragma unroll
    for (int off = 16; off; off >>= 1) {
        s  += __shfl_xor_sync(0xffffffffu, s, off);
        ss += __shfl_xor_sync(0xffffffffu, ss, off);
    }
    __shared__ float rs[8], rss[8], stat[2];
    if ((tid & 31) == 0) { rs[tid >> 5] = s; rss[tid >> 5] = ss; }
    __syncthreads();
    if (tid == 0) {
        float S = 0.f, SS = 0.f;
#pragma unroll
        for (int i = 0; i < 8; i++) { S += rs[i]; SS += rss[i]; }
        const float mean = S * (1.f / DIM);
        const float var  = SS * (1.f / DIM) - mean * mean;
        stat[0] = mean;
        stat[1] = rsqrtf(var + 1e-5f);
    }
    __syncthreads();
    const float mean = stat[0], inv = stat[1];
    const int col = tid * 4;
    const float4 wv = *(const float4*)&w[col];
    const float4 bv = *(const float4*)&b[col];
    float4 o;
    o.x = (x.x - mean) * inv * wv.x + bv.x;
    o.y = (x.y - mean) * inv * wv.y + bv.y;
    o.z = (x.z - mean) * inv * wv.z + bv.z;
    o.w = (x.w - mean) * inv * wv.w + bv.w;
    ((float4*)(out + (size_t)n * DIM))[tid] = o;
}

// ---------------- coord MLP second layer: warp per row ----------------------
__global__ void mlp2_kernel(const float* __restrict__ T, const float* __restrict__ W2,
                            const float* __restrict__ b2, float* __restrict__ cw)
{
    const int warp = (blockIdx.x * blockDim.x + threadIdx.x) >> 5;
    const int lane = threadIdx.x & 31;
    if (warp >= N_TOK) return;
    const float* t = T + (size_t)warp * (DIM / 2);
    float s = 0.f;
#pragma unroll
    for (int j = 0; j < DIM / 2; j += 32) s = fmaf(t[j + lane], W2[j + lane], s);
#pragma unroll
    for (int off = 16; off; off >>= 1) s += __shfl_xor_sync(0xffffffffu, s, off);
    if (lane == 0) cw[warp] = s + b2[0];
}

// ---------------- mean over axis 1 of rel_pos [N,N,3] -----------------------
__global__ __launch_bounds__(128)
void relmean_kernel(const float* __restrict__ rel, float* __restrict__ out)
{
    const int n   = blockIdx.x;
    const int tid = threadIdx.x;
    const float* base = rel + (size_t)n * N_TOK * 3;
    float s0 = 0.f, s1 = 0.f, s2 = 0.f;
    for (int m = tid; m < N_TOK; m += 128) {
        s0 += base[m * 3 + 0];
        s1 += base[m * 3 + 1];
        s2 += base[m * 3 + 2];
    }
#pragma unroll
    for (int off = 16; off; off >>= 1) {
        s0 += __shfl_xor_sync(0xffffffffu, s0, off);
        s1 += __shfl_xor_sync(0xffffffffu, s1, off);
        s2 += __shfl_xor_sync(0xffffffffu, s2, off);
    }
    __shared__ float sm[3][4];
    if ((tid & 31) == 0) {
        sm[0][tid >> 5] = s0; sm[1][tid >> 5] = s1; sm[2][tid >> 5] = s2;
    }
    __syncthreads();
    if (tid == 0) {
        out[n * 3 + 0] = (sm[0][0] + sm[0][1] + sm[0][2] + sm[0][3]) * (1.f / N_TOK);
        out[n * 3 + 1] = (sm[1][0] + sm[1][1] + sm[1][2] + sm[1][3]) * (1.f / N_TOK);
        out[n * 3 + 2] = (sm[2][0] + sm[2][1] + sm[2][2] + sm[2][3]) * (1.f / N_TOK);
    }
}

// ---------------- pos_update = cw * rel_mean --------------------------------
__global__ void posupd_kernel(const float* __restrict__ cw, const float* __restrict__ rm,
                              float* __restrict__ out)
{
    const int i = blockIdx.x * blockDim.x + threadIdx.x;
    if (i < N_TOK * 3) out[i] = cw[i / 3] * rm[i];
}

// ---------------- launcher ---------------------------------------------------
extern "C" void kernel_launch(void* const* d_in, const int* in_sizes, int n_in,
                              void* d_out, int out_size)
{
    const float* h    = (const float*)d_in[0];
    const float* rel  = (const float*)d_in[1];
    const float* Wq   = (const float*)d_in[2];
    const float* bq   = (const float*)d_in[3];
    const float* Wk   = (const float*)d_in[4];
    const float* bk   = (const float*)d_in[5];
    const float* Wv   = (const float*)d_in[6];
    const float* bv   = (const float*)d_in[7];
    const float* Wo   = (const float*)d_in[8];
    const float* bo   = (const float*)d_in[9];
    const float* W1   = (const float*)d_in[10];
    const float* b1   = (const float*)d_in[11];
    const float* W2   = (const float*)d_in[12];
    const float* b2   = (const float*)d_in[13];
    const float* lnw  = (const float*)d_in[14];
    const float* lnb  = (const float*)d_in[15];
    float* out = (float*)d_out;

    float *q, *k, *v, *attn, *x, *t, *cw, *rm;
    cudaGetSymbolAddress((void**)&q,    g_q);
    cudaGetSymbolAddress((void**)&k,    g_k);
    cudaGetSymbolAddress((void**)&v,    g_v);
    cudaGetSymbolAddress((void**)&attn, g_attn);
    cudaGetSymbolAddress((void**)&x,    g_x);
    cudaGetSymbolAddress((void**)&t,    g_t);
    cudaGetSymbolAddress((void**)&cw,   g_cw);
    cudaGetSymbolAddress((void**)&rm,   g_relmean);

    cudaFuncSetAttribute(attn_kernel, cudaFuncAttributeMaxDynamicSharedMemorySize, AT_SMEM);

    const dim3 gFull(DIM / 128, N_TOK / 128);        // (8, 32)
    const dim3 gHalf((DIM / 2) / 128, N_TOK / 128);  // (4, 32)

    // rel_pos mean (independent)
    relmean_kernel<<<N_TOK, 128>>>(rel, rm);

    // QKV projections
    sgemm128<0><<<gFull, 256>>>(h, Wq, bq, nullptr, q, N_TOK, DIM, DIM);
    sgemm128<0><<<gFull, 256>>>(h, Wk, bk, nullptr, k, N_TOK, DIM, DIM);
    sgemm128<0><<<gFull, 256>>>(h, Wv, bv, nullptr, v, N_TOK, DIM, DIM);

    // fused attention (softmax over heads)
    attn_kernel<<<N_TOK / 16, 256, AT_SMEM>>>(q, k, v, attn);

    // output projection + residual
    sgemm128<1><<<gFull, 256>>>(attn, Wo, bo, h, x, N_TOK, DIM, DIM);

    // layernorm -> hn (first N*D elems of output)
    ln_kernel<<<N_TOK, 256>>>(x, lnw, lnb, out);

    // coord MLP
    sgemm128<2><<<gHalf, 256>>>(out, W1, b1, nullptr, t, N_TOK, DIM / 2, DIM);
    mlp2_kernel<<<(N_TOK * 32) / 256, 256>>>(t, W2, b2, cw);

    // pos_update (last N*3 elems of output)
    posupd_kernel<<<(N_TOK * 3 + 255) / 256, 256>>>(cw, rm, out + (size_t)N_TOK * DIM);
}

// round 4
// speedup vs baseline: 1.1011x; 1.1011x over previous
#include <cuda_runtime.h>
#include <math.h>

#define N_TOK 4096
#define DIM   1024
#define NH    16
#define HD    64

typedef unsigned long long ull;

// ---------------- f32x2 helpers (SASS FFMA2 — PTX-only) ---------------------
__device__ __forceinline__ ull ffma2(ull a, ull b, ull c) {
    ull d;
    asm("fma.rn.f32x2 %0, %1, %2, %3;" : "=l"(d) : "l"(a), "l"(b), "l"(c));
    return d;
}
__device__ __forceinline__ ull pack2(float lo, float hi) {
    ull r;
    asm("mov.b64 %0, {%1, %2};" : "=l"(r) : "f"(lo), "f"(hi));
    return r;
}
__device__ __forceinline__ float2 unpack2(ull v) {
    float lo, hi;
    asm("mov.b64 {%0, %1}, %2;" : "=f"(lo), "=f"(hi) : "l"(v));
    return make_float2(lo, hi);
}

// ---------------- scratch (device globals; no allocation allowed) ----------
__device__ float g_q[N_TOK * DIM];
__device__ float g_k[N_TOK * DIM];
__device__ float g_v[N_TOK * DIM];
__device__ float g_attn[N_TOK * DIM];
__device__ float g_x[N_TOK * DIM];
__device__ float g_t[N_TOK * (DIM / 2)];
__device__ float g_cw[N_TOK];
__device__ float g_relmean[N_TOK * 3];

// ---------------- 128x128x8 fp32 GEMM with FFMA2 microkernel ----------------
// C[M,N] = A[M,K] @ B[K,N] + bias[N]  (+ res, or SiLU)
// EPI: 0 = bias, 1 = bias + residual add, 2 = bias + SiLU
template <int EPI>
__global__ __launch_bounds__(256)
void sgemm128(const float* __restrict__ A, const float* __restrict__ B,
              const float* __restrict__ bias, const float* __restrict__ res,
              float* __restrict__ C, int M, int N, int K)
{
    __shared__ float As[8][128];
    __shared__ float Bs[8][128];

    const int tid  = threadIdx.x;
    const int brow = blockIdx.y * 128;
    const int bcol = blockIdx.x * 128;

    const int trow = (tid / 16) * 8;
    const int tcol = (tid % 16) * 8;

    const int aRow = tid / 2;            // 0..127
    const int aCol = (tid % 2) * 4;      // 0 or 4
    const int bRow = tid / 32;           // 0..7
    const int bCol = (tid % 32) * 4;     // 0..124

    ull acc2[8][4];                      // acc2[i][j2] = (c[i][2j2], c[i][2j2+1])
#pragma unroll
    for (int i = 0; i < 8; i++)
#pragma unroll
        for (int j = 0; j < 4; j++) acc2[i][j] = 0ull;

    const float* Aptr = A + (size_t)(brow + aRow) * K + aCol;
    const float* Bptr = B + (size_t)bRow * N + bcol + bCol;

    for (int k0 = 0; k0 < K; k0 += 8) {
        float4 a = *(const float4*)(Aptr + k0);
        As[aCol + 0][aRow] = a.x;
        As[aCol + 1][aRow] = a.y;
        As[aCol + 2][aRow] = a.z;
        As[aCol + 3][aRow] = a.w;
        *(float4*)&Bs[bRow][bCol] = *(const float4*)(Bptr + (size_t)k0 * N);
        __syncthreads();

#pragma unroll
        for (int kk = 0; kk < 8; kk++) {
            const float4 a0 = *(const float4*)&As[kk][trow];
            const float4 a1 = *(const float4*)&As[kk][trow + 4];
            const ulonglong2 b01 = *(const ulonglong2*)&Bs[kk][tcol];
            const ulonglong2 b23 = *(const ulonglong2*)&Bs[kk][tcol + 4];
            ull bb[4] = { b01.x, b01.y, b23.x, b23.y };
            float ar[8] = { a0.x, a0.y, a0.z, a0.w, a1.x, a1.y, a1.z, a1.w };
#pragma unroll
            for (int i = 0; i < 8; i++) {
                const ull ad = pack2(ar[i], ar[i]);
#pragma unroll
                for (int j = 0; j < 4; j++)
                    acc2[i][j] = ffma2(ad, bb[j], acc2[i][j]);
            }
        }
        __syncthreads();
    }

#pragma unroll
    for (int i = 0; i < 8; i++) {
        const int row = brow + trow + i;
#pragma unroll
        for (int j = 0; j < 2; j++) {
            const int col = bcol + tcol + j * 4;
            const float2 p0 = unpack2(acc2[i][2 * j + 0]);
            const float2 p1 = unpack2(acc2[i][2 * j + 1]);
            float4 o;
            o.x = p0.x + bias[col + 0];
            o.y = p0.y + bias[col + 1];
            o.z = p1.x + bias[col + 2];
            o.w = p1.y + bias[col + 3];
            if (EPI == 1) {
                const float4 r = *(const float4*)&res[(size_t)row * N + col];
                o.x += r.x; o.y += r.y; o.z += r.z; o.w += r.w;
            }
            if (EPI == 2) {
                o.x = o.x / (1.f + __expf(-o.x));
                o.y = o.y / (1.f + __expf(-o.y));
                o.z = o.z / (1.f + __expf(-o.z));
                o.w = o.w / (1.f + __expf(-o.w));
            }
            *(float4*)&C[(size_t)row * N + col] = o;
        }
    }
}

// ---------------- fused attention (softmax over HEADS axis) ----------------
// Block: 16 n-rows, 256 threads; thread t -> (n_local = t>>4, head = t&15).
// q row + acc held as f32x2 pairs in registers. Scores are computed for 8
// m-rows at a time BEFORE the softmax shuffles so the 8 independent
// reduction chains interleave (hides SHFL latency at 2 warps/SMSP).
// NOTE: each head segment = 64 floats = 16 ulonglong2 loads (R2 bug: used 8).
#define AT_STRIDE 68                       // floats per head segment
#define AT_ROW    (NH * AT_STRIDE)         // 1088 floats per m-row
#define AT_SMEM   (2 * 16 * AT_ROW * 4)    // 139264 bytes

__global__ __launch_bounds__(256, 1)
void attn_kernel(const float* __restrict__ Q, const float* __restrict__ K,
                 const float* __restrict__ V, float* __restrict__ O)
{
    extern __shared__ float sm[];
    float* ks = sm;
    float* vs = sm + 16 * AT_ROW;

    const int tid = threadIdx.x;
    const int nl  = tid >> 4;
    const int h   = tid & 15;
    const int n   = blockIdx.x * 16 + nl;

    ull q2[32], acc2[32];
    const float4* qp = (const float4*)(Q + (size_t)n * DIM + h * HD);
#pragma unroll
    for (int i = 0; i < 16; i++) {
        float4 t = qp[i];
        q2[2 * i + 0] = pack2(t.x * 0.125f, t.y * 0.125f);  // fold 1/sqrt(HD)
        q2[2 * i + 1] = pack2(t.z * 0.125f, t.w * 0.125f);
        acc2[2 * i + 0] = 0ull;
        acc2[2 * i + 1] = 0ull;
    }

    for (int m0 = 0; m0 < N_TOK; m0 += 16) {
#pragma unroll
        for (int it = 0; it < 16; it++) {
            const int g   = tid + 256 * it;       // float4 index, 0..4095
            const int mm  = g >> 8;               // m-row in tile
            const int hh  = (g >> 4) & 15;        // head
            const int dd  = (g & 15) * 4;         // dim within head
            const int so  = mm * AT_ROW + hh * AT_STRIDE + dd;
            const size_t go = (size_t)(m0 + mm) * DIM + hh * HD + dd;
            *(float4*)&ks[so] = *(const float4*)&K[go];
            *(float4*)&vs[so] = *(const float4*)&V[go];
        }
        __syncthreads();

#pragma unroll
        for (int b = 0; b < 2; b++) {
            // ---- scores for 8 m-rows (full 64-dim head: 16 x 16B loads) ----
            float sc[8];
#pragma unroll
            for (int j = 0; j < 8; j++) {
                const int mm = b * 8 + j;
                const ulonglong2* kp =
                    (const ulonglong2*)&ks[mm * AT_ROW + h * AT_STRIDE];
                ull s0 = 0ull, s1 = 0ull;
#pragma unroll
                for (int i = 0; i < 16; i++) {
                    ulonglong2 t = kp[i];
                    s0 = ffma2(q2[2 * i + 0], t.x, s0);
                    s1 = ffma2(q2[2 * i + 1], t.y, s1);
                }
                const float2 f0 = unpack2(s0);
                const float2 f1 = unpack2(s1);
                sc[j] = (f0.x + f1.x) + (f0.y + f1.y);
            }

            // ---- batched softmax over the 16-lane head group ----
            float mx[8];
#pragma unroll
            for (int j = 0; j < 8; j++) mx[j] = sc[j];
#pragma unroll
            for (int off = 1; off < 16; off <<= 1)
#pragma unroll
                for (int j = 0; j < 8; j++)
                    mx[j] = fmaxf(mx[j], __shfl_xor_sync(0xffffffffu, mx[j], off));
#pragma unroll
            for (int j = 0; j < 8; j++) sc[j] = __expf(sc[j] - mx[j]);
            float sum[8];
#pragma unroll
            for (int j = 0; j < 8; j++) sum[j] = sc[j];
#pragma unroll
            for (int off = 1; off < 16; off <<= 1)
#pragma unroll
                for (int j = 0; j < 8; j++)
                    sum[j] += __shfl_xor_sync(0xffffffffu, sum[j], off);
            ull p2[8];
#pragma unroll
            for (int j = 0; j < 8; j++) {
                const float p = __fdividef(sc[j], sum[j]);
                p2[j] = pack2(p, p);
            }

            // ---- PV accumulate (full 64-dim head) ----
#pragma unroll
            for (int j = 0; j < 8; j++) {
                const int mm = b * 8 + j;
                const ulonglong2* vp =
                    (const ulonglong2*)&vs[mm * AT_ROW + h * AT_STRIDE];
#pragma unroll
                for (int i = 0; i < 16; i++) {
                    ulonglong2 t = vp[i];
                    acc2[2 * i + 0] = ffma2(p2[j], t.x, acc2[2 * i + 0]);
                    acc2[2 * i + 1] = ffma2(p2[j], t.y, acc2[2 * i + 1]);
                }
            }
        }
        __syncthreads();
    }

    float4* op = (float4*)(O + (size_t)n * DIM + h * HD);
#pragma unroll
    for (int i = 0; i < 16; i++) {
        const float2 lo = unpack2(acc2[2 * i + 0]);
        const float2 hi = unpack2(acc2[2 * i + 1]);
        op[i] = make_float4(lo.x, lo.y, hi.x, hi.y);
    }
}

// ---------------- LayerNorm: one block per row ------------------------------
__global__ __launch_bounds__(256)
void ln_kernel(const float* __restrict__ X, const float* __restrict__ w,
               const float* __restrict__ b, float* __restrict__ out)
{
    const int n   = blockIdx.x;
    const int tid = threadIdx.x;
    const float4 x = ((const float4*)(X + (size_t)n * DIM))[tid];

    float s  = x.x + x.y + x.z + x.w;
    float ss = x.x * x.x + x.y * x.y + x.z * x.z + x.w * x.w;
#pragma unroll
    for (int off = 16; off; off >>= 1) {
        s  += __shfl_xor_sync(0xffffffffu, s, off);
        ss += __shfl_xor_sync(0xffffffffu, ss, off);
    }
    __shared__ float rs[8], rss[8], stat[2];
    if ((tid & 31) == 0) { rs[tid >> 5] = s; rss[tid >> 5] = ss; }
    __syncthreads();
    if (tid == 0) {
        float S = 0.f, SS = 0.f;
#pragma unroll
        for (int i = 0; i < 8; i++) { S += rs[i]; SS += rss[i]; }
        const float mean = S * (1.f / DIM);
        const float var  = SS * (1.f / DIM) - mean * mean;
        stat[0] = mean;
        stat[1] = rsqrtf(var + 1e-5f);
    }
    __syncthreads();
    const float mean = stat[0], inv = stat[1];
    const int col = tid * 4;
    const float4 wv = *(const float4*)&w[col];
    const float4 bv = *(const float4*)&b[col];
    float4 o;
    o.x = (x.x - mean) * inv * wv.x + bv.x;
    o.y = (x.y - mean) * inv * wv.y + bv.y;
    o.z = (x.z - mean) * inv * wv.z + bv.z;
    o.w = (x.w - mean) * inv * wv.w + bv.w;
    ((float4*)(out + (size_t)n * DIM))[tid] = o;
}

// ---------------- coord MLP second layer: warp per row ----------------------
__global__ void mlp2_kernel(const float* __restrict__ T, const float* __restrict__ W2,
                            const float* __restrict__ b2, float* __restrict__ cw)
{
    const int warp = (blockIdx.x * blockDim.x + threadIdx.x) >> 5;
    const int lane = threadIdx.x & 31;
    if (warp >= N_TOK) return;
    const float* t = T + (size_t)warp * (DIM / 2);
    float s = 0.f;
#pragma unroll
    for (int j = 0; j < DIM / 2; j += 32) s = fmaf(t[j + lane], W2[j + lane], s);
#pragma unroll
    for (int off = 16; off; off >>= 1) s += __shfl_xor_sync(0xffffffffu, s, off);
    if (lane == 0) cw[warp] = s + b2[0];
}

// ---------------- mean over axis 1 of rel_pos [N,N,3] -----------------------
__global__ __launch_bounds__(128)
void relmean_kernel(const float* __restrict__ rel, float* __restrict__ out)
{
    const int n   = blockIdx.x;
    const int tid = threadIdx.x;
    const float* base = rel + (size_t)n * N_TOK * 3;
    float s0 = 0.f, s1 = 0.f, s2 = 0.f;
    for (int m = tid; m < N_TOK; m += 128) {
        s0 += base[m * 3 + 0];
        s1 += base[m * 3 + 1];
        s2 += base[m * 3 + 2];
    }
#pragma unroll
    for (int off = 16; off; off >>= 1) {
        s0 += __shfl_xor_sync(0xffffffffu, s0, off);
        s1 += __shfl_xor_sync(0xffffffffu, s1, off);
        s2 += __shfl_xor_sync(0xffffffffu, s2, off);
    }
    __shared__ float sm[3][4];
    if ((tid & 31) == 0) {
        sm[0][tid >> 5] = s0; sm[1][tid >> 5] = s1; sm[2][tid >> 5] = s2;
    }
    __syncthreads();
    if (tid == 0) {
        out[n * 3 + 0] = (sm[0][0] + sm[0][1] + sm[0][2] + sm[0][3]) * (1.f / N_TOK);
        out[n * 3 + 1] = (sm[1][0] + sm[1][1] + sm[1][2] + sm[1][3]) * (1.f / N_TOK);
        out[n * 3 + 2] = (sm[2][0] + sm[2][1] + sm[2][2] + sm[2][3]) * (1.f / N_TOK);
    }
}

// ---------------- pos_update = cw * rel_mean --------------------------------
__global__ void posupd_kernel(const float* __restrict__ cw, const float* __restrict__ rm,
                              float* __restrict__ out)
{
    const int i = blockIdx.x * blockDim.x + threadIdx.x;
    if (i < N_TOK * 3) out[i] = cw[i / 3] * rm[i];
}

// ---------------- launcher ---------------------------------------------------
extern "C" void kernel_launch(void* const* d_in, const int* in_sizes, int n_in,
                              void* d_out, int out_size)
{
    const float* h    = (const float*)d_in[0];
    const float* rel  = (const float*)d_in[1];
    const float* Wq   = (const float*)d_in[2];
    const float* bq   = (const float*)d_in[3];
    const float* Wk   = (const float*)d_in[4];
    const float* bk   = (const float*)d_in[5];
    const float* Wv   = (const float*)d_in[6];
    const float* bv   = (const float*)d_in[7];
    const float* Wo   = (const float*)d_in[8];
    const float* bo   = (const float*)d_in[9];
    const float* W1   = (const float*)d_in[10];
    const float* b1   = (const float*)d_in[11];
    const float* W2   = (const float*)d_in[12];
    const float* b2   = (const float*)d_in[13];
    const float* lnw  = (const float*)d_in[14];
    const float* lnb  = (const float*)d_in[15];
    float* out = (float*)d_out;

    float *q, *k, *v, *attn, *x, *t, *cw, *rm;
    cudaGetSymbolAddress((void**)&q,    g_q);
    cudaGetSymbolAddress((void**)&k,    g_k);
    cudaGetSymbolAddress((void**)&v,    g_v);
    cudaGetSymbolAddress((void**)&attn, g_attn);
    cudaGetSymbolAddress((void**)&x,    g_x);
    cudaGetSymbolAddress((void**)&t,    g_t);
    cudaGetSymbolAddress((void**)&cw,   g_cw);
    cudaGetSymbolAddress((void**)&rm,   g_relmean);

    cudaFuncSetAttribute(attn_kernel, cudaFuncAttributeMaxDynamicSharedMemorySize, AT_SMEM);

    const dim3 gFull(DIM / 128, N_TOK / 128);        // (8, 32)
    const dim3 gHalf((DIM / 2) / 128, N_TOK / 128);  // (4, 32)

    // rel_pos mean (independent)
    relmean_kernel<<<N_TOK, 128>>>(rel, rm);

    // QKV projections
    sgemm128<0><<<gFull, 256>>>(h, Wq, bq, nullptr, q, N_TOK, DIM, DIM);
    sgemm128<0><<<gFull, 256>>>(h, Wk, bk, nullptr, k, N_TOK, DIM, DIM);
    sgemm128<0><<<gFull, 256>>>(h, Wv, bv, nullptr, v, N_TOK, DIM, DIM);

    // fused attention (softmax over heads)
    attn_kernel<<<N_TOK / 16, 256, AT_SMEM>>>(q, k, v, attn);

    // output projection + residual
    sgemm128<1><<<gFull, 256>>>(attn, Wo, bo, h, x, N_TOK, DIM, DIM);

    // layernorm -> hn (first N*D elems of output)
    ln_kernel<<<N_TOK, 256>>>(x, lnw, lnb, out);

    // coord MLP
    sgemm128<2><<<gHalf, 256>>>(out, W1, b1, nullptr, t, N_TOK, DIM / 2, DIM);
    mlp2_kernel<<<(N_TOK * 32) / 256, 256>>>(t, W2, b2, cw);

    // pos_update (last N*3 elems of output)
    posupd_kernel<<<(N_TOK * 3 + 255) / 256, 256>>>(cw, rm, out + (size_t)N_TOK * DIM);
}

// round 5
// speedup vs baseline: 2.0067x; 1.8225x over previous
#include <cuda_runtime.h>
#include <math.h>

#define N_TOK 4096
#define DIM   1024
#define NH    16
#define HD    64

typedef unsigned long long ull;

// ---------------- f32x2 helpers (SASS FFMA2 — PTX-only) ---------------------
__device__ __forceinline__ ull ffma2(ull a, ull b, ull c) {
    ull d;
    asm("fma.rn.f32x2 %0, %1, %2, %3;" : "=l"(d) : "l"(a), "l"(b), "l"(c));
    return d;
}
__device__ __forceinline__ ull pack2(float lo, float hi) {
    ull r;
    asm("mov.b64 %0, {%1, %2};" : "=l"(r) : "f"(lo), "f"(hi));
    return r;
}
__device__ __forceinline__ float2 unpack2(ull v) {
    float lo, hi;
    asm("mov.b64 {%0, %1}, %2;" : "=f"(lo), "=f"(hi) : "l"(v));
    return make_float2(lo, hi);
}

// ---------------- scratch (device globals; no allocation allowed) ----------
__device__ float g_q[N_TOK * DIM];
__device__ float g_k[N_TOK * DIM];
__device__ float g_v[N_TOK * DIM];
__device__ float g_attn[N_TOK * DIM];
__device__ float g_x[N_TOK * DIM];
__device__ float g_t[N_TOK * (DIM / 2)];
__device__ float g_cw[N_TOK];
__device__ float g_relmean[N_TOK * 3];
__device__ float g_s[(size_t)NH * N_TOK * N_TOK];   // raw scores [h][n][m], 1 GiB

// ---------------- 128x128x8 fp32 GEMM with FFMA2 microkernel ----------------
// C[M,N] = A[M,K] @ B[K,N] + bias[N]  (+ res, or SiLU)
// EPI: 0 = bias, 1 = bias + residual add, 2 = bias + SiLU
template <int EPI>
__global__ __launch_bounds__(256)
void sgemm128(const float* __restrict__ A, const float* __restrict__ B,
              const float* __restrict__ bias, const float* __restrict__ res,
              float* __restrict__ C, int M, int N, int K)
{
    __shared__ float As[8][128];
    __shared__ float Bs[8][128];

    const int tid  = threadIdx.x;
    const int brow = blockIdx.y * 128;
    const int bcol = blockIdx.x * 128;

    const int trow = (tid / 16) * 8;
    const int tcol = (tid % 16) * 8;

    const int aRow = tid / 2;
    const int aCol = (tid % 2) * 4;
    const int bRow = tid / 32;
    const int bCol = (tid % 32) * 4;

    ull acc2[8][4];
#pragma unroll
    for (int i = 0; i < 8; i++)
#pragma unroll
        for (int j = 0; j < 4; j++) acc2[i][j] = 0ull;

    const float* Aptr = A + (size_t)(brow + aRow) * K + aCol;
    const float* Bptr = B + (size_t)bRow * N + bcol + bCol;

    for (int k0 = 0; k0 < K; k0 += 8) {
        float4 a = *(const float4*)(Aptr + k0);
        As[aCol + 0][aRow] = a.x;
        As[aCol + 1][aRow] = a.y;
        As[aCol + 2][aRow] = a.z;
        As[aCol + 3][aRow] = a.w;
        *(float4*)&Bs[bRow][bCol] = *(const float4*)(Bptr + (size_t)k0 * N);
        __syncthreads();

#pragma unroll
        for (int kk = 0; kk < 8; kk++) {
            const float4 a0 = *(const float4*)&As[kk][trow];
            const float4 a1 = *(const float4*)&As[kk][trow + 4];
            const ulonglong2 b01 = *(const ulonglong2*)&Bs[kk][tcol];
            const ulonglong2 b23 = *(const ulonglong2*)&Bs[kk][tcol + 4];
            ull bb[4] = { b01.x, b01.y, b23.x, b23.y };
            float ar[8] = { a0.x, a0.y, a0.z, a0.w, a1.x, a1.y, a1.z, a1.w };
#pragma unroll
            for (int i = 0; i < 8; i++) {
                const ull ad = pack2(ar[i], ar[i]);
#pragma unroll
                for (int j = 0; j < 4; j++)
                    acc2[i][j] = ffma2(ad, bb[j], acc2[i][j]);
            }
        }
        __syncthreads();
    }

#pragma unroll
    for (int i = 0; i < 8; i++) {
        const int row = brow + trow + i;
#pragma unroll
        for (int j = 0; j < 2; j++) {
            const int col = bcol + tcol + j * 4;
            const float2 p0 = unpack2(acc2[i][2 * j + 0]);
            const float2 p1 = unpack2(acc2[i][2 * j + 1]);
            float4 o;
            o.x = p0.x + bias[col + 0];
            o.y = p0.y + bias[col + 1];
            o.z = p1.x + bias[col + 2];
            o.w = p1.y + bias[col + 3];
            if (EPI == 1) {
                const float4 r = *(const float4*)&res[(size_t)row * N + col];
                o.x += r.x; o.y += r.y; o.z += r.z; o.w += r.w;
            }
            if (EPI == 2) {
                o.x = o.x / (1.f + __expf(-o.x));
                o.y = o.y / (1.f + __expf(-o.y));
                o.z = o.z / (1.f + __expf(-o.z));
                o.w = o.w / (1.f + __expf(-o.w));
            }
            *(float4*)&C[(size_t)row * N + col] = o;
        }
    }
}

// ---------------- Phase A: per-head scores GEMM S_h = Q_h @ K_h^T ----------
// grid (mblk=32, nblk=32, h=16), 128x128 tile, K-dim = 64.
__global__ __launch_bounds__(256)
void scores_kernel(const float* __restrict__ Q, const float* __restrict__ K,
                   float* __restrict__ S)
{
    __shared__ float As[8][128];
    __shared__ float Bs[8][128];

    const int tid = threadIdx.x;
    const int m0  = blockIdx.x * 128;
    const int n0  = blockIdx.y * 128;
    const int h   = blockIdx.z;

    const int trow = (tid / 16) * 8;
    const int tcol = (tid % 16) * 8;
    const int row  = tid / 2;
    const int jj   = (tid % 2) * 4;

    ull acc2[8][4];
#pragma unroll
    for (int i = 0; i < 8; i++)
#pragma unroll
        for (int j = 0; j < 4; j++) acc2[i][j] = 0ull;

    const float* Qp = Q + (size_t)(n0 + row) * DIM + h * HD + jj;
    const float* Kp = K + (size_t)(m0 + row) * DIM + h * HD + jj;

#pragma unroll
    for (int k0 = 0; k0 < HD; k0 += 8) {
        const float4 a = *(const float4*)(Qp + k0);
        As[jj + 0][row] = a.x;
        As[jj + 1][row] = a.y;
        As[jj + 2][row] = a.z;
        As[jj + 3][row] = a.w;
        const float4 b = *(const float4*)(Kp + k0);
        Bs[jj + 0][row] = b.x;
        Bs[jj + 1][row] = b.y;
        Bs[jj + 2][row] = b.z;
        Bs[jj + 3][row] = b.w;
        __syncthreads();

#pragma unroll
        for (int kk = 0; kk < 8; kk++) {
            const float4 a0 = *(const float4*)&As[kk][trow];
            const float4 a1 = *(const float4*)&As[kk][trow + 4];
            const ulonglong2 b01 = *(const ulonglong2*)&Bs[kk][tcol];
            const ulonglong2 b23 = *(const ulonglong2*)&Bs[kk][tcol + 4];
            ull bb[4] = { b01.x, b01.y, b23.x, b23.y };
            float ar[8] = { a0.x, a0.y, a0.z, a0.w, a1.x, a1.y, a1.z, a1.w };
#pragma unroll
            for (int i = 0; i < 8; i++) {
                const ull ad = pack2(ar[i], ar[i]);
#pragma unroll
                for (int j = 0; j < 4; j++)
                    acc2[i][j] = ffma2(ad, bb[j], acc2[i][j]);
            }
        }
        __syncthreads();
    }

    float* Sp = S + (size_t)h * N_TOK * N_TOK;
#pragma unroll
    for (int i = 0; i < 8; i++) {
        const size_t roff = (size_t)(n0 + trow + i) * N_TOK;
#pragma unroll
        for (int j = 0; j < 2; j++) {
            const float2 p0 = unpack2(acc2[i][2 * j + 0]);
            const float2 p1 = unpack2(acc2[i][2 * j + 1]);
            *(float4*)&Sp[roff + m0 + tcol + j * 4] =
                make_float4(p0.x, p0.y, p1.x, p1.y);
        }
    }
}

// ---------------- Phase C: softmax-over-heads + PV, fused -------------------
// Block = 32 n-rows (grid 128). Per 16-m tile: stage S[h][n][m] for all 16 h
// + V tile in smem; thread-local softmax over contiguous h; register-tiled PV
// (thread = (h, 4-n group, 32-d half); 64 FFMA2 per m vs 9 LDS.128).
#define PC_SPLANE 580                     // floats per h-plane: 16m*36 + 4 pad
#define PC_VROW   1088                    // 16h * 68
#define PC_SMEM   ((16 * PC_SPLANE + 16 * PC_VROW) * 4)   // 106752 B

__global__ __launch_bounds__(256, 1)
void pv_kernel(const float* __restrict__ S, const float* __restrict__ V,
               float* __restrict__ O)
{
    extern __shared__ float sm[];
    float* st = sm;                        // score/prob tiles, [h][m][n-pad36]
    float* vt = sm + 16 * PC_SPLANE;       // v tile, [m][h][68]

    const int tid = threadIdx.x;
    const int n0  = blockIdx.x * 32;
    const int h   = tid & 15;
    const int g   = (tid >> 4) & 7;        // n-group: rows 4g..4g+3
    const int dh  = tid >> 7;              // d-half: 32*dh .. 32*dh+31

    ull a2[4][16];
#pragma unroll
    for (int i = 0; i < 4; i++)
#pragma unroll
        for (int j = 0; j < 16; j++) a2[i][j] = 0ull;

    const size_t N2 = (size_t)N_TOK * N_TOK;

    for (int m0 = 0; m0 < N_TOK; m0 += 16) {
        // ---- stage scores: 512 rows of 16 floats, 2 per thread ----
#pragma unroll
        for (int r = tid; r < 512; r += 256) {
            const int hh = r >> 5, nn = r & 31;
            const float4* src =
                (const float4*)(S + (size_t)hh * N2 + (size_t)(n0 + nn) * N_TOK + m0);
            const float4 f0 = src[0], f1 = src[1], f2 = src[2], f3 = src[3];
            float* dst = st + hh * PC_SPLANE + nn;
            dst[0 * 36] = f0.x;  dst[1 * 36] = f0.y;  dst[2 * 36] = f0.z;  dst[3 * 36] = f0.w;
            dst[4 * 36] = f1.x;  dst[5 * 36] = f1.y;  dst[6 * 36] = f1.z;  dst[7 * 36] = f1.w;
            dst[8 * 36] = f2.x;  dst[9 * 36] = f2.y;  dst[10 * 36] = f2.z; dst[11 * 36] = f2.w;
            dst[12 * 36] = f3.x; dst[13 * 36] = f3.y; dst[14 * 36] = f3.z; dst[15 * 36] = f3.w;
        }
        // ---- stage V tile: 16 rows x 1024 floats ----
#pragma unroll
        for (int it = 0; it < 16; it++) {
            const int idx = it * 256 + tid;
            const int mm = idx >> 8;
            const int hh = (idx >> 4) & 15;
            const int dq = idx & 15;
            *(float4*)&vt[mm * PC_VROW + hh * 68 + dq * 4] =
                *(const float4*)&V[(size_t)(m0 + mm) * DIM + hh * HD + dq * 4];
        }
        __syncthreads();

        // ---- softmax over 16 heads, 2 (n,m) pairs per thread, in place ----
#pragma unroll
        for (int pi = 0; pi < 2; pi++) {
            const int p  = tid * 2 + pi;
            const int nn = p & 31, mm = p >> 5;
            float* base = st + mm * 36 + nn;
            float sv[16];
#pragma unroll
            for (int q = 0; q < 16; q++) sv[q] = base[q * PC_SPLANE] * 0.125f;
            float mx = sv[0];
#pragma unroll
            for (int q = 1; q < 16; q++) mx = fmaxf(mx, sv[q]);
            float ssum = 0.f;
#pragma unroll
            for (int q = 0; q < 16; q++) { sv[q] = __expf(sv[q] - mx); ssum += sv[q]; }
            const float rinv = __fdividef(1.f, ssum);
#pragma unroll
            for (int q = 0; q < 16; q++) base[q * PC_SPLANE] = sv[q] * rinv;
        }
        __syncthreads();

        // ---- PV accumulate ----
#pragma unroll
        for (int mm = 0; mm < 16; mm++) {
            const float4 pf = *(const float4*)&st[h * PC_SPLANE + mm * 36 + 4 * g];
            const ull p2[4] = { pack2(pf.x, pf.x), pack2(pf.y, pf.y),
                                pack2(pf.z, pf.z), pack2(pf.w, pf.w) };
            const float* vb = &vt[mm * PC_VROW + h * 68 + dh * 32];
#pragma unroll
            for (int dc = 0; dc < 4; dc++) {
                const ulonglong2 v01 = *(const ulonglong2*)(vb + dc * 8);
                const ulonglong2 v23 = *(const ulonglong2*)(vb + dc * 8 + 4);
#pragma unroll
                for (int i = 0; i < 4; i++) {
                    a2[i][dc * 4 + 0] = ffma2(p2[i], v01.x, a2[i][dc * 4 + 0]);
                    a2[i][dc * 4 + 1] = ffma2(p2[i], v01.y, a2[i][dc * 4 + 1]);
                    a2[i][dc * 4 + 2] = ffma2(p2[i], v23.x, a2[i][dc * 4 + 2]);
                    a2[i][dc * 4 + 3] = ffma2(p2[i], v23.y, a2[i][dc * 4 + 3]);
                }
            }
        }
        __syncthreads();
    }

    // ---- epilogue: out[n][h*64 + dh*32 + d] ----
#pragma unroll
    for (int i = 0; i < 4; i++) {
        float* dst = O + (size_t)(n0 + 4 * g + i) * DIM + h * HD + dh * 32;
#pragma unroll
        for (int dc = 0; dc < 4; dc++) {
            const float2 e0 = unpack2(a2[i][dc * 4 + 0]);
            const float2 e1 = unpack2(a2[i][dc * 4 + 1]);
            const float2 e2 = unpack2(a2[i][dc * 4 + 2]);
            const float2 e3 = unpack2(a2[i][dc * 4 + 3]);
            *(float4*)(dst + dc * 8 + 0) = make_float4(e0.x, e0.y, e1.x, e1.y);
            *(float4*)(dst + dc * 8 + 4) = make_float4(e2.x, e2.y, e3.x, e3.y);
        }
    }
}

// ---------------- LayerNorm: one block per row ------------------------------
__global__ __launch_bounds__(256)
void ln_kernel(const float* __restrict__ X, const float* __restrict__ w,
               const float* __restrict__ b, float* __restrict__ out)
{
    const int n   = blockIdx.x;
    const int tid = threadIdx.x;
    const float4 x = ((const float4*)(X + (size_t)n * DIM))[tid];

    float s  = x.x + x.y + x.z + x.w;
    float ss = x.x * x.x + x.y * x.y + x.z * x.z + x.w * x.w;
#pragma unroll
    for (int off = 16; off; off >>= 1) {
        s  += __shfl_xor_sync(0xffffffffu, s, off);
        ss += __shfl_xor_sync(0xffffffffu, ss, off);
    }
    __shared__ float rs[8], rss[8], stat[2];
    if ((tid & 31) == 0) { rs[tid >> 5] = s; rss[tid >> 5] = ss; }
    __syncthreads();
    if (tid == 0) {
        float S = 0.f, SS = 0.f;
#pragma unroll
        for (int i = 0; i < 8; i++) { S += rs[i]; SS += rss[i]; }
        const float mean = S * (1.f / DIM);
        const float var  = SS * (1.f / DIM) - mean * mean;
        stat[0] = mean;
        stat[1] = rsqrtf(var + 1e-5f);
    }
    __syncthreads();
    const float mean = stat[0], inv = stat[1];
    const int col = tid * 4;
    const float4 wv = *(const float4*)&w[col];
    const float4 bv = *(const float4*)&b[col];
    float4 o;
    o.x = (x.x - mean) * inv * wv.x + bv.x;
    o.y = (x.y - mean) * inv * wv.y + bv.y;
    o.z = (x.z - mean) * inv * wv.z + bv.z;
    o.w = (x.w - mean) * inv * wv.w + bv.w;
    ((float4*)(out + (size_t)n * DIM))[tid] = o;
}

// ---------------- coord MLP second layer: warp per row ----------------------
__global__ void mlp2_kernel(const float* __restrict__ T, const float* __restrict__ W2,
                            const float* __restrict__ b2, float* __restrict__ cw)
{
    const int warp = (blockIdx.x * blockDim.x + threadIdx.x) >> 5;
    const int lane = threadIdx.x & 31;
    if (warp >= N_TOK) return;
    const float* t = T + (size_t)warp * (DIM / 2);
    float s = 0.f;
#pragma unroll
    for (int j = 0; j < DIM / 2; j += 32) s = fmaf(t[j + lane], W2[j + lane], s);
#pragma unroll
    for (int off = 16; off; off >>= 1) s += __shfl_xor_sync(0xffffffffu, s, off);
    if (lane == 0) cw[warp] = s + b2[0];
}

// ---------------- mean over axis 1 of rel_pos [N,N,3] -----------------------
__global__ __launch_bounds__(128)
void relmean_kernel(const float* __restrict__ rel, float* __restrict__ out)
{
    const int n   = blockIdx.x;
    const int tid = threadIdx.x;
    const float* base = rel + (size_t)n * N_TOK * 3;
    float s0 = 0.f, s1 = 0.f, s2 = 0.f;
    for (int m = tid; m < N_TOK; m += 128) {
        s0 += base[m * 3 + 0];
        s1 += base[m * 3 + 1];
        s2 += base[m * 3 + 2];
    }
#pragma unroll
    for (int off = 16; off; off >>= 1) {
        s0 += __shfl_xor_sync(0xffffffffu, s0, off);
        s1 += __shfl_xor_sync(0xffffffffu, s1, off);
        s2 += __shfl_xor_sync(0xffffffffu, s2, off);
    }
    __shared__ float sm[3][4];
    if ((tid & 31) == 0) {
        sm[0][tid >> 5] = s0; sm[1][tid >> 5] = s1; sm[2][tid >> 5] = s2;
    }
    __syncthreads();
    if (tid == 0) {
        out[n * 3 + 0] = (sm[0][0] + sm[0][1] + sm[0][2] + sm[0][3]) * (1.f / N_TOK);
        out[n * 3 + 1] = (sm[1][0] + sm[1][1] + sm[1][2] + sm[1][3]) * (1.f / N_TOK);
        out[n * 3 + 2] = (sm[2][0] + sm[2][1] + sm[2][2] + sm[2][3]) * (1.f / N_TOK);
    }
}

// ---------------- pos_update = cw * rel_mean --------------------------------
__global__ void posupd_kernel(const float* __restrict__ cw, const float* __restrict__ rm,
                              float* __restrict__ out)
{
    const int i = blockIdx.x * blockDim.x + threadIdx.x;
    if (i < N_TOK * 3) out[i] = cw[i / 3] * rm[i];
}

// ---------------- launcher ---------------------------------------------------
extern "C" void kernel_launch(void* const* d_in, const int* in_sizes, int n_in,
                              void* d_out, int out_size)
{
    const float* h    = (const float*)d_in[0];
    const float* rel  = (const float*)d_in[1];
    const float* Wq   = (const float*)d_in[2];
    const float* bq   = (const float*)d_in[3];
    const float* Wk   = (const float*)d_in[4];
    const float* bk   = (const float*)d_in[5];
    const float* Wv   = (const float*)d_in[6];
    const float* bv   = (const float*)d_in[7];
    const float* Wo   = (const float*)d_in[8];
    const float* bo   = (const float*)d_in[9];
    const float* W1   = (const float*)d_in[10];
    const float* b1   = (const float*)d_in[11];
    const float* W2   = (const float*)d_in[12];
    const float* b2   = (const float*)d_in[13];
    const float* lnw  = (const float*)d_in[14];
    const float* lnb  = (const float*)d_in[15];
    float* out = (float*)d_out;

    float *q, *k, *v, *attn, *x, *t, *cw, *rm, *s;
    cudaGetSymbolAddress((void**)&q,    g_q);
    cudaGetSymbolAddress((void**)&k,    g_k);
    cudaGetSymbolAddress((void**)&v,    g_v);
    cudaGetSymbolAddress((void**)&attn, g_attn);
    cudaGetSymbolAddress((void**)&x,    g_x);
    cudaGetSymbolAddress((void**)&t,    g_t);
    cudaGetSymbolAddress((void**)&cw,   g_cw);
    cudaGetSymbolAddress((void**)&rm,   g_relmean);
    cudaGetSymbolAddress((void**)&s,    g_s);

    cudaFuncSetAttribute(pv_kernel, cudaFuncAttributeMaxDynamicSharedMemorySize, PC_SMEM);

    const dim3 gFull(DIM / 128, N_TOK / 128);        // (8, 32)
    const dim3 gHalf((DIM / 2) / 128, N_TOK / 128);  // (4, 32)

    // rel_pos mean (independent)
    relmean_kernel<<<N_TOK, 128>>>(rel, rm);

    // QKV projections
    sgemm128<0><<<gFull, 256>>>(h, Wq, bq, nullptr, q, N_TOK, DIM, DIM);
    sgemm128<0><<<gFull, 256>>>(h, Wk, bk, nullptr, k, N_TOK, DIM, DIM);
    sgemm128<0><<<gFull, 256>>>(h, Wv, bv, nullptr, v, N_TOK, DIM, DIM);

    // attention phase A: raw scores per head
    scores_kernel<<<dim3(N_TOK / 128, N_TOK / 128, NH), 256>>>(q, k, s);

    // attention phase C: softmax over heads + PV
    pv_kernel<<<N_TOK / 32, 256, PC_SMEM>>>(s, v, attn);

    // output projection + residual
    sgemm128<1><<<gFull, 256>>>(attn, Wo, bo, h, x, N_TOK, DIM, DIM);

    // layernorm -> hn (first N*D elems of output)
    ln_kernel<<<N_TOK, 256>>>(x, lnw, lnb, out);

    // coord MLP
    sgemm128<2><<<gHalf, 256>>>(out, W1, b1, nullptr, t, N_TOK, DIM / 2, DIM);
    mlp2_kernel<<<(N_TOK * 32) / 256, 256>>>(t, W2, b2, cw);

    // pos_update (last N*3 elems of output)
    posupd_kernel<<<(N_TOK * 3 + 255) / 256, 256>>>(cw, rm, out + (size_t)N_TOK * DIM);
}

// round 8
// speedup vs baseline: 2.7327x; 1.3618x over previous
#include <cuda_runtime.h>
#include <cuda_bf16.h>
#include <cstdint>
#include <math.h>

#define N_TOK 4096
#define DIM   1024
#define NH    16
#define HD    64

typedef unsigned long long ull;
typedef __nv_bfloat16 bf16;

// ===================== f32x2 helpers (fp32 pv kernel) ========================
__device__ __forceinline__ ull ffma2(ull a, ull b, ull c) {
    ull d;
    asm("fma.rn.f32x2 %0, %1, %2, %3;" : "=l"(d) : "l"(a), "l"(b), "l"(c));
    return d;
}
__device__ __forceinline__ ull pack2(float lo, float hi) {
    ull r;
    asm("mov.b64 %0, {%1, %2};" : "=l"(r) : "f"(lo), "f"(hi));
    return r;
}
__device__ __forceinline__ float2 unpack2(ull v) {
    float lo, hi;
    asm("mov.b64 {%0, %1}, %2;" : "=f"(lo), "=f"(hi) : "l"(v));
    return make_float2(lo, hi);
}

// ===================== HMMA primitives (baseline PTX, no 'a' features) ======
__device__ __forceinline__ uint32_t smem_u32(const void* p) {
    uint32_t a;
    asm("{ .reg .u64 t; cvta.to.shared.u64 t, %1; cvt.u32.u64 %0, t; }"
        : "=r"(a) : "l"(p));
    return a;
}
__device__ __forceinline__ void ldmx4(uint32_t* r, uint32_t addr) {
    asm volatile("ldmatrix.sync.aligned.m8n8.x4.shared.b16 {%0,%1,%2,%3}, [%4];"
                 : "=r"(r[0]), "=r"(r[1]), "=r"(r[2]), "=r"(r[3]) : "r"(addr));
}
__device__ __forceinline__ void mma16816(float* c, const uint32_t* a, const uint32_t* b) {
    asm volatile(
        "mma.sync.aligned.m16n8k16.row.col.f32.bf16.bf16.f32 "
        "{%0,%1,%2,%3}, {%4,%5,%6,%7}, {%8,%9}, {%0,%1,%2,%3};"
        : "+f"(c[0]), "+f"(c[1]), "+f"(c[2]), "+f"(c[3])
        : "r"(a[0]), "r"(a[1]), "r"(a[2]), "r"(a[3]), "r"(b[0]), "r"(b[1]));
}

// smem tile: 128 rows x 32 bf16, row stride 40 bf16 (80 B -> ldmatrix
// row addrs at 20-word stride cover all 32 banks conflict-free)
#define TROW 40
#define TILE_ELEMS (128 * TROW)

// ===================== scratch globals ======================================
__device__ float g_v[N_TOK * DIM];
__device__ float g_attn[N_TOK * DIM];
__device__ float g_x[N_TOK * DIM];
__device__ float g_t[N_TOK * (DIM / 2)];
__device__ float g_cw[N_TOK];
__device__ float g_relmean[N_TOK * 3];
__device__ float g_s[(size_t)NH * N_TOK * N_TOK];   // raw scores [h][n][m]

__device__ bf16 g_ah[N_TOK * DIM], g_al[N_TOK * DIM];   // A-side split (reused)
__device__ bf16 g_qh[N_TOK * DIM], g_ql[N_TOK * DIM];
__device__ bf16 g_kh[N_TOK * DIM], g_kl[N_TOK * DIM];
__device__ bf16 g_wqh[DIM * DIM], g_wql[DIM * DIM];
__device__ bf16 g_wkh[DIM * DIM], g_wkl[DIM * DIM];
__device__ bf16 g_wvh[DIM * DIM], g_wvl[DIM * DIM];
__device__ bf16 g_woh[DIM * DIM], g_wol[DIM * DIM];
__device__ bf16 g_w1h[(DIM / 2) * DIM], g_w1l[(DIM / 2) * DIM];

// ===================== prep kernels =========================================
__global__ __launch_bounds__(256)
void split_f32(const float* __restrict__ X, bf16* __restrict__ hi,
               bf16* __restrict__ lo, int n4)
{
    const int i = blockIdx.x * blockDim.x + threadIdx.x;
    if (i >= n4) return;
    const float4 v = ((const float4*)X)[i];
    const bf16 h0 = __float2bfloat16(v.x), h1 = __float2bfloat16(v.y);
    const bf16 h2 = __float2bfloat16(v.z), h3 = __float2bfloat16(v.w);
    hi[4 * i + 0] = h0; hi[4 * i + 1] = h1; hi[4 * i + 2] = h2; hi[4 * i + 3] = h3;
    lo[4 * i + 0] = __float2bfloat16(v.x - __bfloat162float(h0));
    lo[4 * i + 1] = __float2bfloat16(v.y - __bfloat162float(h1));
    lo[4 * i + 2] = __float2bfloat16(v.z - __bfloat162float(h2));
    lo[4 * i + 3] = __float2bfloat16(v.w - __bfloat162float(h3));
}

// transpose W[K][N] -> T[N][K], split to bf16 hi/lo
__global__ void trsplit(const float* __restrict__ W, bf16* __restrict__ Thi,
                        bf16* __restrict__ Tlo, int K, int N)
{
    __shared__ float t[32][33];
    const int n = blockIdx.x * 32 + threadIdx.x;
    const int k = blockIdx.y * 32 + threadIdx.y;
    t[threadIdx.y][threadIdx.x] = W[(size_t)k * N + n];
    __syncthreads();
    const int nn = blockIdx.x * 32 + threadIdx.y;
    const int kk = blockIdx.y * 32 + threadIdx.x;
    const float v = t[threadIdx.x][threadIdx.y];
    const bf16 h = __float2bfloat16(v);
    Thi[(size_t)nn * K + kk] = h;
    Tlo[(size_t)nn * K + kk] = __float2bfloat16(v - __bfloat162float(h));
}

// ===================== bf16x2 HMMA GEMM =====================================
// D[M,N] = A[M,K] @ Bt[N,K]^T + bias. 3 passes: hi*hi + hi*lo + lo*hi.
// Block 128x128, 8 warps (4M x 2N), warp tile 32x64, k-chunk 32.
// EPI: 0 = f32 +bias, 1 = f32 +bias+res, 2 = f32 +bias+SiLU, 3 = bf16 hi/lo
template <int EPI>
__global__ __launch_bounds__(256)
void gemm_mma(const bf16* __restrict__ Ahi, const bf16* __restrict__ Alo,
              const bf16* __restrict__ Bhi, const bf16* __restrict__ Blo,
              const float* __restrict__ bias, const float* __restrict__ res,
              float* __restrict__ Cf, bf16* __restrict__ Chi, bf16* __restrict__ Clo,
              int M, int N, int K)
{
    __shared__ bf16 sAh[TILE_ELEMS], sAl[TILE_ELEMS];
    __shared__ bf16 sBh[TILE_ELEMS], sBl[TILE_ELEMS];

    const int tid  = threadIdx.x;
    const int wid  = tid >> 5, lane = tid & 31;
    const int m0   = blockIdx.y * 128, n0 = blockIdx.x * 128;
    const int wm   = (wid & 3) * 32;        // warp m-offset in tile
    const int wn   = (wid >> 2) * 64;       // warp n-offset in tile

    const uint32_t aAh = smem_u32(sAh), aAl = smem_u32(sAl);
    const uint32_t aBh = smem_u32(sBh), aBl = smem_u32(sBl);

    float acc[2][8][4];
#pragma unroll
    for (int i = 0; i < 2; i++)
#pragma unroll
        for (int j = 0; j < 8; j++)
#pragma unroll
            for (int r = 0; r < 4; r++) acc[i][j][r] = 0.f;

    // ldmatrix lane geometry
    const int la_rowA = (lane & 7) + ((lane >> 3) & 1) * 8;   // + quad k-sel
    const int la_kA   = (lane >> 4) * 8;
    const int la_rowB = (lane & 7) + (lane >= 16 ? 8 : 0);
    const int la_kB   = ((lane >> 3) & 1) * 8;

    for (int k0 = 0; k0 < K; k0 += 32) {
#pragma unroll
        for (int t = 0; t < 2; t++) {
            const int idx = tid + 256 * t;
            const int r = idx >> 2, cs = (idx & 3) * 8;
            const size_t ga = (size_t)(m0 + r) * K + k0 + cs;
            const size_t gb = (size_t)(n0 + r) * K + k0 + cs;
            *(uint4*)&sAh[r * TROW + cs] = *(const uint4*)&Ahi[ga];
            *(uint4*)&sAl[r * TROW + cs] = *(const uint4*)&Alo[ga];
            *(uint4*)&sBh[r * TROW + cs] = *(const uint4*)&Bhi[gb];
            *(uint4*)&sBl[r * TROW + cs] = *(const uint4*)&Blo[gb];
        }
        __syncthreads();

#pragma unroll
        for (int ks = 0; ks < 32; ks += 16) {
            uint32_t ah[2][4], al[2][4];
#pragma unroll
            for (int mt = 0; mt < 2; mt++) {
                const uint32_t off =
                    (uint32_t)((wm + mt * 16 + la_rowA) * TROW + ks + la_kA) * 2;
                ldmx4(ah[mt], aAh + off);
                ldmx4(al[mt], aAl + off);
            }
#pragma unroll
            for (int nt2 = 0; nt2 < 4; nt2++) {
                uint32_t bh[4], bl[4];
                const uint32_t off =
                    (uint32_t)((wn + nt2 * 16 + la_rowB) * TROW + ks + la_kB) * 2;
                ldmx4(bh, aBh + off);
                ldmx4(bl, aBl + off);
#pragma unroll
                for (int sub = 0; sub < 2; sub++) {
#pragma unroll
                    for (int mt = 0; mt < 2; mt++) {
                        float* c = acc[mt][nt2 * 2 + sub];
                        mma16816(c, ah[mt], &bh[sub * 2]);   // hi*hi
                        mma16816(c, ah[mt], &bl[sub * 2]);   // hi*lo
                        mma16816(c, al[mt], &bh[sub * 2]);   // lo*hi
                    }
                }
            }
        }
        __syncthreads();
    }

    // epilogue: c0,c1 -> (row, col..col+1); c2,c3 -> (row+8, col..col+1)
#pragma unroll
    for (int mt = 0; mt < 2; mt++) {
#pragma unroll
        for (int nt = 0; nt < 8; nt++) {
            const int row = m0 + wm + mt * 16 + (lane >> 2);
            const int col = n0 + wn + nt * 8 + (lane & 3) * 2;
#pragma unroll
            for (int half = 0; half < 2; half++) {
                const int rr = row + half * 8;
                float v0 = acc[mt][nt][half * 2 + 0] + bias[col + 0];
                float v1 = acc[mt][nt][half * 2 + 1] + bias[col + 1];
                if (EPI == 1) {
                    const float2 r2 = *(const float2*)&res[(size_t)rr * N + col];
                    v0 += r2.x; v1 += r2.y;
                }
                if (EPI == 2) {
                    v0 = v0 / (1.f + __expf(-v0));
                    v1 = v1 / (1.f + __expf(-v1));
                }
                if (EPI == 3) {
                    const size_t o = (size_t)rr * N + col;
                    const bf16 h0 = __float2bfloat16(v0), h1 = __float2bfloat16(v1);
                    Chi[o + 0] = h0; Chi[o + 1] = h1;
                    Clo[o + 0] = __float2bfloat16(v0 - __bfloat162float(h0));
                    Clo[o + 1] = __float2bfloat16(v1 - __bfloat162float(h1));
                } else {
                    *(float2*)&Cf[(size_t)rr * N + col] = make_float2(v0, v1);
                }
            }
        }
    }
}

// ===================== scores: S_h = Q_h @ K_h^T (HMMA bf16x2) ==============
// grid (m/128, n/128, h). A = Q rows (out rows n), B = K rows (out cols m).
__global__ __launch_bounds__(256)
void scores_mma(const bf16* __restrict__ Qhi, const bf16* __restrict__ Qlo,
                const bf16* __restrict__ Khi, const bf16* __restrict__ Klo,
                float* __restrict__ S)
{
    __shared__ bf16 sAh[TILE_ELEMS], sAl[TILE_ELEMS];
    __shared__ bf16 sBh[TILE_ELEMS], sBl[TILE_ELEMS];

    const int tid  = threadIdx.x;
    const int wid  = tid >> 5, lane = tid & 31;
    const int mq0  = blockIdx.x * 128;      // out cols (K rows)
    const int nq0  = blockIdx.y * 128;      // out rows (Q rows)
    const int h    = blockIdx.z;
    const int wm   = (wid & 3) * 32;
    const int wn   = (wid >> 2) * 64;

    const uint32_t aAh = smem_u32(sAh), aAl = smem_u32(sAl);
    const uint32_t aBh = smem_u32(sBh), aBl = smem_u32(sBl);

    float acc[2][8][4];
#pragma unroll
    for (int i = 0; i < 2; i++)
#pragma unroll
        for (int j = 0; j < 8; j++)
#pragma unroll
            for (int r = 0; r < 4; r++) acc[i][j][r] = 0.f;

    const int la_rowA = (lane & 7) + ((lane >> 3) & 1) * 8;
    const int la_kA   = (lane >> 4) * 8;
    const int la_rowB = (lane & 7) + (lane >= 16 ? 8 : 0);
    const int la_kB   = ((lane >> 3) & 1) * 8;

#pragma unroll
    for (int k0 = 0; k0 < HD; k0 += 32) {
#pragma unroll
        for (int t = 0; t < 2; t++) {
            const int idx = tid + 256 * t;
            const int r = idx >> 2, cs = (idx & 3) * 8;
            const size_t ga = (size_t)(nq0 + r) * DIM + h * HD + k0 + cs;
            const size_t gb = (size_t)(mq0 + r) * DIM + h * HD + k0 + cs;
            *(uint4*)&sAh[r * TROW + cs] = *(const uint4*)&Qhi[ga];
            *(uint4*)&sAl[r * TROW + cs] = *(const uint4*)&Qlo[ga];
            *(uint4*)&sBh[r * TROW + cs] = *(const uint4*)&Khi[gb];
            *(uint4*)&sBl[r * TROW + cs] = *(const uint4*)&Klo[gb];
        }
        __syncthreads();

#pragma unroll
        for (int ks = 0; ks < 32; ks += 16) {
            uint32_t ah[2][4], al[2][4];
#pragma unroll
            for (int mt = 0; mt < 2; mt++) {
                const uint32_t off =
                    (uint32_t)((wm + mt * 16 + la_rowA) * TROW + ks + la_kA) * 2;
                ldmx4(ah[mt], aAh + off);
                ldmx4(al[mt], aAl + off);
            }
#pragma unroll
            for (int nt2 = 0; nt2 < 4; nt2++) {
                uint32_t bh[4], bl[4];
                const uint32_t off =
                    (uint32_t)((wn + nt2 * 16 + la_rowB) * TROW + ks + la_kB) * 2;
                ldmx4(bh, aBh + off);
                ldmx4(bl, aBl + off);
#pragma unroll
                for (int sub = 0; sub < 2; sub++) {
#pragma unroll
                    for (int mt = 0; mt < 2; mt++) {
                        float* c = acc[mt][nt2 * 2 + sub];
                        mma16816(c, ah[mt], &bh[sub * 2]);
                        mma16816(c, ah[mt], &bl[sub * 2]);
                        mma16816(c, al[mt], &bh[sub * 2]);
                    }
                }
            }
        }
        __syncthreads();
    }

    float* Sp = S + (size_t)h * N_TOK * N_TOK;
#pragma unroll
    for (int mt = 0; mt < 2; mt++) {
#pragma unroll
        for (int nt = 0; nt < 8; nt++) {
            const int row = nq0 + wm + mt * 16 + (lane >> 2);   // n (Q row)
            const int col = mq0 + wn + nt * 8 + (lane & 3) * 2; // m (K row)
#pragma unroll
            for (int half = 0; half < 2; half++) {
                *(float2*)&Sp[(size_t)(row + half * 8) * N_TOK + col] =
                    make_float2(acc[mt][nt][half * 2 + 0], acc[mt][nt][half * 2 + 1]);
            }
        }
    }
}

// ===================== Phase C: softmax-over-heads + PV (fp32) ==============
#define PC_SPLANE 580
#define PC_VROW   1088
#define PC_SMEM   ((16 * PC_SPLANE + 16 * PC_VROW) * 4)

__global__ __launch_bounds__(256, 1)
void pv_kernel(const float* __restrict__ S, const float* __restrict__ V,
               float* __restrict__ O)
{
    extern __shared__ float sm[];
    float* st = sm;
    float* vt = sm + 16 * PC_SPLANE;

    const int tid = threadIdx.x;
    const int n0  = blockIdx.x * 32;
    const int h   = tid & 15;
    const int g   = (tid >> 4) & 7;
    const int dh  = tid >> 7;

    ull a2[4][16];
#pragma unroll
    for (int i = 0; i < 4; i++)
#pragma unroll
        for (int j = 0; j < 16; j++) a2[i][j] = 0ull;

    const size_t N2 = (size_t)N_TOK * N_TOK;

    for (int m0 = 0; m0 < N_TOK; m0 += 16) {
#pragma unroll
        for (int r = tid; r < 512; r += 256) {
            const int hh = r >> 5, nn = r & 31;
            const float4* src =
                (const float4*)(S + (size_t)hh * N2 + (size_t)(n0 + nn) * N_TOK + m0);
            const float4 f0 = src[0], f1 = src[1], f2 = src[2], f3 = src[3];
            float* dst = st + hh * PC_SPLANE + nn;
            dst[0 * 36] = f0.x;  dst[1 * 36] = f0.y;  dst[2 * 36] = f0.z;  dst[3 * 36] = f0.w;
            dst[4 * 36] = f1.x;  dst[5 * 36] = f1.y;  dst[6 * 36] = f1.z;  dst[7 * 36] = f1.w;
            dst[8 * 36] = f2.x;  dst[9 * 36] = f2.y;  dst[10 * 36] = f2.z; dst[11 * 36] = f2.w;
            dst[12 * 36] = f3.x; dst[13 * 36] = f3.y; dst[14 * 36] = f3.z; dst[15 * 36] = f3.w;
        }
#pragma unroll
        for (int it = 0; it < 16; it++) {
            const int idx = it * 256 + tid;
            const int mm = idx >> 8;
            const int hh = (idx >> 4) & 15;
            const int dq = idx & 15;
            *(float4*)&vt[mm * PC_VROW + hh * 68 + dq * 4] =
                *(const float4*)&V[(size_t)(m0 + mm) * DIM + hh * HD + dq * 4];
        }
        __syncthreads();

#pragma unroll
        for (int pi = 0; pi < 2; pi++) {
            const int p  = tid * 2 + pi;
            const int nn = p & 31, mm = p >> 5;
            float* base = st + mm * 36 + nn;
            float sv[16];
#pragma unroll
            for (int q = 0; q < 16; q++) sv[q] = base[q * PC_SPLANE] * 0.125f;
            float mx = sv[0];
#pragma unroll
            for (int q = 1; q < 16; q++) mx = fmaxf(mx, sv[q]);
            float ssum = 0.f;
#pragma unroll
            for (int q = 0; q < 16; q++) { sv[q] = __expf(sv[q] - mx); ssum += sv[q]; }
            const float rinv = __fdividef(1.f, ssum);
#pragma unroll
            for (int q = 0; q < 16; q++) base[q * PC_SPLANE] = sv[q] * rinv;
        }
        __syncthreads();

#pragma unroll
        for (int mm = 0; mm < 16; mm++) {
            const float4 pf = *(const float4*)&st[h * PC_SPLANE + mm * 36 + 4 * g];
            const ull p2[4] = { pack2(pf.x, pf.x), pack2(pf.y, pf.y),
                                pack2(pf.z, pf.z), pack2(pf.w, pf.w) };
            const float* vb = &vt[mm * PC_VROW + h * 68 + dh * 32];
#pragma unroll
            for (int dc = 0; dc < 4; dc++) {
                const ulonglong2 v01 = *(const ulonglong2*)(vb + dc * 8);
                const ulonglong2 v23 = *(const ulonglong2*)(vb + dc * 8 + 4);
#pragma unroll
                for (int i = 0; i < 4; i++) {
                    a2[i][dc * 4 + 0] = ffma2(p2[i], v01.x, a2[i][dc * 4 + 0]);
                    a2[i][dc * 4 + 1] = ffma2(p2[i], v01.y, a2[i][dc * 4 + 1]);
                    a2[i][dc * 4 + 2] = ffma2(p2[i], v23.x, a2[i][dc * 4 + 2]);
                    a2[i][dc * 4 + 3] = ffma2(p2[i], v23.y, a2[i][dc * 4 + 3]);
                }
            }
        }
        __syncthreads();
    }

#pragma unroll
    for (int i = 0; i < 4; i++) {
        float* dst = O + (size_t)(n0 + 4 * g + i) * DIM + h * HD + dh * 32;
#pragma unroll
        for (int dc = 0; dc < 4; dc++) {
            const float2 e0 = unpack2(a2[i][dc * 4 + 0]);
            const float2 e1 = unpack2(a2[i][dc * 4 + 1]);
            const float2 e2 = unpack2(a2[i][dc * 4 + 2]);
            const float2 e3 = unpack2(a2[i][dc * 4 + 3]);
            *(float4*)(dst + dc * 8 + 0) = make_float4(e0.x, e0.y, e1.x, e1.y);
            *(float4*)(dst + dc * 8 + 4) = make_float4(e2.x, e2.y, e3.x, e3.y);
        }
    }
}

// ===================== LayerNorm ============================================
__global__ __launch_bounds__(256)
void ln_kernel(const float* __restrict__ X, const float* __restrict__ w,
               const float* __restrict__ b, float* __restrict__ out)
{
    const int n   = blockIdx.x;
    const int tid = threadIdx.x;
    const float4 x = ((const float4*)(X + (size_t)n * DIM))[tid];

    float s  = x.x + x.y + x.z + x.w;
    float ss = x.x * x.x + x.y * x.y + x.z * x.z + x.w * x.w;
#pragma unroll
    for (int off = 16; off; off >>= 1) {
        s  += __shfl_xor_sync(0xffffffffu, s, off);
        ss += __shfl_xor_sync(0xffffffffu, ss, off);
    }
    __shared__ float rs[8], rss[8], stat[2];
    if ((tid & 31) == 0) { rs[tid >> 5] = s; rss[tid >> 5] = ss; }
    __syncthreads();
    if (tid == 0) {
        float S = 0.f, SS = 0.f;
#pragma unroll
        for (int i = 0; i < 8; i++) { S += rs[i]; SS += rss[i]; }
        const float mean = S * (1.f / DIM);
        const float var  = SS * (1.f / DIM) - mean * mean;
        stat[0] = mean;
        stat[1] = rsqrtf(var + 1e-5f);
    }
    __syncthreads();
    const float mean = stat[0], inv = stat[1];
    const int col = tid * 4;
    const float4 wv = *(const float4*)&w[col];
    const float4 bv = *(const float4*)&b[col];
    float4 o;
    o.x = (x.x - mean) * inv * wv.x + bv.x;
    o.y = (x.y - mean) * inv * wv.y + bv.y;
    o.z = (x.z - mean) * inv * wv.z + bv.z;
    o.w = (x.w - mean) * inv * wv.w + bv.w;
    ((float4*)(out + (size_t)n * DIM))[tid] = o;
}

// ===================== coord MLP layer 2 ====================================
__global__ void mlp2_kernel(const float* __restrict__ T, const float* __restrict__ W2,
                            const float* __restrict__ b2, float* __restrict__ cw)
{
    const int warp = (blockIdx.x * blockDim.x + threadIdx.x) >> 5;
    const int lane = threadIdx.x & 31;
    if (warp >= N_TOK) return;
    const float* t = T + (size_t)warp * (DIM / 2);
    float s = 0.f;
#pragma unroll
    for (int j = 0; j < DIM / 2; j += 32) s = fmaf(t[j + lane], W2[j + lane], s);
#pragma unroll
    for (int off = 16; off; off >>= 1) s += __shfl_xor_sync(0xffffffffu, s, off);
    if (lane == 0) cw[warp] = s + b2[0];
}

// ===================== rel_pos mean =========================================
__global__ __launch_bounds__(128)
void relmean_kernel(const float* __restrict__ rel, float* __restrict__ out)
{
    const int n   = blockIdx.x;
    const int tid = threadIdx.x;
    const float* base = rel + (size_t)n * N_TOK * 3;
    float s0 = 0.f, s1 = 0.f, s2 = 0.f;
    for (int m = tid; m < N_TOK; m += 128) {
        s0 += base[m * 3 + 0];
        s1 += base[m * 3 + 1];
        s2 += base[m * 3 + 2];
    }
#pragma unroll
    for (int off = 16; off; off >>= 1) {
        s0 += __shfl_xor_sync(0xffffffffu, s0, off);
        s1 += __shfl_xor_sync(0xffffffffu, s1, off);
        s2 += __shfl_xor_sync(0xffffffffu, s2, off);
    }
    __shared__ float sm[3][4];
    if ((tid & 31) == 0) {
        sm[0][tid >> 5] = s0; sm[1][tid >> 5] = s1; sm[2][tid >> 5] = s2;
    }
    __syncthreads();
    if (tid == 0) {
        out[n * 3 + 0] = (sm[0][0] + sm[0][1] + sm[0][2] + sm[0][3]) * (1.f / N_TOK);
        out[n * 3 + 1] = (sm[1][0] + sm[1][1] + sm[1][2] + sm[1][3]) * (1.f / N_TOK);
        out[n * 3 + 2] = (sm[2][0] + sm[2][1] + sm[2][2] + sm[2][3]) * (1.f / N_TOK);
    }
}

// ===================== pos_update ===========================================
__global__ void posupd_kernel(const float* __restrict__ cw, const float* __restrict__ rm,
                              float* __restrict__ out)
{
    const int i = blockIdx.x * blockDim.x + threadIdx.x;
    if (i < N_TOK * 3) out[i] = cw[i / 3] * rm[i];
}

// ===================== launcher =============================================
extern "C" void kernel_launch(void* const* d_in, const int* in_sizes, int n_in,
                              void* d_out, int out_size)
{
    const float* h    = (const float*)d_in[0];
    const float* rel  = (const float*)d_in[1];
    const float* Wq   = (const float*)d_in[2];
    const float* bq   = (const float*)d_in[3];
    const float* Wk   = (const float*)d_in[4];
    const float* bk   = (const float*)d_in[5];
    const float* Wv   = (const float*)d_in[6];
    const float* bv   = (const float*)d_in[7];
    const float* Wo   = (const float*)d_in[8];
    const float* bo   = (const float*)d_in[9];
    const float* W1   = (const float*)d_in[10];
    const float* b1   = (const float*)d_in[11];
    const float* W2   = (const float*)d_in[12];
    const float* b2   = (const float*)d_in[13];
    const float* lnw  = (const float*)d_in[14];
    const float* lnb  = (const float*)d_in[15];
    float* out = (float*)d_out;

    float *v, *attn, *x, *t, *cw, *rm, *s;
    bf16 *ah, *al, *qh, *ql, *kh, *kl;
    bf16 *wqh, *wql, *wkh, *wkl, *wvh, *wvl, *woh, *wol, *w1h, *w1l;
    cudaGetSymbolAddress((void**)&v,    g_v);
    cudaGetSymbolAddress((void**)&attn, g_attn);
    cudaGetSymbolAddress((void**)&x,    g_x);
    cudaGetSymbolAddress((void**)&t,    g_t);
    cudaGetSymbolAddress((void**)&cw,   g_cw);
    cudaGetSymbolAddress((void**)&rm,   g_relmean);
    cudaGetSymbolAddress((void**)&s,    g_s);
    cudaGetSymbolAddress((void**)&ah,   g_ah);
    cudaGetSymbolAddress((void**)&al,   g_al);
    cudaGetSymbolAddress((void**)&qh,   g_qh);
    cudaGetSymbolAddress((void**)&ql,   g_ql);
    cudaGetSymbolAddress((void**)&kh,   g_kh);
    cudaGetSymbolAddress((void**)&kl,   g_kl);
    cudaGetSymbolAddress((void**)&wqh,  g_wqh);
    cudaGetSymbolAddress((void**)&wql,  g_wql);
    cudaGetSymbolAddress((void**)&wkh,  g_wkh);
    cudaGetSymbolAddress((void**)&wkl,  g_wkl);
    cudaGetSymbolAddress((void**)&wvh,  g_wvh);
    cudaGetSymbolAddress((void**)&wvl,  g_wvl);
    cudaGetSymbolAddress((void**)&woh,  g_woh);
    cudaGetSymbolAddress((void**)&wol,  g_wol);
    cudaGetSymbolAddress((void**)&w1h,  g_w1h);
    cudaGetSymbolAddress((void**)&w1l,  g_w1l);

    cudaFuncSetAttribute(pv_kernel, cudaFuncAttributeMaxDynamicSharedMemorySize, PC_SMEM);

    // independent: rel_pos mean
    relmean_kernel<<<N_TOK, 128>>>(rel, rm);

    // weight prep: transpose + bf16 split
    trsplit<<<dim3(32, 32), dim3(32, 32)>>>(Wq, wqh, wql, DIM, DIM);
    trsplit<<<dim3(32, 32), dim3(32, 32)>>>(Wk, wkh, wkl, DIM, DIM);
    trsplit<<<dim3(32, 32), dim3(32, 32)>>>(Wv, wvh, wvl, DIM, DIM);
    trsplit<<<dim3(32, 32), dim3(32, 32)>>>(Wo, woh, wol, DIM, DIM);
    trsplit<<<dim3(16, 32), dim3(32, 32)>>>(W1, w1h, w1l, DIM, DIM / 2);

    // h split -> A operand
    split_f32<<<(N_TOK * DIM / 4 + 255) / 256, 256>>>(h, ah, al, N_TOK * DIM / 4);

    // QKV (q,k written as bf16 hi/lo for scores; v fp32 for PV)
    gemm_mma<3><<<dim3(8, 32), 256>>>(ah, al, wqh, wql, bq, nullptr, nullptr, qh, ql, N_TOK, DIM, DIM);
    gemm_mma<3><<<dim3(8, 32), 256>>>(ah, al, wkh, wkl, bk, nullptr, nullptr, kh, kl, N_TOK, DIM, DIM);
    gemm_mma<0><<<dim3(8, 32), 256>>>(ah, al, wvh, wvl, bv, nullptr, v, nullptr, nullptr, N_TOK, DIM, DIM);

    // attention phase A: raw scores (HMMA)
    scores_mma<<<dim3(32, 32, 16), 256>>>(qh, ql, kh, kl, s);

    // attention phase C: softmax over heads + PV
    pv_kernel<<<N_TOK / 32, 256, PC_SMEM>>>(s, v, attn);

    // O projection + residual
    split_f32<<<(N_TOK * DIM / 4 + 255) / 256, 256>>>(attn, ah, al, N_TOK * DIM / 4);
    gemm_mma<1><<<dim3(8, 32), 256>>>(ah, al, woh, wol, bo, h, x, nullptr, nullptr, N_TOK, DIM, DIM);

    // layernorm -> hn
    ln_kernel<<<N_TOK, 256>>>(x, lnw, lnb, out);

    // coord MLP
    split_f32<<<(N_TOK * DIM / 4 + 255) / 256, 256>>>(out, ah, al, N_TOK * DIM / 4);
    gemm_mma<2><<<dim3(4, 32), 256>>>(ah, al, w1h, w1l, b1, nullptr, t, nullptr, nullptr, N_TOK, DIM / 2, DIM);
    mlp2_kernel<<<(N_TOK * 32) / 256, 256>>>(t, W2, b2, cw);

    // pos_update
    posupd_kernel<<<(N_TOK * 3 + 255) / 256, 256>>>(cw, rm, out + (size_t)N_TOK * DIM);
}

// round 9
// speedup vs baseline: 3.2741x; 1.1981x over previous
#include <cuda_runtime.h>
#include <cuda_bf16.h>
#include <cstdint>
#include <math.h>

#define N_TOK 4096
#define DIM   1024
#define NH    16
#define HD    64

typedef unsigned long long ull;
typedef __nv_bfloat16 bf16;

// ===================== HMMA primitives (baseline PTX, no 'a' features) ======
__device__ __forceinline__ uint32_t smem_u32(const void* p) {
    uint32_t a;
    asm("{ .reg .u64 t; cvta.to.shared.u64 t, %1; cvt.u32.u64 %0, t; }"
        : "=r"(a) : "l"(p));
    return a;
}
__device__ __forceinline__ void ldmx4(uint32_t* r, uint32_t addr) {
    asm volatile("ldmatrix.sync.aligned.m8n8.x4.shared.b16 {%0,%1,%2,%3}, [%4];"
                 : "=r"(r[0]), "=r"(r[1]), "=r"(r[2]), "=r"(r[3]) : "r"(addr));
}
__device__ __forceinline__ void mma16816(float* c, const uint32_t* a, const uint32_t* b) {
    asm volatile(
        "mma.sync.aligned.m16n8k16.row.col.f32.bf16.bf16.f32 "
        "{%0,%1,%2,%3}, {%4,%5,%6,%7}, {%8,%9}, {%0,%1,%2,%3};"
        : "+f"(c[0]), "+f"(c[1]), "+f"(c[2]), "+f"(c[3])
        : "r"(a[0]), "r"(a[1]), "r"(a[2]), "r"(a[3]), "r"(b[0]), "r"(b[1]));
}

// smem tile for dense GEMMs: 128 rows x 32 bf16, row stride 40 bf16 (80 B)
#define TROW 40
#define TILE_ELEMS (128 * TROW)

// ===================== scratch globals ======================================
__device__ float g_attn[N_TOK * DIM];
__device__ float g_x[N_TOK * DIM];
__device__ float g_t[N_TOK * (DIM / 2)];
__device__ float g_cw[N_TOK];
__device__ float g_relmean[N_TOK * 3];
__device__ float g_s[(size_t)NH * N_TOK * N_TOK];   // raw scores [h][n][m]

__device__ bf16 g_ah[N_TOK * DIM], g_al[N_TOK * DIM];   // A-side split (reused)
__device__ bf16 g_qh[N_TOK * DIM], g_ql[N_TOK * DIM];
__device__ bf16 g_kh[N_TOK * DIM], g_kl[N_TOK * DIM];
__device__ bf16 g_vh[N_TOK * DIM], g_vl[N_TOK * DIM];
__device__ bf16 g_vtb[(size_t)256 * 32 * 64 * 16];      // blocked V [mb][h*2+hl][d][16m]
__device__ bf16 g_wqh[DIM * DIM], g_wql[DIM * DIM];
__device__ bf16 g_wkh[DIM * DIM], g_wkl[DIM * DIM];
__device__ bf16 g_wvh[DIM * DIM], g_wvl[DIM * DIM];
__device__ bf16 g_woh[DIM * DIM], g_wol[DIM * DIM];
__device__ bf16 g_w1h[(DIM / 2) * DIM], g_w1l[(DIM / 2) * DIM];

// ===================== prep kernels =========================================
__global__ __launch_bounds__(256)
void split_f32(const float* __restrict__ X, bf16* __restrict__ hi,
               bf16* __restrict__ lo, int n4)
{
    const int i = blockIdx.x * blockDim.x + threadIdx.x;
    if (i >= n4) return;
    const float4 v = ((const float4*)X)[i];
    const bf16 h0 = __float2bfloat16(v.x), h1 = __float2bfloat16(v.y);
    const bf16 h2 = __float2bfloat16(v.z), h3 = __float2bfloat16(v.w);
    hi[4 * i + 0] = h0; hi[4 * i + 1] = h1; hi[4 * i + 2] = h2; hi[4 * i + 3] = h3;
    lo[4 * i + 0] = __float2bfloat16(v.x - __bfloat162float(h0));
    lo[4 * i + 1] = __float2bfloat16(v.y - __bfloat162float(h1));
    lo[4 * i + 2] = __float2bfloat16(v.z - __bfloat162float(h2));
    lo[4 * i + 3] = __float2bfloat16(v.w - __bfloat162float(h3));
}

// transpose W[K][N] -> T[N][K], split to bf16 hi/lo
__global__ void trsplit(const float* __restrict__ W, bf16* __restrict__ Thi,
                        bf16* __restrict__ Tlo, int K, int N)
{
    __shared__ float t[32][33];
    const int n = blockIdx.x * 32 + threadIdx.x;
    const int k = blockIdx.y * 32 + threadIdx.y;
    t[threadIdx.y][threadIdx.x] = W[(size_t)k * N + n];
    __syncthreads();
    const int nn = blockIdx.x * 32 + threadIdx.y;
    const int kk = blockIdx.y * 32 + threadIdx.x;
    const float v = t[threadIdx.x][threadIdx.y];
    const bf16 h = __float2bfloat16(v);
    Thi[(size_t)nn * K + kk] = h;
    Tlo[(size_t)nn * K + kk] = __float2bfloat16(v - __bfloat162float(h));
}

// block V hi/lo [m][1024] -> [mb][pl=h*2+hl][d][16m] (contiguous per m-tile)
__global__ __launch_bounds__(512)
void vblock(const bf16* __restrict__ vh, const bf16* __restrict__ vl,
            bf16* __restrict__ out)
{
    __shared__ bf16 sh[16 * 1024];
    __shared__ bf16 sl[16 * 1024];
    const int mb  = blockIdx.x;
    const int tid = threadIdx.x;

#pragma unroll
    for (int j = 0; j < 4; j++) {
        const int e  = j * 512 + tid;           // uint4 idx, 2048 total
        const int mm = e >> 7;
        const int c8 = e & 127;
        const size_t go = (size_t)(mb * 16 + mm) * DIM + c8 * 8;
        ((uint4*)sh)[e] = *(const uint4*)&vh[go];
        ((uint4*)sl)[e] = *(const uint4*)&vl[go];
    }
    __syncthreads();

#pragma unroll
    for (int j = 0; j < 8; j++) {
        const int e    = j * 512 + tid;         // out uint4 idx, 4096 total
        const int pl   = e >> 7;
        const int d    = (e >> 1) & 63;
        const int half = e & 1;
        const int h    = pl >> 1;
        const bf16* src = (pl & 1) ? sl : sh;
        bf16 tmp[8];
#pragma unroll
        for (int k2 = 0; k2 < 8; k2++)
            tmp[k2] = src[(half * 8 + k2) * 1024 + h * 64 + d];
        *(uint4*)&out[(size_t)mb * 32768 + (size_t)e * 8] = *(uint4*)tmp;
    }
}

// ===================== tile loader for dense GEMMs ===========================
// (loads done inline in gemm_mma)

// ===================== bf16x2 HMMA GEMM =====================================
// D[M,N] = A[M,K] @ Bt[N,K]^T + bias. 3 passes: hi*hi + hi*lo + lo*hi.
// EPI: 0 = f32 +bias, 1 = f32 +bias+res, 2 = f32 +bias+SiLU, 3 = bf16 hi/lo
template <int EPI>
__global__ __launch_bounds__(256)
void gemm_mma(const bf16* __restrict__ Ahi, const bf16* __restrict__ Alo,
              const bf16* __restrict__ Bhi, const bf16* __restrict__ Blo,
              const float* __restrict__ bias, const float* __restrict__ res,
              float* __restrict__ Cf, bf16* __restrict__ Chi, bf16* __restrict__ Clo,
              int M, int N, int K)
{
    __shared__ bf16 sAh[TILE_ELEMS], sAl[TILE_ELEMS];
    __shared__ bf16 sBh[TILE_ELEMS], sBl[TILE_ELEMS];

    const int tid  = threadIdx.x;
    const int wid  = tid >> 5, lane = tid & 31;
    const int m0   = blockIdx.y * 128, n0 = blockIdx.x * 128;
    const int wm   = (wid & 3) * 32;
    const int wn   = (wid >> 2) * 64;

    const uint32_t aAh = smem_u32(sAh), aAl = smem_u32(sAl);
    const uint32_t aBh = smem_u32(sBh), aBl = smem_u32(sBl);

    float acc[2][8][4];
#pragma unroll
    for (int i = 0; i < 2; i++)
#pragma unroll
        for (int j = 0; j < 8; j++)
#pragma unroll
            for (int r = 0; r < 4; r++) acc[i][j][r] = 0.f;

    const int la_rowA = (lane & 7) + ((lane >> 3) & 1) * 8;
    const int la_kA   = (lane >> 4) * 8;
    const int la_rowB = (lane & 7) + (lane >= 16 ? 8 : 0);
    const int la_kB   = ((lane >> 3) & 1) * 8;

    for (int k0 = 0; k0 < K; k0 += 32) {
#pragma unroll
        for (int t = 0; t < 2; t++) {
            const int idx = tid + 256 * t;
            const int r = idx >> 2, cs = (idx & 3) * 8;
            const size_t ga = (size_t)(m0 + r) * K + k0 + cs;
            const size_t gb = (size_t)(n0 + r) * K + k0 + cs;
            *(uint4*)&sAh[r * TROW + cs] = *(const uint4*)&Ahi[ga];
            *(uint4*)&sAl[r * TROW + cs] = *(const uint4*)&Alo[ga];
            *(uint4*)&sBh[r * TROW + cs] = *(const uint4*)&Bhi[gb];
            *(uint4*)&sBl[r * TROW + cs] = *(const uint4*)&Blo[gb];
        }
        __syncthreads();

#pragma unroll
        for (int ks = 0; ks < 32; ks += 16) {
            uint32_t ah[2][4], al[2][4];
#pragma unroll
            for (int mt = 0; mt < 2; mt++) {
                const uint32_t off =
                    (uint32_t)((wm + mt * 16 + la_rowA) * TROW + ks + la_kA) * 2;
                ldmx4(ah[mt], aAh + off);
                ldmx4(al[mt], aAl + off);
            }
#pragma unroll
            for (int nt2 = 0; nt2 < 4; nt2++) {
                uint32_t bh[4], bl[4];
                const uint32_t off =
                    (uint32_t)((wn + nt2 * 16 + la_rowB) * TROW + ks + la_kB) * 2;
                ldmx4(bh, aBh + off);
                ldmx4(bl, aBl + off);
#pragma unroll
                for (int sub = 0; sub < 2; sub++) {
#pragma unroll
                    for (int mt = 0; mt < 2; mt++) {
                        float* c = acc[mt][nt2 * 2 + sub];
                        mma16816(c, ah[mt], &bh[sub * 2]);
                        mma16816(c, ah[mt], &bl[sub * 2]);
                        mma16816(c, al[mt], &bh[sub * 2]);
                    }
                }
            }
        }
        __syncthreads();
    }

#pragma unroll
    for (int mt = 0; mt < 2; mt++) {
#pragma unroll
        for (int nt = 0; nt < 8; nt++) {
            const int row = m0 + wm + mt * 16 + (lane >> 2);
            const int col = n0 + wn + nt * 8 + (lane & 3) * 2;
#pragma unroll
            for (int half = 0; half < 2; half++) {
                const int rr = row + half * 8;
                float v0 = acc[mt][nt][half * 2 + 0] + bias[col + 0];
                float v1 = acc[mt][nt][half * 2 + 1] + bias[col + 1];
                if (EPI == 1) {
                    const float2 r2 = *(const float2*)&res[(size_t)rr * N + col];
                    v0 += r2.x; v1 += r2.y;
                }
                if (EPI == 2) {
                    v0 = v0 / (1.f + __expf(-v0));
                    v1 = v1 / (1.f + __expf(-v1));
                }
                if (EPI == 3) {
                    const size_t o = (size_t)rr * N + col;
                    const bf16 h0 = __float2bfloat16(v0), h1 = __float2bfloat16(v1);
                    Chi[o + 0] = h0; Chi[o + 1] = h1;
                    Clo[o + 0] = __float2bfloat16(v0 - __bfloat162float(h0));
                    Clo[o + 1] = __float2bfloat16(v1 - __bfloat162float(h1));
                } else {
                    *(float2*)&Cf[(size_t)rr * N + col] = make_float2(v0, v1);
                }
            }
        }
    }
}

// ===================== scores: S_h = Q_h @ K_h^T (HMMA bf16x2) ==============
__global__ __launch_bounds__(256)
void scores_mma(const bf16* __restrict__ Qhi, const bf16* __restrict__ Qlo,
                const bf16* __restrict__ Khi, const bf16* __restrict__ Klo,
                float* __restrict__ S)
{
    __shared__ bf16 sAh[TILE_ELEMS], sAl[TILE_ELEMS];
    __shared__ bf16 sBh[TILE_ELEMS], sBl[TILE_ELEMS];

    const int tid  = threadIdx.x;
    const int wid  = tid >> 5, lane = tid & 31;
    const int mq0  = blockIdx.x * 128;
    const int nq0  = blockIdx.y * 128;
    const int h    = blockIdx.z;
    const int wm   = (wid & 3) * 32;
    const int wn   = (wid >> 2) * 64;

    const uint32_t aAh = smem_u32(sAh), aAl = smem_u32(sAl);
    const uint32_t aBh = smem_u32(sBh), aBl = smem_u32(sBl);

    float acc[2][8][4];
#pragma unroll
    for (int i = 0; i < 2; i++)
#pragma unroll
        for (int j = 0; j < 8; j++)
#pragma unroll
            for (int r = 0; r < 4; r++) acc[i][j][r] = 0.f;

    const int la_rowA = (lane & 7) + ((lane >> 3) & 1) * 8;
    const int la_kA   = (lane >> 4) * 8;
    const int la_rowB = (lane & 7) + (lane >= 16 ? 8 : 0);
    const int la_kB   = ((lane >> 3) & 1) * 8;

#pragma unroll
    for (int k0 = 0; k0 < HD; k0 += 32) {
#pragma unroll
        for (int t = 0; t < 2; t++) {
            const int idx = tid + 256 * t;
            const int r = idx >> 2, cs = (idx & 3) * 8;
            const size_t ga = (size_t)(nq0 + r) * DIM + h * HD + k0 + cs;
            const size_t gb = (size_t)(mq0 + r) * DIM + h * HD + k0 + cs;
            *(uint4*)&sAh[r * TROW + cs] = *(const uint4*)&Qhi[ga];
            *(uint4*)&sAl[r * TROW + cs] = *(const uint4*)&Qlo[ga];
            *(uint4*)&sBh[r * TROW + cs] = *(const uint4*)&Khi[gb];
            *(uint4*)&sBl[r * TROW + cs] = *(const uint4*)&Klo[gb];
        }
        __syncthreads();

#pragma unroll
        for (int ks = 0; ks < 32; ks += 16) {
            uint32_t ah[2][4], al[2][4];
#pragma unroll
            for (int mt = 0; mt < 2; mt++) {
                const uint32_t off =
                    (uint32_t)((wm + mt * 16 + la_rowA) * TROW + ks + la_kA) * 2;
                ldmx4(ah[mt], aAh + off);
                ldmx4(al[mt], aAl + off);
            }
#pragma unroll
            for (int nt2 = 0; nt2 < 4; nt2++) {
                uint32_t bh[4], bl[4];
                const uint32_t off =
                    (uint32_t)((wn + nt2 * 16 + la_rowB) * TROW + ks + la_kB) * 2;
                ldmx4(bh, aBh + off);
                ldmx4(bl, aBl + off);
#pragma unroll
                for (int sub = 0; sub < 2; sub++) {
#pragma unroll
                    for (int mt = 0; mt < 2; mt++) {
                        float* c = acc[mt][nt2 * 2 + sub];
                        mma16816(c, ah[mt], &bh[sub * 2]);
                        mma16816(c, ah[mt], &bl[sub * 2]);
                        mma16816(c, al[mt], &bh[sub * 2]);
                    }
                }
            }
        }
        __syncthreads();
    }

    float* Sp = S + (size_t)h * N_TOK * N_TOK;
#pragma unroll
    for (int mt = 0; mt < 2; mt++) {
#pragma unroll
        for (int nt = 0; nt < 8; nt++) {
            const int row = nq0 + wm + mt * 16 + (lane >> 2);
            const int col = mq0 + wn + nt * 8 + (lane & 3) * 2;
#pragma unroll
            for (int half = 0; half < 2; half++) {
                *(float2*)&Sp[(size_t)(row + half * 8) * N_TOK + col] =
                    make_float2(acc[mt][nt][half * 2 + 0], acc[mt][nt][half * 2 + 1]);
            }
        }
    }
}

// ===================== Phase C: softmax-over-heads + PV on HMMA =============
// Block = 32 n-rows, 512 threads, warp = head. m in 16-tiles.
// P planes: [16h][2hl][32n][24m-stride] bf16; V planes: [16h][2hl][64d][40m-stride].
#define P_PLANE 768                 // 32 * 24
#define V_PLANE 2560                // 64 * 40
#define PV_SMEM ((32 * P_PLANE + 32 * V_PLANE) * 2)   // 212992 B

__global__ __launch_bounds__(512, 1)
void pv_mma(const float* __restrict__ S, const bf16* __restrict__ Vtb,
            float* __restrict__ O)
{
    extern __shared__ bf16 smb[];
    bf16* ps = smb;                       // 32 planes x 768
    bf16* vs = smb + 32 * P_PLANE;        // 32 planes x 2560

    const int tid  = threadIdx.x;
    const int wid  = tid >> 5;            // = head
    const int lane = tid & 31;
    const int n0   = blockIdx.x * 32;
    const int nn   = tid >> 4;            // 0..31
    const int mmq  = tid & 15;            // 0..15

    const uint32_t psb = smem_u32(ps);
    const uint32_t vsb = smem_u32(vs);

    float acc[2][8][4];
#pragma unroll
    for (int i = 0; i < 2; i++)
#pragma unroll
        for (int j = 0; j < 8; j++)
#pragma unroll
            for (int r = 0; r < 4; r++) acc[i][j][r] = 0.f;

    const int la_rowA = (lane & 7) + ((lane >> 3) & 1) * 8;
    const int la_kA   = (lane >> 4) * 8;
    const int la_rowB = (lane & 7) + (lane >= 16 ? 8 : 0);
    const int la_kB   = ((lane >> 3) & 1) * 8;

    const size_t N2 = (size_t)N_TOK * N_TOK;
    const float* sp0 = S + (size_t)(n0 + nn) * N_TOK + mmq;

    for (int mt0 = 0; mt0 < N_TOK / 16; mt0++) {
        const int m0 = mt0 * 16;

        // ---- stage V tile (fully coalesced; layout matches vblock) ----
        const uint4* vsrc = (const uint4*)(Vtb + (size_t)mt0 * 32768);
#pragma unroll
        for (int j = 0; j < 8; j++) {
            const int e    = j * 512 + tid;       // 0..4095
            const int pl   = e >> 7;
            const int d    = (e >> 1) & 63;
            const int half = e & 1;
            *(uint4*)&vs[pl * V_PLANE + d * 40 + half * 8] = vsrc[e];
        }

        // ---- softmax over heads for this thread's (n, m) pair ----
        {
            const float* sp = sp0 + m0;
            float sv[16];
#pragma unroll
            for (int q = 0; q < 16; q++) sv[q] = sp[(size_t)q * N2] * 0.125f;
            float mx = sv[0];
#pragma unroll
            for (int q = 1; q < 16; q++) mx = fmaxf(mx, sv[q]);
            float ssum = 0.f;
#pragma unroll
            for (int q = 0; q < 16; q++) { sv[q] = __expf(sv[q] - mx); ssum += sv[q]; }
            const float rinv = __fdividef(1.f, ssum);
#pragma unroll
            for (int q = 0; q < 16; q++) {
                const float p  = sv[q] * rinv;
                const bf16  ph = __float2bfloat16(p);
                ps[(q * 2 + 0) * P_PLANE + nn * 24 + mmq] = ph;
                ps[(q * 2 + 1) * P_PLANE + nn * 24 + mmq] =
                    __float2bfloat16(p - __bfloat162float(ph));
            }
        }
        __syncthreads();

        // ---- HMMA: warp = head; C[32n][64d] += P[32n][16m] x Vt[64d][16m]^T
        {
            const uint32_t pbh = psb + (uint32_t)(wid * 2 + 0) * P_PLANE * 2;
            const uint32_t pbl = psb + (uint32_t)(wid * 2 + 1) * P_PLANE * 2;
            const uint32_t vbh = vsb + (uint32_t)(wid * 2 + 0) * V_PLANE * 2;
            const uint32_t vbl = vsb + (uint32_t)(wid * 2 + 1) * V_PLANE * 2;

            uint32_t ah[2][4], al[2][4];
#pragma unroll
            for (int mt = 0; mt < 2; mt++) {
                const uint32_t off =
                    (uint32_t)((mt * 16 + la_rowA) * 24 + la_kA) * 2;
                ldmx4(ah[mt], pbh + off);
                ldmx4(al[mt], pbl + off);
            }
#pragma unroll
            for (int nt2 = 0; nt2 < 4; nt2++) {
                uint32_t bh[4], bl[4];
                const uint32_t off =
                    (uint32_t)((nt2 * 16 + la_rowB) * 40 + la_kB) * 2;
                ldmx4(bh, vbh + off);
                ldmx4(bl, vbl + off);
#pragma unroll
                for (int sub = 0; sub < 2; sub++) {
#pragma unroll
                    for (int mt = 0; mt < 2; mt++) {
                        float* c = acc[mt][nt2 * 2 + sub];
                        mma16816(c, ah[mt], &bh[sub * 2]);   // Ph*Vh
                        mma16816(c, ah[mt], &bl[sub * 2]);   // Ph*Vl
                        mma16816(c, al[mt], &bh[sub * 2]);   // Pl*Vh
                    }
                }
            }
        }
        __syncthreads();
    }

    // ---- epilogue: O[n][wid*64 + d] ----
#pragma unroll
    for (int mt = 0; mt < 2; mt++) {
#pragma unroll
        for (int nt = 0; nt < 8; nt++) {
            const int row = n0 + mt * 16 + (lane >> 2);
            const int col = wid * 64 + nt * 8 + (lane & 3) * 2;
#pragma unroll
            for (int half = 0; half < 2; half++) {
                *(float2*)&O[(size_t)(row + half * 8) * DIM + col] =
                    make_float2(acc[mt][nt][half * 2 + 0], acc[mt][nt][half * 2 + 1]);
            }
        }
    }
}

// ===================== LayerNorm ============================================
__global__ __launch_bounds__(256)
void ln_kernel(const float* __restrict__ X, const float* __restrict__ w,
               const float* __restrict__ b, float* __restrict__ out)
{
    const int n   = blockIdx.x;
    const int tid = threadIdx.x;
    const float4 x = ((const float4*)(X + (size_t)n * DIM))[tid];

    float s  = x.x + x.y + x.z + x.w;
    float ss = x.x * x.x + x.y * x.y + x.z * x.z + x.w * x.w;
#pragma unroll
    for (int off = 16; off; off >>= 1) {
        s  += __shfl_xor_sync(0xffffffffu, s, off);
        ss += __shfl_xor_sync(0xffffffffu, ss, off);
    }
    __shared__ float rs[8], rss[8], stat[2];
    if ((tid & 31) == 0) { rs[tid >> 5] = s; rss[tid >> 5] = ss; }
    __syncthreads();
    if (tid == 0) {
        float S = 0.f, SS = 0.f;
#pragma unroll
        for (int i = 0; i < 8; i++) { S += rs[i]; SS += rss[i]; }
        const float mean = S * (1.f / DIM);
        const float var  = SS * (1.f / DIM) - mean * mean;
        stat[0] = mean;
        stat[1] = rsqrtf(var + 1e-5f);
    }
    __syncthreads();
    const float mean = stat[0], inv = stat[1];
    const int col = tid * 4;
    const float4 wv = *(const float4*)&w[col];
    const float4 bv = *(const float4*)&b[col];
    float4 o;
    o.x = (x.x - mean) * inv * wv.x + bv.x;
    o.y = (x.y - mean) * inv * wv.y + bv.y;
    o.z = (x.z - mean) * inv * wv.z + bv.z;
    o.w = (x.w - mean) * inv * wv.w + bv.w;
    ((float4*)(out + (size_t)n * DIM))[tid] = o;
}

// ===================== coord MLP layer 2 ====================================
__global__ void mlp2_kernel(const float* __restrict__ T, const float* __restrict__ W2,
                            const float* __restrict__ b2, float* __restrict__ cw)
{
    const int warp = (blockIdx.x * blockDim.x + threadIdx.x) >> 5;
    const int lane = threadIdx.x & 31;
    if (warp >= N_TOK) return;
    const float* t = T + (size_t)warp * (DIM / 2);
    float s = 0.f;
#pragma unroll
    for (int j = 0; j < DIM / 2; j += 32) s = fmaf(t[j + lane], W2[j + lane], s);
#pragma unroll
    for (int off = 16; off; off >>= 1) s += __shfl_xor_sync(0xffffffffu, s, off);
    if (lane == 0) cw[warp] = s + b2[0];
}

// ===================== rel_pos mean =========================================
__global__ __launch_bounds__(128)
void relmean_kernel(const float* __restrict__ rel, float* __restrict__ out)
{
    const int n   = blockIdx.x;
    const int tid = threadIdx.x;
    const float* base = rel + (size_t)n * N_TOK * 3;
    float s0 = 0.f, s1 = 0.f, s2 = 0.f;
    for (int m = tid; m < N_TOK; m += 128) {
        s0 += base[m * 3 + 0];
        s1 += base[m * 3 + 1];
        s2 += base[m * 3 + 2];
    }
#pragma unroll
    for (int off = 16; off; off >>= 1) {
        s0 += __shfl_xor_sync(0xffffffffu, s0, off);
        s1 += __shfl_xor_sync(0xffffffffu, s1, off);
        s2 += __shfl_xor_sync(0xffffffffu, s2, off);
    }
    __shared__ float sm[3][4];
    if ((tid & 31) == 0) {
        sm[0][tid >> 5] = s0; sm[1][tid >> 5] = s1; sm[2][tid >> 5] = s2;
    }
    __syncthreads();
    if (tid == 0) {
        out[n * 3 + 0] = (sm[0][0] + sm[0][1] + sm[0][2] + sm[0][3]) * (1.f / N_TOK);
        out[n * 3 + 1] = (sm[1][0] + sm[1][1] + sm[1][2] + sm[1][3]) * (1.f / N_TOK);
        out[n * 3 + 2] = (sm[2][0] + sm[2][1] + sm[2][2] + sm[2][3]) * (1.f / N_TOK);
    }
}

// ===================== pos_update ===========================================
__global__ void posupd_kernel(const float* __restrict__ cw, const float* __restrict__ rm,
                              float* __restrict__ out)
{
    const int i = blockIdx.x * blockDim.x + threadIdx.x;
    if (i < N_TOK * 3) out[i] = cw[i / 3] * rm[i];
}

// ===================== launcher =============================================
extern "C" void kernel_launch(void* const* d_in, const int* in_sizes, int n_in,
                              void* d_out, int out_size)
{
    const float* h    = (const float*)d_in[0];
    const float* rel  = (const float*)d_in[1];
    const float* Wq   = (const float*)d_in[2];
    const float* bq   = (const float*)d_in[3];
    const float* Wk   = (const float*)d_in[4];
    const float* bk   = (const float*)d_in[5];
    const float* Wv   = (const float*)d_in[6];
    const float* bv   = (const float*)d_in[7];
    const float* Wo   = (const float*)d_in[8];
    const float* bo   = (const float*)d_in[9];
    const float* W1   = (const float*)d_in[10];
    const float* b1   = (const float*)d_in[11];
    const float* W2   = (const float*)d_in[12];
    const float* b2   = (const float*)d_in[13];
    const float* lnw  = (const float*)d_in[14];
    const float* lnb  = (const float*)d_in[15];
    float* out = (float*)d_out;

    float *attn, *x, *t, *cw, *rm, *s;
    bf16 *ah, *al, *qh, *ql, *kh, *kl, *vh, *vl, *vtb;
    bf16 *wqh, *wql, *wkh, *wkl, *wvh, *wvl, *woh, *wol, *w1h, *w1l;
    cudaGetSymbolAddress((void**)&attn, g_attn);
    cudaGetSymbolAddress((void**)&x,    g_x);
    cudaGetSymbolAddress((void**)&t,    g_t);
    cudaGetSymbolAddress((void**)&cw,   g_cw);
    cudaGetSymbolAddress((void**)&rm,   g_relmean);
    cudaGetSymbolAddress((void**)&s,    g_s);
    cudaGetSymbolAddress((void**)&ah,   g_ah);
    cudaGetSymbolAddress((void**)&al,   g_al);
    cudaGetSymbolAddress((void**)&qh,   g_qh);
    cudaGetSymbolAddress((void**)&ql,   g_ql);
    cudaGetSymbolAddress((void**)&kh,   g_kh);
    cudaGetSymbolAddress((void**)&kl,   g_kl);
    cudaGetSymbolAddress((void**)&vh,   g_vh);
    cudaGetSymbolAddress((void**)&vl,   g_vl);
    cudaGetSymbolAddress((void**)&vtb,  g_vtb);
    cudaGetSymbolAddress((void**)&wqh,  g_wqh);
    cudaGetSymbolAddress((void**)&wql,  g_wql);
    cudaGetSymbolAddress((void**)&wkh,  g_wkh);
    cudaGetSymbolAddress((void**)&wkl,  g_wkl);
    cudaGetSymbolAddress((void**)&wvh,  g_wvh);
    cudaGetSymbolAddress((void**)&wvl,  g_wvl);
    cudaGetSymbolAddress((void**)&woh,  g_woh);
    cudaGetSymbolAddress((void**)&wol,  g_wol);
    cudaGetSymbolAddress((void**)&w1h,  g_w1h);
    cudaGetSymbolAddress((void**)&w1l,  g_w1l);

    cudaFuncSetAttribute(pv_mma, cudaFuncAttributeMaxDynamicSharedMemorySize, PV_SMEM);

    // independent: rel_pos mean
    relmean_kernel<<<N_TOK, 128>>>(rel, rm);

    // weight prep: transpose + bf16 split
    trsplit<<<dim3(32, 32), dim3(32, 32)>>>(Wq, wqh, wql, DIM, DIM);
    trsplit<<<dim3(32, 32), dim3(32, 32)>>>(Wk, wkh, wkl, DIM, DIM);
    trsplit<<<dim3(32, 32), dim3(32, 32)>>>(Wv, wvh, wvl, DIM, DIM);
    trsplit<<<dim3(32, 32), dim3(32, 32)>>>(Wo, woh, wol, DIM, DIM);
    trsplit<<<dim3(16, 32), dim3(32, 32)>>>(W1, w1h, w1l, DIM, DIM / 2);

    // h split -> A operand
    split_f32<<<(N_TOK * DIM / 4 + 255) / 256, 256>>>(h, ah, al, N_TOK * DIM / 4);

    // QKV (q,k,v all written as bf16 hi/lo)
    gemm_mma<3><<<dim3(8, 32), 256>>>(ah, al, wqh, wql, bq, nullptr, nullptr, qh, ql, N_TOK, DIM, DIM);
    gemm_mma<3><<<dim3(8, 32), 256>>>(ah, al, wkh, wkl, bk, nullptr, nullptr, kh, kl, N_TOK, DIM, DIM);
    gemm_mma<3><<<dim3(8, 32), 256>>>(ah, al, wvh, wvl, bv, nullptr, nullptr, vh, vl, N_TOK, DIM, DIM);

    // block V for pv_mma staging
    vblock<<<N_TOK / 16, 512>>>(vh, vl, vtb);

    // attention phase A: raw scores (HMMA)
    scores_mma<<<dim3(32, 32, 16), 256>>>(qh, ql, kh, kl, s);

    // attention phase C: softmax over heads + PV on tensor cores
    pv_mma<<<N_TOK / 32, 512, PV_SMEM>>>(s, vtb, attn);

    // O projection + residual
    split_f32<<<(N_TOK * DIM / 4 + 255) / 256, 256>>>(attn, ah, al, N_TOK * DIM / 4);
    gemm_mma<1><<<dim3(8, 32), 256>>>(ah, al, woh, wol, bo, h, x, nullptr, nullptr, N_TOK, DIM, DIM);

    // layernorm -> hn
    ln_kernel<<<N_TOK, 256>>>(x, lnw, lnb, out);

    // coord MLP
    split_f32<<<(N_TOK * DIM / 4 + 255) / 256, 256>>>(out, ah, al, N_TOK * DIM / 4);
    gemm_mma<2><<<dim3(4, 32), 256>>>(ah, al, w1h, w1l, b1, nullptr, t, nullptr, nullptr, N_TOK, DIM / 2, DIM);
    mlp2_kernel<<<(N_TOK * 32) / 256, 256>>>(t, W2, b2, cw);

    // pos_update
    posupd_kernel<<<(N_TOK * 3 + 255) / 256, 256>>>(cw, rm, out + (size_t)N_TOK * DIM);
}

// round 10
// speedup vs baseline: 3.6652x; 1.1195x over previous
#include <cuda_runtime.h>
#include <cuda_bf16.h>
#include <cstdint>
#include <math.h>

#define N_TOK 4096
#define DIM   1024
#define NH    16
#define HD    64

typedef unsigned long long ull;
typedef __nv_bfloat16 bf16;

// ===================== HMMA primitives (baseline PTX, no 'a' features) ======
__device__ __forceinline__ uint32_t smem_u32(const void* p) {
    uint32_t a;
    asm("{ .reg .u64 t; cvta.to.shared.u64 t, %1; cvt.u32.u64 %0, t; }"
        : "=r"(a) : "l"(p));
    return a;
}
__device__ __forceinline__ void ldmx4(uint32_t* r, uint32_t addr) {
    asm volatile("ldmatrix.sync.aligned.m8n8.x4.shared.b16 {%0,%1,%2,%3}, [%4];"
                 : "=r"(r[0]), "=r"(r[1]), "=r"(r[2]), "=r"(r[3]) : "r"(addr));
}
__device__ __forceinline__ void mma16816(float* c, const uint32_t* a, const uint32_t* b) {
    asm volatile(
        "mma.sync.aligned.m16n8k16.row.col.f32.bf16.bf16.f32 "
        "{%0,%1,%2,%3}, {%4,%5,%6,%7}, {%8,%9}, {%0,%1,%2,%3};"
        : "+f"(c[0]), "+f"(c[1]), "+f"(c[2]), "+f"(c[3])
        : "r"(a[0]), "r"(a[1]), "r"(a[2]), "r"(a[3]), "r"(b[0]), "r"(b[1]));
}
__device__ __forceinline__ void cpa16(uint32_t dst, const void* src) {
    asm volatile("cp.async.cg.shared.global [%0], [%1], 16;"
                 :: "r"(dst), "l"(src) : "memory");
}
#define CP_COMMIT() asm volatile("cp.async.commit_group;" ::: "memory")
#define CP_WAIT(n)  asm volatile("cp.async.wait_group %0;" :: "n"(n) : "memory")

// dense GEMM smem tile: 128 rows x 32 bf16, row stride 40 (80 B)
#define TROW 40
#define TILE_ELEMS (128 * TROW)
#define GEMM_SMEM (2 * 4 * TILE_ELEMS * 2)      // 81920 B (2 buffers x 4 tiles)

// scores smem: Q persistent + double-buffered K; 128 rows x 64 bf16, stride 72
#define QROW 72
#define QTILE (128 * QROW)                       // 9216 elems
#define SC_SMEM (6 * QTILE * 2)                  // 110592 B

// ===================== scratch globals ======================================
__device__ float g_attn[N_TOK * DIM];
__device__ float g_x[N_TOK * DIM];
__device__ float g_t[N_TOK * (DIM / 2)];
__device__ float g_cw[N_TOK];
__device__ float g_relmean[N_TOK * 3];
__device__ float g_s[(size_t)NH * N_TOK * N_TOK];   // raw scores [h][n][m]

__device__ bf16 g_ah[N_TOK * DIM], g_al[N_TOK * DIM];
__device__ bf16 g_qh[N_TOK * DIM], g_ql[N_TOK * DIM];
__device__ bf16 g_kh[N_TOK * DIM], g_kl[N_TOK * DIM];
__device__ bf16 g_vh[N_TOK * DIM], g_vl[N_TOK * DIM];
__device__ bf16 g_vtb[(size_t)256 * 32 * 64 * 16];  // blocked V [mb][h*2+hl][d][16m]
__device__ bf16 g_wqh[DIM * DIM], g_wql[DIM * DIM];
__device__ bf16 g_wkh[DIM * DIM], g_wkl[DIM * DIM];
__device__ bf16 g_wvh[DIM * DIM], g_wvl[DIM * DIM];
__device__ bf16 g_woh[DIM * DIM], g_wol[DIM * DIM];
__device__ bf16 g_w1h[(DIM / 2) * DIM], g_w1l[(DIM / 2) * DIM];

// ===================== prep kernels =========================================
__global__ __launch_bounds__(256)
void split_f32(const float* __restrict__ X, bf16* __restrict__ hi,
               bf16* __restrict__ lo, int n4)
{
    const int i = blockIdx.x * blockDim.x + threadIdx.x;
    if (i >= n4) return;
    const float4 v = ((const float4*)X)[i];
    const bf16 h0 = __float2bfloat16(v.x), h1 = __float2bfloat16(v.y);
    const bf16 h2 = __float2bfloat16(v.z), h3 = __float2bfloat16(v.w);
    hi[4 * i + 0] = h0; hi[4 * i + 1] = h1; hi[4 * i + 2] = h2; hi[4 * i + 3] = h3;
    lo[4 * i + 0] = __float2bfloat16(v.x - __bfloat162float(h0));
    lo[4 * i + 1] = __float2bfloat16(v.y - __bfloat162float(h1));
    lo[4 * i + 2] = __float2bfloat16(v.z - __bfloat162float(h2));
    lo[4 * i + 3] = __float2bfloat16(v.w - __bfloat162float(h3));
}

__global__ void trsplit(const float* __restrict__ W, bf16* __restrict__ Thi,
                        bf16* __restrict__ Tlo, int K, int N)
{
    __shared__ float t[32][33];
    const int n = blockIdx.x * 32 + threadIdx.x;
    const int k = blockIdx.y * 32 + threadIdx.y;
    t[threadIdx.y][threadIdx.x] = W[(size_t)k * N + n];
    __syncthreads();
    const int nn = blockIdx.x * 32 + threadIdx.y;
    const int kk = blockIdx.y * 32 + threadIdx.x;
    const float v = t[threadIdx.x][threadIdx.y];
    const bf16 h = __float2bfloat16(v);
    Thi[(size_t)nn * K + kk] = h;
    Tlo[(size_t)nn * K + kk] = __float2bfloat16(v - __bfloat162float(h));
}

// block V hi/lo [m][1024] -> [mb][pl=h*2+hl][d][16m]
__global__ __launch_bounds__(512)
void vblock(const bf16* __restrict__ vh, const bf16* __restrict__ vl,
            bf16* __restrict__ out)
{
    __shared__ bf16 sh[16 * 1024];
    __shared__ bf16 sl[16 * 1024];
    const int mb  = blockIdx.x;
    const int tid = threadIdx.x;

#pragma unroll
    for (int j = 0; j < 4; j++) {
        const int e  = j * 512 + tid;
        const int mm = e >> 7;
        const int c8 = e & 127;
        const size_t go = (size_t)(mb * 16 + mm) * DIM + c8 * 8;
        ((uint4*)sh)[e] = *(const uint4*)&vh[go];
        ((uint4*)sl)[e] = *(const uint4*)&vl[go];
    }
    __syncthreads();

#pragma unroll
    for (int j = 0; j < 8; j++) {
        const int e    = j * 512 + tid;
        const int pl   = e >> 7;
        const int d    = (e >> 1) & 63;
        const int half = e & 1;
        const int h    = pl >> 1;
        const bf16* src = (pl & 1) ? sl : sh;
        bf16 tmp[8];
#pragma unroll
        for (int k2 = 0; k2 < 8; k2++)
            tmp[k2] = src[(half * 8 + k2) * 1024 + h * 64 + d];
        *(uint4*)&out[(size_t)mb * 32768 + (size_t)e * 8] = *(uint4*)tmp;
    }
}

// ===================== bf16x2 HMMA GEMM (cp.async double-buffered) ==========
// D[M,N] = A[M,K] @ Bt[N,K]^T + bias. 3 passes: hi*hi + hi*lo + lo*hi.
// EPI: 0 = f32 +bias, 1 = f32 +bias+res, 2 = f32 +bias+SiLU, 3 = bf16 hi/lo
template <int EPI>
__global__ __launch_bounds__(256)
void gemm_mma(const bf16* __restrict__ Ahi, const bf16* __restrict__ Alo,
              const bf16* __restrict__ Bhi, const bf16* __restrict__ Blo,
              const float* __restrict__ bias, const float* __restrict__ res,
              float* __restrict__ Cf, bf16* __restrict__ Chi, bf16* __restrict__ Clo,
              int M, int N, int K)
{
    extern __shared__ bf16 gsm[];
    const uint32_t base = smem_u32(gsm);

    const int tid  = threadIdx.x;
    const int wid  = tid >> 5, lane = tid & 31;
    const int m0   = blockIdx.y * 128, n0 = blockIdx.x * 128;
    const int wm   = (wid & 3) * 32;
    const int wn   = (wid >> 2) * 64;

    float acc[2][8][4];
#pragma unroll
    for (int i = 0; i < 2; i++)
#pragma unroll
        for (int j = 0; j < 8; j++)
#pragma unroll
            for (int r = 0; r < 4; r++) acc[i][j][r] = 0.f;

    const int la_rowA = (lane & 7) + ((lane >> 3) & 1) * 8;
    const int la_kA   = (lane >> 4) * 8;
    const int la_rowB = (lane & 7) + (lane >= 16 ? 8 : 0);
    const int la_kB   = ((lane >> 3) & 1) * 8;

    const int chunks = K >> 5;

    // stage chunk c into buffer b
    const int r_st  = tid >> 2;
    const int cs_st = (tid & 3) * 8;
#define G_STAGE(c, b) do { \
        const uint32_t bb = base + (uint32_t)(b) * 4 * TILE_ELEMS * 2; \
        _Pragma("unroll") \
        for (int t = 0; t < 2; t++) { \
            const int r = r_st + t * 64; \
            const uint32_t so = (uint32_t)(r * TROW + cs_st) * 2; \
            const size_t ga = (size_t)(m0 + r) * K + (c) * 32 + cs_st; \
            const size_t gb = (size_t)(n0 + r) * K + (c) * 32 + cs_st; \
            cpa16(bb + so,                      Ahi + ga); \
            cpa16(bb + TILE_ELEMS * 2 + so,     Alo + ga); \
            cpa16(bb + TILE_ELEMS * 4 + so,     Bhi + gb); \
            cpa16(bb + TILE_ELEMS * 6 + so,     Blo + gb); \
        } \
        CP_COMMIT(); \
    } while (0)

    G_STAGE(0, 0);

    for (int c = 0; c < chunks; c++) {
        if (c + 1 < chunks) { G_STAGE(c + 1, (c + 1) & 1); CP_WAIT(1); }
        else                { CP_WAIT(0); }
        __syncthreads();

        const uint32_t bb  = base + (uint32_t)(c & 1) * 4 * TILE_ELEMS * 2;
        const uint32_t aAh = bb;
        const uint32_t aAl = bb + TILE_ELEMS * 2;
        const uint32_t aBh = bb + TILE_ELEMS * 4;
        const uint32_t aBl = bb + TILE_ELEMS * 6;

#pragma unroll
        for (int ks = 0; ks < 32; ks += 16) {
            uint32_t ah[2][4], al[2][4];
#pragma unroll
            for (int mt = 0; mt < 2; mt++) {
                const uint32_t off =
                    (uint32_t)((wm + mt * 16 + la_rowA) * TROW + ks + la_kA) * 2;
                ldmx4(ah[mt], aAh + off);
                ldmx4(al[mt], aAl + off);
            }
#pragma unroll
            for (int nt2 = 0; nt2 < 4; nt2++) {
                uint32_t bh[4], bl[4];
                const uint32_t off =
                    (uint32_t)((wn + nt2 * 16 + la_rowB) * TROW + ks + la_kB) * 2;
                ldmx4(bh, aBh + off);
                ldmx4(bl, aBl + off);
#pragma unroll
                for (int sub = 0; sub < 2; sub++) {
#pragma unroll
                    for (int mt = 0; mt < 2; mt++) {
                        float* cc = acc[mt][nt2 * 2 + sub];
                        mma16816(cc, ah[mt], &bh[sub * 2]);
                        mma16816(cc, ah[mt], &bl[sub * 2]);
                        mma16816(cc, al[mt], &bh[sub * 2]);
                    }
                }
            }
        }
        __syncthreads();
    }
#undef G_STAGE

#pragma unroll
    for (int mt = 0; mt < 2; mt++) {
#pragma unroll
        for (int nt = 0; nt < 8; nt++) {
            const int row = m0 + wm + mt * 16 + (lane >> 2);
            const int col = n0 + wn + nt * 8 + (lane & 3) * 2;
#pragma unroll
            for (int half = 0; half < 2; half++) {
                const int rr = row + half * 8;
                float v0 = acc[mt][nt][half * 2 + 0] + bias[col + 0];
                float v1 = acc[mt][nt][half * 2 + 1] + bias[col + 1];
                if (EPI == 1) {
                    const float2 r2 = *(const float2*)&res[(size_t)rr * N + col];
                    v0 += r2.x; v1 += r2.y;
                }
                if (EPI == 2) {
                    v0 = v0 / (1.f + __expf(-v0));
                    v1 = v1 / (1.f + __expf(-v1));
                }
                if (EPI == 3) {
                    const size_t o = (size_t)rr * N + col;
                    const bf16 h0 = __float2bfloat16(v0), h1 = __float2bfloat16(v1);
                    Chi[o + 0] = h0; Chi[o + 1] = h1;
                    Clo[o + 0] = __float2bfloat16(v0 - __bfloat162float(h0));
                    Clo[o + 1] = __float2bfloat16(v1 - __bfloat162float(h1));
                } else {
                    *(float2*)&Cf[(size_t)rr * N + col] = make_float2(v0, v1);
                }
            }
        }
    }
}

// ===================== scores2: Q-persistent, m-looped, K double-buffered ===
// grid (n/128, h). Per block: stage Q[128n x 64k] hi/lo once; loop 32 m-blocks
// with cp.async prefetch; per m-block compute S tile and store.
__global__ __launch_bounds__(256)
void scores2(const bf16* __restrict__ Qhi, const bf16* __restrict__ Qlo,
             const bf16* __restrict__ Khi, const bf16* __restrict__ Klo,
             float* __restrict__ S)
{
    extern __shared__ bf16 ssm[];
    const uint32_t base = smem_u32(ssm);
    const uint32_t aQh = base;
    const uint32_t aQl = base + QTILE * 2;
    // K buffers: [buf][hi/lo]
    const uint32_t aK0h = base + QTILE * 4;
    const uint32_t aK0l = base + QTILE * 6;
    const uint32_t aK1h = base + QTILE * 8;
    const uint32_t aK1l = base + QTILE * 10;

    const int tid  = threadIdx.x;
    const int wid  = tid >> 5, lane = tid & 31;
    const int nq0  = blockIdx.x * 128;
    const int h    = blockIdx.y;
    const int wm   = (wid & 3) * 32;     // n-direction (A side)
    const int wn   = (wid >> 2) * 64;    // m-direction (B side)

    const int r_st  = tid >> 1;          // 0..127
    const int c8_st = (tid & 1) * 4;     // 0 or 4 (x8 elems each)

    // stage Q + K block 0 (one cp.async group)
#pragma unroll
    for (int t = 0; t < 2; t++) {
        const int c8 = c8_st + t;        // wait — need 8 segs/row over 2 thr
        // each row has 8 uint4 segs; 2 threads/row x 4 segs each
#pragma unroll
        for (int u = 0; u < 4; u++) {
            // only run once (t==0) to avoid duplication
            if (t == 0) {
                const int seg = c8_st + u; // 0..7
                const uint32_t so = (uint32_t)(r_st * QROW + seg * 8) * 2;
                const size_t gq = (size_t)(nq0 + r_st) * DIM + h * 64 + seg * 8;
                const size_t gk = (size_t)(0 + r_st) * DIM + h * 64 + seg * 8;
                cpa16(aQh + so, Qhi + gq);
                cpa16(aQl + so, Qlo + gq);
                cpa16(aK0h + so, Khi + gk);
                cpa16(aK0l + so, Klo + gk);
            }
        }
    }
    CP_COMMIT();

    const int la_rowA = (lane & 7) + ((lane >> 3) & 1) * 8;
    const int la_kA   = (lane >> 4) * 8;
    const int la_rowB = (lane & 7) + (lane >= 16 ? 8 : 0);
    const int la_kB   = ((lane >> 3) & 1) * 8;

    float* Sp = S + (size_t)h * N_TOK * N_TOK;

    for (int mb = 0; mb < 32; mb++) {
        if (mb + 1 < 32) {
            const uint32_t kh = ((mb + 1) & 1) ? aK1h : aK0h;
            const uint32_t kl = ((mb + 1) & 1) ? aK1l : aK0l;
#pragma unroll
            for (int u = 0; u < 4; u++) {
                const int seg = c8_st + u;
                const uint32_t so = (uint32_t)(r_st * QROW + seg * 8) * 2;
                const size_t gk = (size_t)((mb + 1) * 128 + r_st) * DIM + h * 64 + seg * 8;
                cpa16(kh + so, Khi + gk);
                cpa16(kl + so, Klo + gk);
            }
            CP_COMMIT();
            CP_WAIT(1);
        } else {
            CP_WAIT(0);
        }
        __syncthreads();

        const uint32_t aKh = (mb & 1) ? aK1h : aK0h;
        const uint32_t aKl = (mb & 1) ? aK1l : aK0l;

        float acc[2][8][4];
#pragma unroll
        for (int i = 0; i < 2; i++)
#pragma unroll
            for (int j = 0; j < 8; j++)
#pragma unroll
                for (int r = 0; r < 4; r++) acc[i][j][r] = 0.f;

#pragma unroll
        for (int ks = 0; ks < 64; ks += 16) {
            uint32_t ah[2][4], al[2][4];
#pragma unroll
            for (int mt = 0; mt < 2; mt++) {
                const uint32_t off =
                    (uint32_t)((wm + mt * 16 + la_rowA) * QROW + ks + la_kA) * 2;
                ldmx4(ah[mt], aQh + off);
                ldmx4(al[mt], aQl + off);
            }
#pragma unroll
            for (int nt2 = 0; nt2 < 4; nt2++) {
                uint32_t bh[4], bl[4];
                const uint32_t off =
                    (uint32_t)((wn + nt2 * 16 + la_rowB) * QROW + ks + la_kB) * 2;
                ldmx4(bh, aKh + off);
                ldmx4(bl, aKl + off);
#pragma unroll
                for (int sub = 0; sub < 2; sub++) {
#pragma unroll
                    for (int mt = 0; mt < 2; mt++) {
                        float* cc = acc[mt][nt2 * 2 + sub];
                        mma16816(cc, ah[mt], &bh[sub * 2]);
                        mma16816(cc, ah[mt], &bl[sub * 2]);
                        mma16816(cc, al[mt], &bh[sub * 2]);
                    }
                }
            }
        }

        // store S tile
#pragma unroll
        for (int mt = 0; mt < 2; mt++) {
#pragma unroll
            for (int nt = 0; nt < 8; nt++) {
                const int row = nq0 + wm + mt * 16 + (lane >> 2);
                const int col = mb * 128 + wn + nt * 8 + (lane & 3) * 2;
#pragma unroll
                for (int half = 0; half < 2; half++) {
                    *(float2*)&Sp[(size_t)(row + half * 8) * N_TOK + col] =
                        make_float2(acc[mt][nt][half * 2 + 0],
                                    acc[mt][nt][half * 2 + 1]);
                }
            }
        }
        __syncthreads();
    }
}

// ===================== Phase C: softmax-over-heads + PV on HMMA =============
#define P_PLANE 768
#define V_PLANE 2560
#define PV_SMEM ((32 * P_PLANE + 32 * V_PLANE) * 2)   // 212992 B

__global__ __launch_bounds__(512, 1)
void pv_mma(const float* __restrict__ S, const bf16* __restrict__ Vtb,
            float* __restrict__ O)
{
    extern __shared__ bf16 smb[];
    bf16* ps = smb;
    bf16* vs = smb + 32 * P_PLANE;

    const int tid  = threadIdx.x;
    const int wid  = tid >> 5;
    const int lane = tid & 31;
    const int n0   = blockIdx.x * 32;
    const int nn   = tid >> 4;
    const int mmq  = tid & 15;

    const uint32_t psb = smem_u32(ps);
    const uint32_t vsb = smem_u32(vs);

    float acc[2][8][4];
#pragma unroll
    for (int i = 0; i < 2; i++)
#pragma unroll
        for (int j = 0; j < 8; j++)
#pragma unroll
            for (int r = 0; r < 4; r++) acc[i][j][r] = 0.f;

    const int la_rowA = (lane & 7) + ((lane >> 3) & 1) * 8;
    const int la_kA   = (lane >> 4) * 8;
    const int la_rowB = (lane & 7) + (lane >= 16 ? 8 : 0);
    const int la_kB   = ((lane >> 3) & 1) * 8;

    const size_t N2 = (size_t)N_TOK * N_TOK;
    const float* sp0 = S + (size_t)(n0 + nn) * N_TOK + mmq;

    for (int mt0 = 0; mt0 < N_TOK / 16; mt0++) {
        const int m0 = mt0 * 16;

        const uint4* vsrc = (const uint4*)(Vtb + (size_t)mt0 * 32768);
#pragma unroll
        for (int j = 0; j < 8; j++) {
            const int e    = j * 512 + tid;
            const int pl   = e >> 7;
            const int d    = (e >> 1) & 63;
            const int half = e & 1;
            *(uint4*)&vs[pl * V_PLANE + d * 40 + half * 8] = vsrc[e];
        }

        {
            const float* sp = sp0 + m0;
            float sv[16];
#pragma unroll
            for (int q = 0; q < 16; q++) sv[q] = sp[(size_t)q * N2] * 0.125f;
            float mx = sv[0];
#pragma unroll
            for (int q = 1; q < 16; q++) mx = fmaxf(mx, sv[q]);
            float ssum = 0.f;
#pragma unroll
            for (int q = 0; q < 16; q++) { sv[q] = __expf(sv[q] - mx); ssum += sv[q]; }
            const float rinv = __fdividef(1.f, ssum);
#pragma unroll
            for (int q = 0; q < 16; q++) {
                const float p  = sv[q] * rinv;
                const bf16  ph = __float2bfloat16(p);
                ps[(q * 2 + 0) * P_PLANE + nn * 24 + mmq] = ph;
                ps[(q * 2 + 1) * P_PLANE + nn * 24 + mmq] =
                    __float2bfloat16(p - __bfloat162float(ph));
            }
        }
        __syncthreads();

        {
            const uint32_t pbh = psb + (uint32_t)(wid * 2 + 0) * P_PLANE * 2;
            const uint32_t pbl = psb + (uint32_t)(wid * 2 + 1) * P_PLANE * 2;
            const uint32_t vbh = vsb + (uint32_t)(wid * 2 + 0) * V_PLANE * 2;
            const uint32_t vbl = vsb + (uint32_t)(wid * 2 + 1) * V_PLANE * 2;

            uint32_t ah[2][4], al[2][4];
#pragma unroll
            for (int mt = 0; mt < 2; mt++) {
                const uint32_t off =
                    (uint32_t)((mt * 16 + la_rowA) * 24 + la_kA) * 2;
                ldmx4(ah[mt], pbh + off);
                ldmx4(al[mt], pbl + off);
            }
#pragma unroll
            for (int nt2 = 0; nt2 < 4; nt2++) {
                uint32_t bh[4], bl[4];
                const uint32_t off =
                    (uint32_t)((nt2 * 16 + la_rowB) * 40 + la_kB) * 2;
                ldmx4(bh, vbh + off);
                ldmx4(bl, vbl + off);
#pragma unroll
                for (int sub = 0; sub < 2; sub++) {
#pragma unroll
                    for (int mt = 0; mt < 2; mt++) {
                        float* c = acc[mt][nt2 * 2 + sub];
                        mma16816(c, ah[mt], &bh[sub * 2]);
                        mma16816(c, ah[mt], &bl[sub * 2]);
                        mma16816(c, al[mt], &bh[sub * 2]);
                    }
                }
            }
        }
        __syncthreads();
    }

#pragma unroll
    for (int mt = 0; mt < 2; mt++) {
#pragma unroll
        for (int nt = 0; nt < 8; nt++) {
            const int row = n0 + mt * 16 + (lane >> 2);
            const int col = wid * 64 + nt * 8 + (lane & 3) * 2;
#pragma unroll
            for (int half = 0; half < 2; half++) {
                *(float2*)&O[(size_t)(row + half * 8) * DIM + col] =
                    make_float2(acc[mt][nt][half * 2 + 0], acc[mt][nt][half * 2 + 1]);
            }
        }
    }
}

// ===================== LayerNorm ============================================
__global__ __launch_bounds__(256)
void ln_kernel(const float* __restrict__ X, const float* __restrict__ w,
               const float* __restrict__ b, float* __restrict__ out)
{
    const int n   = blockIdx.x;
    const int tid = threadIdx.x;
    const float4 x = ((const float4*)(X + (size_t)n * DIM))[tid];

    float s  = x.x + x.y + x.z + x.w;
    float ss = x.x * x.x + x.y * x.y + x.z * x.z + x.w * x.w;
#pragma unroll
    for (int off = 16; off; off >>= 1) {
        s  += __shfl_xor_sync(0xffffffffu, s, off);
        ss += __shfl_xor_sync(0xffffffffu, ss, off);
    }
    __shared__ float rs[8], rss[8], stat[2];
    if ((tid & 31) == 0) { rs[tid >> 5] = s; rss[tid >> 5] = ss; }
    __syncthreads();
    if (tid == 0) {
        float S = 0.f, SS = 0.f;
#pragma unroll
        for (int i = 0; i < 8; i++) { S += rs[i]; SS += rss[i]; }
        const float mean = S * (1.f / DIM);
        const float var  = SS * (1.f / DIM) - mean * mean;
        stat[0] = mean;
        stat[1] = rsqrtf(var + 1e-5f);
    }
    __syncthreads();
    const float mean = stat[0], inv = stat[1];
    const int col = tid * 4;
    const float4 wv = *(const float4*)&w[col];
    const float4 bv = *(const float4*)&b[col];
    float4 o;
    o.x = (x.x - mean) * inv * wv.x + bv.x;
    o.y = (x.y - mean) * inv * wv.y + bv.y;
    o.z = (x.z - mean) * inv * wv.z + bv.z;
    o.w = (x.w - mean) * inv * wv.w + bv.w;
    ((float4*)(out + (size_t)n * DIM))[tid] = o;
}

// ===================== coord MLP layer 2 ====================================
__global__ void mlp2_kernel(const float* __restrict__ T, const float* __restrict__ W2,
                            const float* __restrict__ b2, float* __restrict__ cw)
{
    const int warp = (blockIdx.x * blockDim.x + threadIdx.x) >> 5;
    const int lane = threadIdx.x & 31;
    if (warp >= N_TOK) return;
    const float* t = T + (size_t)warp * (DIM / 2);
    float s = 0.f;
#pragma unroll
    for (int j = 0; j < DIM / 2; j += 32) s = fmaf(t[j + lane], W2[j + lane], s);
#pragma unroll
    for (int off = 16; off; off >>= 1) s += __shfl_xor_sync(0xffffffffu, s, off);
    if (lane == 0) cw[warp] = s + b2[0];
}

// ===================== rel_pos mean =========================================
__global__ __launch_bounds__(128)
void relmean_kernel(const float* __restrict__ rel, float* __restrict__ out)
{
    const int n   = blockIdx.x;
    const int tid = threadIdx.x;
    const float* base = rel + (size_t)n * N_TOK * 3;
    float s0 = 0.f, s1 = 0.f, s2 = 0.f;
    for (int m = tid; m < N_TOK; m += 128) {
        s0 += base[m * 3 + 0];
        s1 += base[m * 3 + 1];
        s2 += base[m * 3 + 2];
    }
#pragma unroll
    for (int off = 16; off; off >>= 1) {
        s0 += __shfl_xor_sync(0xffffffffu, s0, off);
        s1 += __shfl_xor_sync(0xffffffffu, s1, off);
        s2 += __shfl_xor_sync(0xffffffffu, s2, off);
    }
    __shared__ float sm[3][4];
    if ((tid & 31) == 0) {
        sm[0][tid >> 5] = s0; sm[1][tid >> 5] = s1; sm[2][tid >> 5] = s2;
    }
    __syncthreads();
    if (tid == 0) {
        out[n * 3 + 0] = (sm[0][0] + sm[0][1] + sm[0][2] + sm[0][3]) * (1.f / N_TOK);
        out[n * 3 + 1] = (sm[1][0] + sm[1][1] + sm[1][2] + sm[1][3]) * (1.f / N_TOK);
        out[n * 3 + 2] = (sm[2][0] + sm[2][1] + sm[2][2] + sm[2][3]) * (1.f / N_TOK);
    }
}

// ===================== pos_update ===========================================
__global__ void posupd_kernel(const float* __restrict__ cw, const float* __restrict__ rm,
                              float* __restrict__ out)
{
    const int i = blockIdx.x * blockDim.x + threadIdx.x;
    if (i < N_TOK * 3) out[i] = cw[i / 3] * rm[i];
}

// ===================== launcher =============================================
extern "C" void kernel_launch(void* const* d_in, const int* in_sizes, int n_in,
                              void* d_out, int out_size)
{
    const float* h    = (const float*)d_in[0];
    const float* rel  = (const float*)d_in[1];
    const float* Wq   = (const float*)d_in[2];
    const float* bq   = (const float*)d_in[3];
    const float* Wk   = (const float*)d_in[4];
    const float* bk   = (const float*)d_in[5];
    const float* Wv   = (const float*)d_in[6];
    const float* bv   = (const float*)d_in[7];
    const float* Wo   = (const float*)d_in[8];
    const float* bo   = (const float*)d_in[9];
    const float* W1   = (const float*)d_in[10];
    const float* b1   = (const float*)d_in[11];
    const float* W2   = (const float*)d_in[12];
    const float* b2   = (const float*)d_in[13];
    const float* lnw  = (const float*)d_in[14];
    const float* lnb  = (const float*)d_in[15];
    float* out = (float*)d_out;

    float *attn, *x, *t, *cw, *rm, *s;
    bf16 *ah, *al, *qh, *ql, *kh, *kl, *vh, *vl, *vtb;
    bf16 *wqh, *wql, *wkh, *wkl, *wvh, *wvl, *woh, *wol, *w1h, *w1l;
    cudaGetSymbolAddress((void**)&attn, g_attn);
    cudaGetSymbolAddress((void**)&x,    g_x);
    cudaGetSymbolAddress((void**)&t,    g_t);
    cudaGetSymbolAddress((void**)&cw,   g_cw);
    cudaGetSymbolAddress((void**)&rm,   g_relmean);
    cudaGetSymbolAddress((void**)&s,    g_s);
    cudaGetSymbolAddress((void**)&ah,   g_ah);
    cudaGetSymbolAddress((void**)&al,   g_al);
    cudaGetSymbolAddress((void**)&qh,   g_qh);
    cudaGetSymbolAddress((void**)&ql,   g_ql);
    cudaGetSymbolAddress((void**)&kh,   g_kh);
    cudaGetSymbolAddress((void**)&kl,   g_kl);
    cudaGetSymbolAddress((void**)&vh,   g_vh);
    cudaGetSymbolAddress((void**)&vl,   g_vl);
    cudaGetSymbolAddress((void**)&vtb,  g_vtb);
    cudaGetSymbolAddress((void**)&wqh,  g_wqh);
    cudaGetSymbolAddress((void**)&wql,  g_wql);
    cudaGetSymbolAddress((void**)&wkh,  g_wkh);
    cudaGetSymbolAddress((void**)&wkl,  g_wkl);
    cudaGetSymbolAddress((void**)&wvh,  g_wvh);
    cudaGetSymbolAddress((void**)&wvl,  g_wvl);
    cudaGetSymbolAddress((void**)&woh,  g_woh);
    cudaGetSymbolAddress((void**)&wol,  g_wol);
    cudaGetSymbolAddress((void**)&w1h,  g_w1h);
    cudaGetSymbolAddress((void**)&w1l,  g_w1l);

    cudaFuncSetAttribute(pv_mma,     cudaFuncAttributeMaxDynamicSharedMemorySize, PV_SMEM);
    cudaFuncSetAttribute(scores2,    cudaFuncAttributeMaxDynamicSharedMemorySize, SC_SMEM);
    cudaFuncSetAttribute(gemm_mma<0>, cudaFuncAttributeMaxDynamicSharedMemorySize, GEMM_SMEM);
    cudaFuncSetAttribute(gemm_mma<1>, cudaFuncAttributeMaxDynamicSharedMemorySize, GEMM_SMEM);
    cudaFuncSetAttribute(gemm_mma<2>, cudaFuncAttributeMaxDynamicSharedMemorySize, GEMM_SMEM);
    cudaFuncSetAttribute(gemm_mma<3>, cudaFuncAttributeMaxDynamicSharedMemorySize, GEMM_SMEM);

    // independent: rel_pos mean
    relmean_kernel<<<N_TOK, 128>>>(rel, rm);

    // weight prep: transpose + bf16 split
    trsplit<<<dim3(32, 32), dim3(32, 32)>>>(Wq, wqh, wql, DIM, DIM);
    trsplit<<<dim3(32, 32), dim3(32, 32)>>>(Wk, wkh, wkl, DIM, DIM);
    trsplit<<<dim3(32, 32), dim3(32, 32)>>>(Wv, wvh, wvl, DIM, DIM);
    trsplit<<<dim3(32, 32), dim3(32, 32)>>>(Wo, woh, wol, DIM, DIM);
    trsplit<<<dim3(16, 32), dim3(32, 32)>>>(W1, w1h, w1l, DIM, DIM / 2);

    // h split -> A operand
    split_f32<<<(N_TOK * DIM / 4 + 255) / 256, 256>>>(h, ah, al, N_TOK * DIM / 4);

    // QKV (all written as bf16 hi/lo)
    gemm_mma<3><<<dim3(8, 32), 256, GEMM_SMEM>>>(ah, al, wqh, wql, bq, nullptr, nullptr, qh, ql, N_TOK, DIM, DIM);
    gemm_mma<3><<<dim3(8, 32), 256, GEMM_SMEM>>>(ah, al, wkh, wkl, bk, nullptr, nullptr, kh, kl, N_TOK, DIM, DIM);
    gemm_mma<3><<<dim3(8, 32), 256, GEMM_SMEM>>>(ah, al, wvh, wvl, bv, nullptr, nullptr, vh, vl, N_TOK, DIM, DIM);

    // block V for pv_mma staging
    vblock<<<N_TOK / 16, 512>>>(vh, vl, vtb);

    // attention phase A: raw scores (Q-persistent, K double-buffered)
    scores2<<<dim3(32, 16), 256, SC_SMEM>>>(qh, ql, kh, kl, s);

    // attention phase C: softmax over heads + PV on tensor cores
    pv_mma<<<N_TOK / 32, 512, PV_SMEM>>>(s, vtb, attn);

    // O projection + residual
    split_f32<<<(N_TOK * DIM / 4 + 255) / 256, 256>>>(attn, ah, al, N_TOK * DIM / 4);
    gemm_mma<1><<<dim3(8, 32), 256, GEMM_SMEM>>>(ah, al, woh, wol, bo, h, x, nullptr, nullptr, N_TOK, DIM, DIM);

    // layernorm -> hn
    ln_kernel<<<N_TOK, 256>>>(x, lnw, lnb, out);

    // coord MLP
    split_f32<<<(N_TOK * DIM / 4 + 255) / 256, 256>>>(out, ah, al, N_TOK * DIM / 4);
    gemm_mma<2><<<dim3(4, 32), 256, GEMM_SMEM>>>(ah, al, w1h, w1l, b1, nullptr, t, nullptr, nullptr, N_TOK, DIM / 2, DIM);
    mlp2_kernel<<<(N_TOK * 32) / 256, 256>>>(t, W2, b2, cw);

    // pos_update
    posupd_kernel<<<(N_TOK * 3 + 255) / 256, 256>>>(cw, rm, out + (size_t)N_TOK * DIM);
}

// round 11
// speedup vs baseline: 3.7313x; 1.0180x over previous
#include <cuda_runtime.h>
#include <cuda_bf16.h>
#include <cuda_fp16.h>
#include <cstdint>
#include <math.h>

#define N_TOK 4096
#define DIM   1024
#define NH    16
#define HD    64

typedef unsigned long long ull;
typedef __nv_bfloat16 bf16;

// ===================== HMMA primitives (baseline PTX, no 'a' features) ======
__device__ __forceinline__ uint32_t smem_u32(const void* p) {
    uint32_t a;
    asm("{ .reg .u64 t; cvta.to.shared.u64 t, %1; cvt.u32.u64 %0, t; }"
        : "=r"(a) : "l"(p));
    return a;
}
__device__ __forceinline__ void ldmx4(uint32_t* r, uint32_t addr) {
    asm volatile("ldmatrix.sync.aligned.m8n8.x4.shared.b16 {%0,%1,%2,%3}, [%4];"
                 : "=r"(r[0]), "=r"(r[1]), "=r"(r[2]), "=r"(r[3]) : "r"(addr));
}
__device__ __forceinline__ void mma16816(float* c, const uint32_t* a, const uint32_t* b) {
    asm volatile(
        "mma.sync.aligned.m16n8k16.row.col.f32.bf16.bf16.f32 "
        "{%0,%1,%2,%3}, {%4,%5,%6,%7}, {%8,%9}, {%0,%1,%2,%3};"
        : "+f"(c[0]), "+f"(c[1]), "+f"(c[2]), "+f"(c[3])
        : "r"(a[0]), "r"(a[1]), "r"(a[2]), "r"(a[3]), "r"(b[0]), "r"(b[1]));
}
__device__ __forceinline__ void cpa16(uint32_t dst, const void* src) {
    asm volatile("cp.async.cg.shared.global [%0], [%1], 16;"
                 :: "r"(dst), "l"(src) : "memory");
}
#define CP_COMMIT() asm volatile("cp.async.commit_group;" ::: "memory")
#define CP_WAIT(n)  asm volatile("cp.async.wait_group %0;" :: "n"(n) : "memory")

// dense GEMM smem tile: 128 rows x 32 bf16, row stride 40 (80 B)
#define TROW 40
#define TILE_ELEMS (128 * TROW)
#define GEMM_SMEM (2 * 4 * TILE_ELEMS * 2)      // 81920 B

// scores smem: Q persistent + double-buffered K; 128 rows x 64 bf16, stride 72
#define QROW 72
#define QTILE (128 * QROW)
#define SC_SMEM (6 * QTILE * 2)                  // 110592 B

// ===================== scratch globals ======================================
__device__ float g_attn[N_TOK * DIM];
__device__ float g_x[N_TOK * DIM];
__device__ float g_t[N_TOK * (DIM / 2)];
__device__ float g_cw[N_TOK];
__device__ float g_relmean[N_TOK * 3];
__device__ __half g_s[(size_t)NH * N_TOK * N_TOK];  // raw scores [h][n][m], fp16

__device__ bf16 g_ah[N_TOK * DIM], g_al[N_TOK * DIM];
__device__ bf16 g_qh[N_TOK * DIM], g_ql[N_TOK * DIM];
__device__ bf16 g_kh[N_TOK * DIM], g_kl[N_TOK * DIM];
__device__ bf16 g_vh[N_TOK * DIM], g_vl[N_TOK * DIM];
__device__ bf16 g_vtb[(size_t)256 * 32 * 64 * 16];  // blocked V [mb][h*2+hl][d][16m]
__device__ bf16 g_wqh[DIM * DIM], g_wql[DIM * DIM];
__device__ bf16 g_wkh[DIM * DIM], g_wkl[DIM * DIM];
__device__ bf16 g_wvh[DIM * DIM], g_wvl[DIM * DIM];
__device__ bf16 g_woh[DIM * DIM], g_wol[DIM * DIM];
__device__ bf16 g_w1h[(DIM / 2) * DIM], g_w1l[(DIM / 2) * DIM];

// ===================== prep kernels =========================================
__global__ __launch_bounds__(256)
void split_f32(const float* __restrict__ X, bf16* __restrict__ hi,
               bf16* __restrict__ lo, int n4)
{
    const int i = blockIdx.x * blockDim.x + threadIdx.x;
    if (i >= n4) return;
    const float4 v = ((const float4*)X)[i];
    const bf16 h0 = __float2bfloat16(v.x), h1 = __float2bfloat16(v.y);
    const bf16 h2 = __float2bfloat16(v.z), h3 = __float2bfloat16(v.w);
    hi[4 * i + 0] = h0; hi[4 * i + 1] = h1; hi[4 * i + 2] = h2; hi[4 * i + 3] = h3;
    lo[4 * i + 0] = __float2bfloat16(v.x - __bfloat162float(h0));
    lo[4 * i + 1] = __float2bfloat16(v.y - __bfloat162float(h1));
    lo[4 * i + 2] = __float2bfloat16(v.z - __bfloat162float(h2));
    lo[4 * i + 3] = __float2bfloat16(v.w - __bfloat162float(h3));
}

__global__ void trsplit(const float* __restrict__ W, bf16* __restrict__ Thi,
                        bf16* __restrict__ Tlo, int K, int N)
{
    __shared__ float t[32][33];
    const int n = blockIdx.x * 32 + threadIdx.x;
    const int k = blockIdx.y * 32 + threadIdx.y;
    t[threadIdx.y][threadIdx.x] = W[(size_t)k * N + n];
    __syncthreads();
    const int nn = blockIdx.x * 32 + threadIdx.y;
    const int kk = blockIdx.y * 32 + threadIdx.x;
    const float v = t[threadIdx.x][threadIdx.y];
    const bf16 h = __float2bfloat16(v);
    Thi[(size_t)nn * K + kk] = h;
    Tlo[(size_t)nn * K + kk] = __float2bfloat16(v - __bfloat162float(h));
}

// block V hi/lo [m][1024] -> [mb][pl=h*2+hl][d][16m]
__global__ __launch_bounds__(512)
void vblock(const bf16* __restrict__ vh, const bf16* __restrict__ vl,
            bf16* __restrict__ out)
{
    __shared__ bf16 sh[16 * 1024];
    __shared__ bf16 sl[16 * 1024];
    const int mb  = blockIdx.x;
    const int tid = threadIdx.x;

#pragma unroll
    for (int j = 0; j < 4; j++) {
        const int e  = j * 512 + tid;
        const int mm = e >> 7;
        const int c8 = e & 127;
        const size_t go = (size_t)(mb * 16 + mm) * DIM + c8 * 8;
        ((uint4*)sh)[e] = *(const uint4*)&vh[go];
        ((uint4*)sl)[e] = *(const uint4*)&vl[go];
    }
    __syncthreads();

#pragma unroll
    for (int j = 0; j < 8; j++) {
        const int e    = j * 512 + tid;
        const int pl   = e >> 7;
        const int d    = (e >> 1) & 63;
        const int half = e & 1;
        const int h    = pl >> 1;
        const bf16* src = (pl & 1) ? sl : sh;
        bf16 tmp[8];
#pragma unroll
        for (int k2 = 0; k2 < 8; k2++)
            tmp[k2] = src[(half * 8 + k2) * 1024 + h * 64 + d];
        *(uint4*)&out[(size_t)mb * 32768 + (size_t)e * 8] = *(uint4*)tmp;
    }
}

// ===================== bf16x2 HMMA GEMM (cp.async double-buffered) ==========
template <int EPI>
__global__ __launch_bounds__(256)
void gemm_mma(const bf16* __restrict__ Ahi, const bf16* __restrict__ Alo,
              const bf16* __restrict__ Bhi, const bf16* __restrict__ Blo,
              const float* __restrict__ bias, const float* __restrict__ res,
              float* __restrict__ Cf, bf16* __restrict__ Chi, bf16* __restrict__ Clo,
              int M, int N, int K)
{
    extern __shared__ bf16 gsm[];
    const uint32_t base = smem_u32(gsm);

    const int tid  = threadIdx.x;
    const int wid  = tid >> 5, lane = tid & 31;
    const int m0   = blockIdx.y * 128, n0 = blockIdx.x * 128;
    const int wm   = (wid & 3) * 32;
    const int wn   = (wid >> 2) * 64;

    float acc[2][8][4];
#pragma unroll
    for (int i = 0; i < 2; i++)
#pragma unroll
        for (int j = 0; j < 8; j++)
#pragma unroll
            for (int r = 0; r < 4; r++) acc[i][j][r] = 0.f;

    const int la_rowA = (lane & 7) + ((lane >> 3) & 1) * 8;
    const int la_kA   = (lane >> 4) * 8;
    const int la_rowB = (lane & 7) + (lane >= 16 ? 8 : 0);
    const int la_kB   = ((lane >> 3) & 1) * 8;

    const int chunks = K >> 5;
    const int r_st  = tid >> 2;
    const int cs_st = (tid & 3) * 8;
#define G_STAGE(c, b) do { \
        const uint32_t bb = base + (uint32_t)(b) * 4 * TILE_ELEMS * 2; \
        _Pragma("unroll") \
        for (int t = 0; t < 2; t++) { \
            const int r = r_st + t * 64; \
            const uint32_t so = (uint32_t)(r * TROW + cs_st) * 2; \
            const size_t ga = (size_t)(m0 + r) * K + (c) * 32 + cs_st; \
            const size_t gb = (size_t)(n0 + r) * K + (c) * 32 + cs_st; \
            cpa16(bb + so,                      Ahi + ga); \
            cpa16(bb + TILE_ELEMS * 2 + so,     Alo + ga); \
            cpa16(bb + TILE_ELEMS * 4 + so,     Bhi + gb); \
            cpa16(bb + TILE_ELEMS * 6 + so,     Blo + gb); \
        } \
        CP_COMMIT(); \
    } while (0)

    G_STAGE(0, 0);

    for (int c = 0; c < chunks; c++) {
        if (c + 1 < chunks) { G_STAGE(c + 1, (c + 1) & 1); CP_WAIT(1); }
        else                { CP_WAIT(0); }
        __syncthreads();

        const uint32_t bb  = base + (uint32_t)(c & 1) * 4 * TILE_ELEMS * 2;
        const uint32_t aAh = bb;
        const uint32_t aAl = bb + TILE_ELEMS * 2;
        const uint32_t aBh = bb + TILE_ELEMS * 4;
        const uint32_t aBl = bb + TILE_ELEMS * 6;

#pragma unroll
        for (int ks = 0; ks < 32; ks += 16) {
            uint32_t ah[2][4], al[2][4];
#pragma unroll
            for (int mt = 0; mt < 2; mt++) {
                const uint32_t off =
                    (uint32_t)((wm + mt * 16 + la_rowA) * TROW + ks + la_kA) * 2;
                ldmx4(ah[mt], aAh + off);
                ldmx4(al[mt], aAl + off);
            }
#pragma unroll
            for (int nt2 = 0; nt2 < 4; nt2++) {
                uint32_t bh[4], bl[4];
                const uint32_t off =
                    (uint32_t)((wn + nt2 * 16 + la_rowB) * TROW + ks + la_kB) * 2;
                ldmx4(bh, aBh + off);
                ldmx4(bl, aBl + off);
#pragma unroll
                for (int sub = 0; sub < 2; sub++) {
#pragma unroll
                    for (int mt = 0; mt < 2; mt++) {
                        float* cc = acc[mt][nt2 * 2 + sub];
                        mma16816(cc, ah[mt], &bh[sub * 2]);
                        mma16816(cc, ah[mt], &bl[sub * 2]);
                        mma16816(cc, al[mt], &bh[sub * 2]);
                    }
                }
            }
        }
        __syncthreads();
    }
#undef G_STAGE

#pragma unroll
    for (int mt = 0; mt < 2; mt++) {
#pragma unroll
        for (int nt = 0; nt < 8; nt++) {
            const int row = m0 + wm + mt * 16 + (lane >> 2);
            const int col = n0 + wn + nt * 8 + (lane & 3) * 2;
#pragma unroll
            for (int half = 0; half < 2; half++) {
                const int rr = row + half * 8;
                float v0 = acc[mt][nt][half * 2 + 0] + bias[col + 0];
                float v1 = acc[mt][nt][half * 2 + 1] + bias[col + 1];
                if (EPI == 1) {
                    const float2 r2 = *(const float2*)&res[(size_t)rr * N + col];
                    v0 += r2.x; v1 += r2.y;
                }
                if (EPI == 2) {
                    v0 = v0 / (1.f + __expf(-v0));
                    v1 = v1 / (1.f + __expf(-v1));
                }
                if (EPI == 3) {
                    const size_t o = (size_t)rr * N + col;
                    const bf16 h0 = __float2bfloat16(v0), h1 = __float2bfloat16(v1);
                    Chi[o + 0] = h0; Chi[o + 1] = h1;
                    Clo[o + 0] = __float2bfloat16(v0 - __bfloat162float(h0));
                    Clo[o + 1] = __float2bfloat16(v1 - __bfloat162float(h1));
                } else {
                    *(float2*)&Cf[(size_t)rr * N + col] = make_float2(v0, v1);
                }
            }
        }
    }
}

// ===================== scores2: Q-persistent, K double-buffered, fp16 S =====
__global__ __launch_bounds__(256)
void scores2(const bf16* __restrict__ Qhi, const bf16* __restrict__ Qlo,
             const bf16* __restrict__ Khi, const bf16* __restrict__ Klo,
             __half* __restrict__ S)
{
    extern __shared__ bf16 ssm[];
    const uint32_t base = smem_u32(ssm);
    const uint32_t aQh = base;
    const uint32_t aQl = base + QTILE * 2;
    const uint32_t aK0h = base + QTILE * 4;
    const uint32_t aK0l = base + QTILE * 6;
    const uint32_t aK1h = base + QTILE * 8;
    const uint32_t aK1l = base + QTILE * 10;

    const int tid  = threadIdx.x;
    const int wid  = tid >> 5, lane = tid & 31;
    const int nq0  = blockIdx.x * 128;
    const int h    = blockIdx.y;
    const int wm   = (wid & 3) * 32;
    const int wn   = (wid >> 2) * 64;

    const int r_st  = tid >> 1;
    const int c8_st = (tid & 1) * 4;

#pragma unroll
    for (int u = 0; u < 4; u++) {
        const int seg = c8_st + u;
        const uint32_t so = (uint32_t)(r_st * QROW + seg * 8) * 2;
        const size_t gq = (size_t)(nq0 + r_st) * DIM + h * 64 + seg * 8;
        const size_t gk = (size_t)r_st * DIM + h * 64 + seg * 8;
        cpa16(aQh + so, Qhi + gq);
        cpa16(aQl + so, Qlo + gq);
        cpa16(aK0h + so, Khi + gk);
        cpa16(aK0l + so, Klo + gk);
    }
    CP_COMMIT();

    const int la_rowA = (lane & 7) + ((lane >> 3) & 1) * 8;
    const int la_kA   = (lane >> 4) * 8;
    const int la_rowB = (lane & 7) + (lane >= 16 ? 8 : 0);
    const int la_kB   = ((lane >> 3) & 1) * 8;

    __half* Sp = S + (size_t)h * N_TOK * N_TOK;

    for (int mb = 0; mb < 32; mb++) {
        if (mb + 1 < 32) {
            const uint32_t kh = ((mb + 1) & 1) ? aK1h : aK0h;
            const uint32_t kl = ((mb + 1) & 1) ? aK1l : aK0l;
#pragma unroll
            for (int u = 0; u < 4; u++) {
                const int seg = c8_st + u;
                const uint32_t so = (uint32_t)(r_st * QROW + seg * 8) * 2;
                const size_t gk = (size_t)((mb + 1) * 128 + r_st) * DIM + h * 64 + seg * 8;
                cpa16(kh + so, Khi + gk);
                cpa16(kl + so, Klo + gk);
            }
            CP_COMMIT();
            CP_WAIT(1);
        } else {
            CP_WAIT(0);
        }
        __syncthreads();

        const uint32_t aKh = (mb & 1) ? aK1h : aK0h;
        const uint32_t aKl = (mb & 1) ? aK1l : aK0l;

        float acc[2][8][4];
#pragma unroll
        for (int i = 0; i < 2; i++)
#pragma unroll
            for (int j = 0; j < 8; j++)
#pragma unroll
                for (int r = 0; r < 4; r++) acc[i][j][r] = 0.f;

#pragma unroll
        for (int ks = 0; ks < 64; ks += 16) {
            uint32_t ah[2][4], al[2][4];
#pragma unroll
            for (int mt = 0; mt < 2; mt++) {
                const uint32_t off =
                    (uint32_t)((wm + mt * 16 + la_rowA) * QROW + ks + la_kA) * 2;
                ldmx4(ah[mt], aQh + off);
                ldmx4(al[mt], aQl + off);
            }
#pragma unroll
            for (int nt2 = 0; nt2 < 4; nt2++) {
                uint32_t bh[4], bl[4];
                const uint32_t off =
                    (uint32_t)((wn + nt2 * 16 + la_rowB) * QROW + ks + la_kB) * 2;
                ldmx4(bh, aKh + off);
                ldmx4(bl, aKl + off);
#pragma unroll
                for (int sub = 0; sub < 2; sub++) {
#pragma unroll
                    for (int mt = 0; mt < 2; mt++) {
                        float* cc = acc[mt][nt2 * 2 + sub];
                        mma16816(cc, ah[mt], &bh[sub * 2]);
                        mma16816(cc, ah[mt], &bl[sub * 2]);
                        mma16816(cc, al[mt], &bh[sub * 2]);
                    }
                }
            }
        }

        // store S tile as fp16
#pragma unroll
        for (int mt = 0; mt < 2; mt++) {
#pragma unroll
            for (int nt = 0; nt < 8; nt++) {
                const int row = nq0 + wm + mt * 16 + (lane >> 2);
                const int col = mb * 128 + wn + nt * 8 + (lane & 3) * 2;
#pragma unroll
                for (int half = 0; half < 2; half++) {
                    *(__half2*)&Sp[(size_t)(row + half * 8) * N_TOK + col] =
                        __floats2half2_rn(acc[mt][nt][half * 2 + 0],
                                          acc[mt][nt][half * 2 + 1]);
                }
            }
        }
        __syncthreads();
    }
}

// ===================== Phase C: softmax-over-heads + PV on HMMA =============
#define P_PLANE 768
#define V_PLANE 2560
#define PV_SMEM ((32 * P_PLANE + 32 * V_PLANE) * 2)   // 212992 B

__global__ __launch_bounds__(512, 1)
void pv_mma(const __half* __restrict__ S, const bf16* __restrict__ Vtb,
            float* __restrict__ O)
{
    extern __shared__ bf16 smb[];
    bf16* ps = smb;
    bf16* vs = smb + 32 * P_PLANE;

    const int tid  = threadIdx.x;
    const int wid  = tid >> 5;
    const int lane = tid & 31;
    const int n0   = blockIdx.x * 32;
    const int nn   = tid >> 4;
    const int mmq  = tid & 15;

    const uint32_t psb = smem_u32(ps);
    const uint32_t vsb = smem_u32(vs);

    float acc[2][8][4];
#pragma unroll
    for (int i = 0; i < 2; i++)
#pragma unroll
        for (int j = 0; j < 8; j++)
#pragma unroll
            for (int r = 0; r < 4; r++) acc[i][j][r] = 0.f;

    const int la_rowA = (lane & 7) + ((lane >> 3) & 1) * 8;
    const int la_kA   = (lane >> 4) * 8;
    const int la_rowB = (lane & 7) + (lane >= 16 ? 8 : 0);
    const int la_kB   = ((lane >> 3) & 1) * 8;

    const size_t N2 = (size_t)N_TOK * N_TOK;
    const __half* sp0 = S + (size_t)(n0 + nn) * N_TOK + mmq;

    for (int mt0 = 0; mt0 < N_TOK / 16; mt0++) {
        const int m0 = mt0 * 16;

        const uint4* vsrc = (const uint4*)(Vtb + (size_t)mt0 * 32768);
#pragma unroll
        for (int j = 0; j < 8; j++) {
            const int e    = j * 512 + tid;
            const int pl   = e >> 7;
            const int d    = (e >> 1) & 63;
            const int half = e & 1;
            *(uint4*)&vs[pl * V_PLANE + d * 40 + half * 8] = vsrc[e];
        }

        {
            const __half* sp = sp0 + m0;
            float sv[16];
#pragma unroll
            for (int q = 0; q < 16; q++)
                sv[q] = __half2float(sp[(size_t)q * N2]) * 0.125f;
            float mx = sv[0];
#pragma unroll
            for (int q = 1; q < 16; q++) mx = fmaxf(mx, sv[q]);
            float ssum = 0.f;
#pragma unroll
            for (int q = 0; q < 16; q++) { sv[q] = __expf(sv[q] - mx); ssum += sv[q]; }
            const float rinv = __fdividef(1.f, ssum);
#pragma unroll
            for (int q = 0; q < 16; q++) {
                const float p  = sv[q] * rinv;
                const bf16  ph = __float2bfloat16(p);
                ps[(q * 2 + 0) * P_PLANE + nn * 24 + mmq] = ph;
                ps[(q * 2 + 1) * P_PLANE + nn * 24 + mmq] =
                    __float2bfloat16(p - __bfloat162float(ph));
            }
        }
        __syncthreads();

        {
            const uint32_t pbh = psb + (uint32_t)(wid * 2 + 0) * P_PLANE * 2;
            const uint32_t pbl = psb + (uint32_t)(wid * 2 + 1) * P_PLANE * 2;
            const uint32_t vbh = vsb + (uint32_t)(wid * 2 + 0) * V_PLANE * 2;
            const uint32_t vbl = vsb + (uint32_t)(wid * 2 + 1) * V_PLANE * 2;

            uint32_t ah[2][4], al[2][4];
#pragma unroll
            for (int mt = 0; mt < 2; mt++) {
                const uint32_t off =
                    (uint32_t)((mt * 16 + la_rowA) * 24 + la_kA) * 2;
                ldmx4(ah[mt], pbh + off);
                ldmx4(al[mt], pbl + off);
            }
#pragma unroll
            for (int nt2 = 0; nt2 < 4; nt2++) {
                uint32_t bh[4], bl[4];
                const uint32_t off =
                    (uint32_t)((nt2 * 16 + la_rowB) * 40 + la_kB) * 2;
                ldmx4(bh, vbh + off);
                ldmx4(bl, vbl + off);
#pragma unroll
                for (int sub = 0; sub < 2; sub++) {
#pragma unroll
                    for (int mt = 0; mt < 2; mt++) {
                        float* c = acc[mt][nt2 * 2 + sub];
                        mma16816(c, ah[mt], &bh[sub * 2]);
                        mma16816(c, ah[mt], &bl[sub * 2]);
                        mma16816(c, al[mt], &bh[sub * 2]);
                    }
                }
            }
        }
        __syncthreads();
    }

#pragma unroll
    for (int mt = 0; mt < 2; mt++) {
#pragma unroll
        for (int nt = 0; nt < 8; nt++) {
            const int row = n0 + mt * 16 + (lane >> 2);
            const int col = wid * 64 + nt * 8 + (lane & 3) * 2;
#pragma unroll
            for (int half = 0; half < 2; half++) {
                *(float2*)&O[(size_t)(row + half * 8) * DIM + col] =
                    make_float2(acc[mt][nt][half * 2 + 0], acc[mt][nt][half * 2 + 1]);
            }
        }
    }
}

// ===================== LayerNorm ============================================
__global__ __launch_bounds__(256)
void ln_kernel(const float* __restrict__ X, const float* __restrict__ w,
               const float* __restrict__ b, float* __restrict__ out)
{
    const int n   = blockIdx.x;
    const int tid = threadIdx.x;
    const float4 x = ((const float4*)(X + (size_t)n * DIM))[tid];

    float s  = x.x + x.y + x.z + x.w;
    float ss = x.x * x.x + x.y * x.y + x.z * x.z + x.w * x.w;
#pragma unroll
    for (int off = 16; off; off >>= 1) {
        s  += __shfl_xor_sync(0xffffffffu, s, off);
        ss += __shfl_xor_sync(0xffffffffu, ss, off);
    }
    __shared__ float rs[8], rss[8], stat[2];
    if ((tid & 31) == 0) { rs[tid >> 5] = s; rss[tid >> 5] = ss; }
    __syncthreads();
    if (tid == 0) {
        float S = 0.f, SS = 0.f;
#pragma unroll
        for (int i = 0; i < 8; i++) { S += rs[i]; SS += rss[i]; }
        const float mean = S * (1.f / DIM);
        const float var  = SS * (1.f / DIM) - mean * mean;
        stat[0] = mean;
        stat[1] = rsqrtf(var + 1e-5f);
    }
    __syncthreads();
    const float mean = stat[0], inv = stat[1];
    const int col = tid * 4;
    const float4 wv = *(const float4*)&w[col];
    const float4 bv = *(const float4*)&b[col];
    float4 o;
    o.x = (x.x - mean) * inv * wv.x + bv.x;
    o.y = (x.y - mean) * inv * wv.y + bv.y;
    o.z = (x.z - mean) * inv * wv.z + bv.z;
    o.w = (x.w - mean) * inv * wv.w + bv.w;
    ((float4*)(out + (size_t)n * DIM))[tid] = o;
}

// ===================== coord MLP layer 2 ====================================
__global__ void mlp2_kernel(const float* __restrict__ T, const float* __restrict__ W2,
                            const float* __restrict__ b2, float* __restrict__ cw)
{
    const int warp = (blockIdx.x * blockDim.x + threadIdx.x) >> 5;
    const int lane = threadIdx.x & 31;
    if (warp >= N_TOK) return;
    const float* t = T + (size_t)warp * (DIM / 2);
    float s = 0.f;
#pragma unroll
    for (int j = 0; j < DIM / 2; j += 32) s = fmaf(t[j + lane], W2[j + lane], s);
#pragma unroll
    for (int off = 16; off; off >>= 1) s += __shfl_xor_sync(0xffffffffu, s, off);
    if (lane == 0) cw[warp] = s + b2[0];
}

// ===================== rel_pos mean =========================================
__global__ __launch_bounds__(128)
void relmean_kernel(const float* __restrict__ rel, float* __restrict__ out)
{
    const int n   = blockIdx.x;
    const int tid = threadIdx.x;
    const float* base = rel + (size_t)n * N_TOK * 3;
    float s0 = 0.f, s1 = 0.f, s2 = 0.f;
    for (int m = tid; m < N_TOK; m += 128) {
        s0 += base[m * 3 + 0];
        s1 += base[m * 3 + 1];
        s2 += base[m * 3 + 2];
    }
#pragma unroll
    for (int off = 16; off; off >>= 1) {
        s0 += __shfl_xor_sync(0xffffffffu, s0, off);
        s1 += __shfl_xor_sync(0xffffffffu, s1, off);
        s2 += __shfl_xor_sync(0xffffffffu, s2, off);
    }
    __shared__ float sm[3][4];
    if ((tid & 31) == 0) {
        sm[0][tid >> 5] = s0; sm[1][tid >> 5] = s1; sm[2][tid >> 5] = s2;
    }
    __syncthreads();
    if (tid == 0) {
        out[n * 3 + 0] = (sm[0][0] + sm[0][1] + sm[0][2] + sm[0][3]) * (1.f / N_TOK);
        out[n * 3 + 1] = (sm[1][0] + sm[1][1] + sm[1][2] + sm[1][3]) * (1.f / N_TOK);
        out[n * 3 + 2] = (sm[2][0] + sm[2][1] + sm[2][2] + sm[2][3]) * (1.f / N_TOK);
    }
}

// ===================== pos_update ===========================================
__global__ void posupd_kernel(const float* __restrict__ cw, const float* __restrict__ rm,
                              float* __restrict__ out)
{
    const int i = blockIdx.x * blockDim.x + threadIdx.x;
    if (i < N_TOK * 3) out[i] = cw[i / 3] * rm[i];
}

// ===================== launcher =============================================
extern "C" void kernel_launch(void* const* d_in, const int* in_sizes, int n_in,
                              void* d_out, int out_size)
{
    const float* h    = (const float*)d_in[0];
    const float* rel  = (const float*)d_in[1];
    const float* Wq   = (const float*)d_in[2];
    const float* bq   = (const float*)d_in[3];
    const float* Wk   = (const float*)d_in[4];
    const float* bk   = (const float*)d_in[5];
    const float* Wv   = (const float*)d_in[6];
    const float* bv   = (const float*)d_in[7];
    const float* Wo   = (const float*)d_in[8];
    const float* bo   = (const float*)d_in[9];
    const float* W1   = (const float*)d_in[10];
    const float* b1   = (const float*)d_in[11];
    const float* W2   = (const float*)d_in[12];
    const float* b2   = (const float*)d_in[13];
    const float* lnw  = (const float*)d_in[14];
    const float* lnb  = (const float*)d_in[15];
    float* out = (float*)d_out;

    float *attn, *x, *t, *cw, *rm;
    __half* s;
    bf16 *ah, *al, *qh, *ql, *kh, *kl, *vh, *vl, *vtb;
    bf16 *wqh, *wql, *wkh, *wkl, *wvh, *wvl, *woh, *wol, *w1h, *w1l;
    cudaGetSymbolAddress((void**)&attn, g_attn);
    cudaGetSymbolAddress((void**)&x,    g_x);
    cudaGetSymbolAddress((void**)&t,    g_t);
    cudaGetSymbolAddress((void**)&cw,   g_cw);
    cudaGetSymbolAddress((void**)&rm,   g_relmean);
    cudaGetSymbolAddress((void**)&s,    g_s);
    cudaGetSymbolAddress((void**)&ah,   g_ah);
    cudaGetSymbolAddress((void**)&al,   g_al);
    cudaGetSymbolAddress((void**)&qh,   g_qh);
    cudaGetSymbolAddress((void**)&ql,   g_ql);
    cudaGetSymbolAddress((void**)&kh,   g_kh);
    cudaGetSymbolAddress((void**)&kl,   g_kl);
    cudaGetSymbolAddress((void**)&vh,   g_vh);
    cudaGetSymbolAddress((void**)&vl,   g_vl);
    cudaGetSymbolAddress((void**)&vtb,  g_vtb);
    cudaGetSymbolAddress((void**)&wqh,  g_wqh);
    cudaGetSymbolAddress((void**)&wql,  g_wql);
    cudaGetSymbolAddress((void**)&wkh,  g_wkh);
    cudaGetSymbolAddress((void**)&wkl,  g_wkl);
    cudaGetSymbolAddress((void**)&wvh,  g_wvh);
    cudaGetSymbolAddress((void**)&wvl,  g_wvl);
    cudaGetSymbolAddress((void**)&woh,  g_woh);
    cudaGetSymbolAddress((void**)&wol,  g_wol);
    cudaGetSymbolAddress((void**)&w1h,  g_w1h);
    cudaGetSymbolAddress((void**)&w1l,  g_w1l);

    cudaFuncSetAttribute(pv_mma,      cudaFuncAttributeMaxDynamicSharedMemorySize, PV_SMEM);
    cudaFuncSetAttribute(scores2,     cudaFuncAttributeMaxDynamicSharedMemorySize, SC_SMEM);
    cudaFuncSetAttribute(gemm_mma<0>, cudaFuncAttributeMaxDynamicSharedMemorySize, GEMM_SMEM);
    cudaFuncSetAttribute(gemm_mma<1>, cudaFuncAttributeMaxDynamicSharedMemorySize, GEMM_SMEM);
    cudaFuncSetAttribute(gemm_mma<2>, cudaFuncAttributeMaxDynamicSharedMemorySize, GEMM_SMEM);
    cudaFuncSetAttribute(gemm_mma<3>, cudaFuncAttributeMaxDynamicSharedMemorySize, GEMM_SMEM);

    // independent: rel_pos mean
    relmean_kernel<<<N_TOK, 128>>>(rel, rm);

    // weight prep: transpose + bf16 split
    trsplit<<<dim3(32, 32), dim3(32, 32)>>>(Wq, wqh, wql, DIM, DIM);
    trsplit<<<dim3(32, 32), dim3(32, 32)>>>(Wk, wkh, wkl, DIM, DIM);
    trsplit<<<dim3(32, 32), dim3(32, 32)>>>(Wv, wvh, wvl, DIM, DIM);
    trsplit<<<dim3(32, 32), dim3(32, 32)>>>(Wo, woh, wol, DIM, DIM);
    trsplit<<<dim3(16, 32), dim3(32, 32)>>>(W1, w1h, w1l, DIM, DIM / 2);

    // h split -> A operand
    split_f32<<<(N_TOK * DIM / 4 + 255) / 256, 256>>>(h, ah, al, N_TOK * DIM / 4);

    // QKV (all written as bf16 hi/lo)
    gemm_mma<3><<<dim3(8, 32), 256, GEMM_SMEM>>>(ah, al, wqh, wql, bq, nullptr, nullptr, qh, ql, N_TOK, DIM, DIM);
    gemm_mma<3><<<dim3(8, 32), 256, GEMM_SMEM>>>(ah, al, wkh, wkl, bk, nullptr, nullptr, kh, kl, N_TOK, DIM, DIM);
    gemm_mma<3><<<dim3(8, 32), 256, GEMM_SMEM>>>(ah, al, wvh, wvl, bv, nullptr, nullptr, vh, vl, N_TOK, DIM, DIM);

    // block V for pv_mma staging
    vblock<<<N_TOK / 16, 512>>>(vh, vl, vtb);

    // attention phase A: raw scores -> fp16
    scores2<<<dim3(32, 16), 256, SC_SMEM>>>(qh, ql, kh, kl, s);

    // attention phase C: softmax over heads + PV on tensor cores
    pv_mma<<<N_TOK / 32, 512, PV_SMEM>>>(s, vtb, attn);

    // O projection + residual
    split_f32<<<(N_TOK * DIM / 4 + 255) / 256, 256>>>(attn, ah, al, N_TOK * DIM / 4);
    gemm_mma<1><<<dim3(8, 32), 256, GEMM_SMEM>>>(ah, al, woh, wol, bo, h, x, nullptr, nullptr, N_TOK, DIM, DIM);

    // layernorm -> hn
    ln_kernel<<<N_TOK, 256>>>(x, lnw, lnb, out);

    // coord MLP
    split_f32<<<(N_TOK * DIM / 4 + 255) / 256, 256>>>(out, ah, al, N_TOK * DIM / 4);
    gemm_mma<2><<<dim3(4, 32), 256, GEMM_SMEM>>>(ah, al, w1h, w1l, b1, nullptr, t, nullptr, nullptr, N_TOK, DIM / 2, DIM);
    mlp2_kernel<<<(N_TOK * 32) / 256, 256>>>(t, W2, b2, cw);

    // pos_update
    posupd_kernel<<<(N_TOK * 3 + 255) / 256, 256>>>(cw, rm, out + (size_t)N_TOK * DIM);
}

// round 12
// speedup vs baseline: 4.4713x; 1.1983x over previous
#include <cuda_runtime.h>
#include <cuda_bf16.h>
#include <cuda_fp16.h>
#include <cstdint>
#include <math.h>

#define N_TOK 4096
#define DIM   1024
#define NH    16
#define HD    64

typedef unsigned long long ull;
typedef __nv_bfloat16 bf16;

// ===================== HMMA primitives (baseline PTX, no 'a' features) ======
__device__ __forceinline__ uint32_t smem_u32(const void* p) {
    uint32_t a;
    asm("{ .reg .u64 t; cvta.to.shared.u64 t, %1; cvt.u32.u64 %0, t; }"
        : "=r"(a) : "l"(p));
    return a;
}
__device__ __forceinline__ void ldmx4(uint32_t* r, uint32_t addr) {
    asm volatile("ldmatrix.sync.aligned.m8n8.x4.shared.b16 {%0,%1,%2,%3}, [%4];"
                 : "=r"(r[0]), "=r"(r[1]), "=r"(r[2]), "=r"(r[3]) : "r"(addr));
}
__device__ __forceinline__ void mma16816(float* c, const uint32_t* a, const uint32_t* b) {
    asm volatile(
        "mma.sync.aligned.m16n8k16.row.col.f32.bf16.bf16.f32 "
        "{%0,%1,%2,%3}, {%4,%5,%6,%7}, {%8,%9}, {%0,%1,%2,%3};"
        : "+f"(c[0]), "+f"(c[1]), "+f"(c[2]), "+f"(c[3])
        : "r"(a[0]), "r"(a[1]), "r"(a[2]), "r"(a[3]), "r"(b[0]), "r"(b[1]));
}
__device__ __forceinline__ void mma16816h(float* c, const uint32_t* a, const uint32_t* b) {
    asm volatile(
        "mma.sync.aligned.m16n8k16.row.col.f32.f16.f16.f32 "
        "{%0,%1,%2,%3}, {%4,%5,%6,%7}, {%8,%9}, {%0,%1,%2,%3};"
        : "+f"(c[0]), "+f"(c[1]), "+f"(c[2]), "+f"(c[3])
        : "r"(a[0]), "r"(a[1]), "r"(a[2]), "r"(a[3]), "r"(b[0]), "r"(b[1]));
}
__device__ __forceinline__ void cpa16(uint32_t dst, const void* src) {
    asm volatile("cp.async.cg.shared.global [%0], [%1], 16;"
                 :: "r"(dst), "l"(src) : "memory");
}
#define CP_COMMIT() asm volatile("cp.async.commit_group;" ::: "memory")
#define CP_WAIT(n)  asm volatile("cp.async.wait_group %0;" :: "n"(n) : "memory")

// dense GEMM smem tile: 128 rows x 32 bf16, row stride 40 (80 B)
#define TROW 40
#define TILE_ELEMS (128 * TROW)
#define GEMM_SMEM (2 * 4 * TILE_ELEMS * 2)      // 81920 B

// scores smem: Q persistent + double-buffered K; 128 rows x 64 bf16, stride 72
#define QROW 72
#define QTILE (128 * QROW)
#define SC_SMEM (6 * QTILE * 2)                  // 110592 B

// ===================== scratch globals ======================================
__device__ float g_attn[N_TOK * DIM];
__device__ float g_x[N_TOK * DIM];
__device__ float g_t[N_TOK * (DIM / 2)];
__device__ float g_cw[N_TOK];
__device__ float g_relmean[N_TOK * 3];
__device__ __half g_s[(size_t)NH * N_TOK * N_TOK];  // raw scores [h][n][m], fp16

__device__ bf16 g_ah[N_TOK * DIM], g_al[N_TOK * DIM];
__device__ bf16 g_qh[N_TOK * DIM], g_ql[N_TOK * DIM];
__device__ bf16 g_kh[N_TOK * DIM], g_kl[N_TOK * DIM];
__device__ __half g_vq[N_TOK * DIM];                // V as single fp16
__device__ __half g_vtb[(size_t)256 * 16 * 64 * 16]; // blocked V [mb][h][d][16m] fp16
__device__ bf16 g_wqh[DIM * DIM], g_wql[DIM * DIM];
__device__ bf16 g_wkh[DIM * DIM], g_wkl[DIM * DIM];
__device__ bf16 g_wvh[DIM * DIM], g_wvl[DIM * DIM];
__device__ bf16 g_woh[DIM * DIM], g_wol[DIM * DIM];
__device__ bf16 g_w1h[(DIM / 2) * DIM], g_w1l[(DIM / 2) * DIM];

// ===================== prep kernels =========================================
__global__ __launch_bounds__(256)
void split_f32(const float* __restrict__ X, bf16* __restrict__ hi,
               bf16* __restrict__ lo, int n4)
{
    const int i = blockIdx.x * blockDim.x + threadIdx.x;
    if (i >= n4) return;
    const float4 v = ((const float4*)X)[i];
    const bf16 h0 = __float2bfloat16(v.x), h1 = __float2bfloat16(v.y);
    const bf16 h2 = __float2bfloat16(v.z), h3 = __float2bfloat16(v.w);
    hi[4 * i + 0] = h0; hi[4 * i + 1] = h1; hi[4 * i + 2] = h2; hi[4 * i + 3] = h3;
    lo[4 * i + 0] = __float2bfloat16(v.x - __bfloat162float(h0));
    lo[4 * i + 1] = __float2bfloat16(v.y - __bfloat162float(h1));
    lo[4 * i + 2] = __float2bfloat16(v.z - __bfloat162float(h2));
    lo[4 * i + 3] = __float2bfloat16(v.w - __bfloat162float(h3));
}

__global__ void trsplit(const float* __restrict__ W, bf16* __restrict__ Thi,
                        bf16* __restrict__ Tlo, int K, int N)
{
    __shared__ float t[32][33];
    const int n = blockIdx.x * 32 + threadIdx.x;
    const int k = blockIdx.y * 32 + threadIdx.y;
    t[threadIdx.y][threadIdx.x] = W[(size_t)k * N + n];
    __syncthreads();
    const int nn = blockIdx.x * 32 + threadIdx.y;
    const int kk = blockIdx.y * 32 + threadIdx.x;
    const float v = t[threadIdx.x][threadIdx.y];
    const bf16 h = __float2bfloat16(v);
    Thi[(size_t)nn * K + kk] = h;
    Tlo[(size_t)nn * K + kk] = __float2bfloat16(v - __bfloat162float(h));
}

// block V fp16 [m][1024] -> [mb][h][d][16m]
__global__ __launch_bounds__(512)
void vblock(const __half* __restrict__ vq, __half* __restrict__ out)
{
    __shared__ __half sh[16 * 1024];
    const int mb  = blockIdx.x;
    const int tid = threadIdx.x;

#pragma unroll
    for (int j = 0; j < 4; j++) {
        const int e  = j * 512 + tid;           // uint4 idx, 2048 total
        const int mm = e >> 7;
        const int c8 = e & 127;
        ((uint4*)sh)[e] = *(const uint4*)&vq[(size_t)(mb * 16 + mm) * DIM + c8 * 8];
    }
    __syncthreads();

#pragma unroll
    for (int j = 0; j < 4; j++) {
        const int e    = j * 512 + tid;         // out uint4 idx, 2048 total
        const int pl   = e >> 7;                // head
        const int d    = (e >> 1) & 63;
        const int half = e & 1;
        __half tmp[8];
#pragma unroll
        for (int k2 = 0; k2 < 8; k2++)
            tmp[k2] = sh[(half * 8 + k2) * 1024 + pl * 64 + d];
        *(uint4*)&out[(size_t)mb * 16384 + (size_t)e * 8] = *(uint4*)tmp;
    }
}

// ===================== bf16x2 HMMA GEMM (cp.async double-buffered) ==========
// EPI: 0 f32+bias, 1 f32+bias+res, 2 f32+bias+SiLU, 3 bf16 hi/lo, 4 fp16 single
template <int EPI>
__global__ __launch_bounds__(256)
void gemm_mma(const bf16* __restrict__ Ahi, const bf16* __restrict__ Alo,
              const bf16* __restrict__ Bhi, const bf16* __restrict__ Blo,
              const float* __restrict__ bias, const float* __restrict__ res,
              float* __restrict__ Cf, bf16* __restrict__ Chi, bf16* __restrict__ Clo,
              __half* __restrict__ Cq, int M, int N, int K)
{
    extern __shared__ bf16 gsm[];
    const uint32_t base = smem_u32(gsm);

    const int tid  = threadIdx.x;
    const int wid  = tid >> 5, lane = tid & 31;
    const int m0   = blockIdx.y * 128, n0 = blockIdx.x * 128;
    const int wm   = (wid & 3) * 32;
    const int wn   = (wid >> 2) * 64;

    float acc[2][8][4];
#pragma unroll
    for (int i = 0; i < 2; i++)
#pragma unroll
        for (int j = 0; j < 8; j++)
#pragma unroll
            for (int r = 0; r < 4; r++) acc[i][j][r] = 0.f;

    const int la_rowA = (lane & 7) + ((lane >> 3) & 1) * 8;
    const int la_kA   = (lane >> 4) * 8;
    const int la_rowB = (lane & 7) + (lane >= 16 ? 8 : 0);
    const int la_kB   = ((lane >> 3) & 1) * 8;

    const int chunks = K >> 5;
    const int r_st  = tid >> 2;
    const int cs_st = (tid & 3) * 8;
#define G_STAGE(c, b) do { \
        const uint32_t bb = base + (uint32_t)(b) * 4 * TILE_ELEMS * 2; \
        _Pragma("unroll") \
        for (int t = 0; t < 2; t++) { \
            const int r = r_st + t * 64; \
            const uint32_t so = (uint32_t)(r * TROW + cs_st) * 2; \
            const size_t ga = (size_t)(m0 + r) * K + (c) * 32 + cs_st; \
            const size_t gb = (size_t)(n0 + r) * K + (c) * 32 + cs_st; \
            cpa16(bb + so,                      Ahi + ga); \
            cpa16(bb + TILE_ELEMS * 2 + so,     Alo + ga); \
            cpa16(bb + TILE_ELEMS * 4 + so,     Bhi + gb); \
            cpa16(bb + TILE_ELEMS * 6 + so,     Blo + gb); \
        } \
        CP_COMMIT(); \
    } while (0)

    G_STAGE(0, 0);

    for (int c = 0; c < chunks; c++) {
        if (c + 1 < chunks) { G_STAGE(c + 1, (c + 1) & 1); CP_WAIT(1); }
        else                { CP_WAIT(0); }
        __syncthreads();

        const uint32_t bb  = base + (uint32_t)(c & 1) * 4 * TILE_ELEMS * 2;
        const uint32_t aAh = bb;
        const uint32_t aAl = bb + TILE_ELEMS * 2;
        const uint32_t aBh = bb + TILE_ELEMS * 4;
        const uint32_t aBl = bb + TILE_ELEMS * 6;

#pragma unroll
        for (int ks = 0; ks < 32; ks += 16) {
            uint32_t ah[2][4], al[2][4];
#pragma unroll
            for (int mt = 0; mt < 2; mt++) {
                const uint32_t off =
                    (uint32_t)((wm + mt * 16 + la_rowA) * TROW + ks + la_kA) * 2;
                ldmx4(ah[mt], aAh + off);
                ldmx4(al[mt], aAl + off);
            }
#pragma unroll
            for (int nt2 = 0; nt2 < 4; nt2++) {
                uint32_t bh[4], bl[4];
                const uint32_t off =
                    (uint32_t)((wn + nt2 * 16 + la_rowB) * TROW + ks + la_kB) * 2;
                ldmx4(bh, aBh + off);
                ldmx4(bl, aBl + off);
#pragma unroll
                for (int sub = 0; sub < 2; sub++) {
#pragma unroll
                    for (int mt = 0; mt < 2; mt++) {
                        float* cc = acc[mt][nt2 * 2 + sub];
                        mma16816(cc, ah[mt], &bh[sub * 2]);
                        mma16816(cc, ah[mt], &bl[sub * 2]);
                        mma16816(cc, al[mt], &bh[sub * 2]);
                    }
                }
            }
        }
        __syncthreads();
    }
#undef G_STAGE

#pragma unroll
    for (int mt = 0; mt < 2; mt++) {
#pragma unroll
        for (int nt = 0; nt < 8; nt++) {
            const int row = m0 + wm + mt * 16 + (lane >> 2);
            const int col = n0 + wn + nt * 8 + (lane & 3) * 2;
#pragma unroll
            for (int half = 0; half < 2; half++) {
                const int rr = row + half * 8;
                float v0 = acc[mt][nt][half * 2 + 0] + bias[col + 0];
                float v1 = acc[mt][nt][half * 2 + 1] + bias[col + 1];
                if (EPI == 1) {
                    const float2 r2 = *(const float2*)&res[(size_t)rr * N + col];
                    v0 += r2.x; v1 += r2.y;
                }
                if (EPI == 2) {
                    v0 = v0 / (1.f + __expf(-v0));
                    v1 = v1 / (1.f + __expf(-v1));
                }
                if (EPI == 3) {
                    const size_t o = (size_t)rr * N + col;
                    const bf16 h0 = __float2bfloat16(v0), h1 = __float2bfloat16(v1);
                    Chi[o + 0] = h0; Chi[o + 1] = h1;
                    Clo[o + 0] = __float2bfloat16(v0 - __bfloat162float(h0));
                    Clo[o + 1] = __float2bfloat16(v1 - __bfloat162float(h1));
                } else if (EPI == 4) {
                    *(__half2*)&Cq[(size_t)rr * N + col] = __floats2half2_rn(v0, v1);
                } else {
                    *(float2*)&Cf[(size_t)rr * N + col] = make_float2(v0, v1);
                }
            }
        }
    }
}

// ===================== scores2: Q-persistent, K double-buffered, fp16 S =====
__global__ __launch_bounds__(256)
void scores2(const bf16* __restrict__ Qhi, const bf16* __restrict__ Qlo,
             const bf16* __restrict__ Khi, const bf16* __restrict__ Klo,
             __half* __restrict__ S)
{
    extern __shared__ bf16 ssm[];
    const uint32_t base = smem_u32(ssm);
    const uint32_t aQh = base;
    const uint32_t aQl = base + QTILE * 2;
    const uint32_t aK0h = base + QTILE * 4;
    const uint32_t aK0l = base + QTILE * 6;
    const uint32_t aK1h = base + QTILE * 8;
    const uint32_t aK1l = base + QTILE * 10;

    const int tid  = threadIdx.x;
    const int wid  = tid >> 5, lane = tid & 31;
    const int nq0  = blockIdx.x * 128;
    const int h    = blockIdx.y;
    const int wm   = (wid & 3) * 32;
    const int wn   = (wid >> 2) * 64;

    const int r_st  = tid >> 1;
    const int c8_st = (tid & 1) * 4;

#pragma unroll
    for (int u = 0; u < 4; u++) {
        const int seg = c8_st + u;
        const uint32_t so = (uint32_t)(r_st * QROW + seg * 8) * 2;
        const size_t gq = (size_t)(nq0 + r_st) * DIM + h * 64 + seg * 8;
        const size_t gk = (size_t)r_st * DIM + h * 64 + seg * 8;
        cpa16(aQh + so, Qhi + gq);
        cpa16(aQl + so, Qlo + gq);
        cpa16(aK0h + so, Khi + gk);
        cpa16(aK0l + so, Klo + gk);
    }
    CP_COMMIT();

    const int la_rowA = (lane & 7) + ((lane >> 3) & 1) * 8;
    const int la_kA   = (lane >> 4) * 8;
    const int la_rowB = (lane & 7) + (lane >= 16 ? 8 : 0);
    const int la_kB   = ((lane >> 3) & 1) * 8;

    __half* Sp = S + (size_t)h * N_TOK * N_TOK;

    for (int mb = 0; mb < 32; mb++) {
        if (mb + 1 < 32) {
            const uint32_t kh = ((mb + 1) & 1) ? aK1h : aK0h;
            const uint32_t kl = ((mb + 1) & 1) ? aK1l : aK0l;
#pragma unroll
            for (int u = 0; u < 4; u++) {
                const int seg = c8_st + u;
                const uint32_t so = (uint32_t)(r_st * QROW + seg * 8) * 2;
                const size_t gk = (size_t)((mb + 1) * 128 + r_st) * DIM + h * 64 + seg * 8;
                cpa16(kh + so, Khi + gk);
                cpa16(kl + so, Klo + gk);
            }
            CP_COMMIT();
            CP_WAIT(1);
        } else {
            CP_WAIT(0);
        }
        __syncthreads();

        const uint32_t aKh = (mb & 1) ? aK1h : aK0h;
        const uint32_t aKl = (mb & 1) ? aK1l : aK0l;

        float acc[2][8][4];
#pragma unroll
        for (int i = 0; i < 2; i++)
#pragma unroll
            for (int j = 0; j < 8; j++)
#pragma unroll
                for (int r = 0; r < 4; r++) acc[i][j][r] = 0.f;

#pragma unroll
        for (int ks = 0; ks < 64; ks += 16) {
            uint32_t ah[2][4], al[2][4];
#pragma unroll
            for (int mt = 0; mt < 2; mt++) {
                const uint32_t off =
                    (uint32_t)((wm + mt * 16 + la_rowA) * QROW + ks + la_kA) * 2;
                ldmx4(ah[mt], aQh + off);
                ldmx4(al[mt], aQl + off);
            }
#pragma unroll
            for (int nt2 = 0; nt2 < 4; nt2++) {
                uint32_t bh[4], bl[4];
                const uint32_t off =
                    (uint32_t)((wn + nt2 * 16 + la_rowB) * QROW + ks + la_kB) * 2;
                ldmx4(bh, aKh + off);
                ldmx4(bl, aKl + off);
#pragma unroll
                for (int sub = 0; sub < 2; sub++) {
#pragma unroll
                    for (int mt = 0; mt < 2; mt++) {
                        float* cc = acc[mt][nt2 * 2 + sub];
                        mma16816(cc, ah[mt], &bh[sub * 2]);
                        mma16816(cc, ah[mt], &bl[sub * 2]);
                        mma16816(cc, al[mt], &bh[sub * 2]);
                    }
                }
            }
        }

#pragma unroll
        for (int mt = 0; mt < 2; mt++) {
#pragma unroll
            for (int nt = 0; nt < 8; nt++) {
                const int row = nq0 + wm + mt * 16 + (lane >> 2);
                const int col = mb * 128 + wn + nt * 8 + (lane & 3) * 2;
#pragma unroll
                for (int half = 0; half < 2; half++) {
                    *(__half2*)&Sp[(size_t)(row + half * 8) * N_TOK + col] =
                        __floats2half2_rn(acc[mt][nt][half * 2 + 0],
                                          acc[mt][nt][half * 2 + 1]);
                }
            }
        }
        __syncthreads();
    }
}

// ===================== Phase C: softmax-over-heads + PV (fp16 HMMA) =========
// P: fp16 hi/lo planes [16h][2hl][32n][24m]; V: fp16 planes [16h][64d][40m].
#define P_PLANE 768                 // 32 * 24
#define V_PLANE 2560                // 64 * 40
#define PV_SMEM ((32 * P_PLANE + 16 * V_PLANE) * 2)   // 131072 B

__global__ __launch_bounds__(512, 1)
void pv_mma(const __half* __restrict__ S, const __half* __restrict__ Vtb,
            float* __restrict__ O)
{
    extern __shared__ __half smh[];
    __half* ps = smh;                     // 32 planes x 768
    __half* vs = smh + 32 * P_PLANE;      // 16 planes x 2560

    const int tid  = threadIdx.x;
    const int wid  = tid >> 5;            // = head
    const int lane = tid & 31;
    const int n0   = blockIdx.x * 32;
    const int nn   = tid >> 4;
    const int mmq  = tid & 15;

    const uint32_t psb = smem_u32(ps);
    const uint32_t vsb = smem_u32(vs);

    float acc[2][8][4];
#pragma unroll
    for (int i = 0; i < 2; i++)
#pragma unroll
        for (int j = 0; j < 8; j++)
#pragma unroll
            for (int r = 0; r < 4; r++) acc[i][j][r] = 0.f;

    const int la_rowA = (lane & 7) + ((lane >> 3) & 1) * 8;
    const int la_kA   = (lane >> 4) * 8;
    const int la_rowB = (lane & 7) + (lane >= 16 ? 8 : 0);
    const int la_kB   = ((lane >> 3) & 1) * 8;

    const size_t N2 = (size_t)N_TOK * N_TOK;
    const __half* sp0 = S + (size_t)(n0 + nn) * N_TOK + mmq;

    for (int mt0 = 0; mt0 < N_TOK / 16; mt0++) {
        const int m0 = mt0 * 16;

        // ---- stage V tile: 2048 uint4, 4 per thread ----
        const uint4* vsrc = (const uint4*)(Vtb + (size_t)mt0 * 16384);
#pragma unroll
        for (int j = 0; j < 4; j++) {
            const int e    = j * 512 + tid;
            const int pl   = e >> 7;              // head
            const int d    = (e >> 1) & 63;
            const int half = e & 1;
            *(uint4*)&vs[pl * V_PLANE + d * 40 + half * 8] = vsrc[e];
        }

        // ---- softmax over heads, fp16 P hi/lo ----
        {
            const __half* sp = sp0 + m0;
            float sv[16];
#pragma unroll
            for (int q = 0; q < 16; q++)
                sv[q] = __half2float(sp[(size_t)q * N2]) * 0.125f;
            float mx = sv[0];
#pragma unroll
            for (int q = 1; q < 16; q++) mx = fmaxf(mx, sv[q]);
            float ssum = 0.f;
#pragma unroll
            for (int q = 0; q < 16; q++) { sv[q] = __expf(sv[q] - mx); ssum += sv[q]; }
            const float rinv = __fdividef(1.f, ssum);
#pragma unroll
            for (int q = 0; q < 16; q++) {
                const float p   = sv[q] * rinv;
                const __half ph = __float2half_rn(p);
                ps[(q * 2 + 0) * P_PLANE + nn * 24 + mmq] = ph;
                ps[(q * 2 + 1) * P_PLANE + nn * 24 + mmq] =
                    __float2half_rn(p - __half2float(ph));
            }
        }
        __syncthreads();

        // ---- fp16 HMMA: 2 passes (Ph*V + Pl*V) ----
        {
            const uint32_t pbh = psb + (uint32_t)(wid * 2 + 0) * P_PLANE * 2;
            const uint32_t pbl = psb + (uint32_t)(wid * 2 + 1) * P_PLANE * 2;
            const uint32_t vb  = vsb + (uint32_t)wid * V_PLANE * 2;

            uint32_t ah[2][4], al[2][4];
#pragma unroll
            for (int mt = 0; mt < 2; mt++) {
                const uint32_t off =
                    (uint32_t)((mt * 16 + la_rowA) * 24 + la_kA) * 2;
                ldmx4(ah[mt], pbh + off);
                ldmx4(al[mt], pbl + off);
            }
#pragma unroll
            for (int nt2 = 0; nt2 < 4; nt2++) {
                uint32_t bv[4];
                const uint32_t off =
                    (uint32_t)((nt2 * 16 + la_rowB) * 40 + la_kB) * 2;
                ldmx4(bv, vb + off);
#pragma unroll
                for (int sub = 0; sub < 2; sub++) {
#pragma unroll
                    for (int mt = 0; mt < 2; mt++) {
                        float* c = acc[mt][nt2 * 2 + sub];
                        mma16816h(c, ah[mt], &bv[sub * 2]);
                        mma16816h(c, al[mt], &bv[sub * 2]);
                    }
                }
            }
        }
        __syncthreads();
    }

#pragma unroll
    for (int mt = 0; mt < 2; mt++) {
#pragma unroll
        for (int nt = 0; nt < 8; nt++) {
            const int row = n0 + mt * 16 + (lane >> 2);
            const int col = wid * 64 + nt * 8 + (lane & 3) * 2;
#pragma unroll
            for (int half = 0; half < 2; half++) {
                *(float2*)&O[(size_t)(row + half * 8) * DIM + col] =
                    make_float2(acc[mt][nt][half * 2 + 0], acc[mt][nt][half * 2 + 1]);
            }
        }
    }
}

// ===================== LayerNorm ============================================
__global__ __launch_bounds__(256)
void ln_kernel(const float* __restrict__ X, const float* __restrict__ w,
               const float* __restrict__ b, float* __restrict__ out)
{
    const int n   = blockIdx.x;
    const int tid = threadIdx.x;
    const float4 x = ((const float4*)(X + (size_t)n * DIM))[tid];

    float s  = x.x + x.y + x.z + x.w;
    float ss = x.x * x.x + x.y * x.y + x.z * x.z + x.w * x.w;
#pragma unroll
    for (int off = 16; off; off >>= 1) {
        s  += __shfl_xor_sync(0xffffffffu, s, off);
        ss += __shfl_xor_sync(0xffffffffu, ss, off);
    }
    __shared__ float rs[8], rss[8], stat[2];
    if ((tid & 31) == 0) { rs[tid >> 5] = s; rss[tid >> 5] = ss; }
    __syncthreads();
    if (tid == 0) {
        float S = 0.f, SS = 0.f;
#pragma unroll
        for (int i = 0; i < 8; i++) { S += rs[i]; SS += rss[i]; }
        const float mean = S * (1.f / DIM);
        const float var  = SS * (1.f / DIM) - mean * mean;
        stat[0] = mean;
        stat[1] = rsqrtf(var + 1e-5f);
    }
    __syncthreads();
    const float mean = stat[0], inv = stat[1];
    const int col = tid * 4;
    const float4 wv = *(const float4*)&w[col];
    const float4 bv = *(const float4*)&b[col];
    float4 o;
    o.x = (x.x - mean) * inv * wv.x + bv.x;
    o.y = (x.y - mean) * inv * wv.y + bv.y;
    o.z = (x.z - mean) * inv * wv.z + bv.z;
    o.w = (x.w - mean) * inv * wv.w + bv.w;
    ((float4*)(out + (size_t)n * DIM))[tid] = o;
}

// ===================== coord MLP layer 2 ====================================
__global__ void mlp2_kernel(const float* __restrict__ T, const float* __restrict__ W2,
                            const float* __restrict__ b2, float* __restrict__ cw)
{
    const int warp = (blockIdx.x * blockDim.x + threadIdx.x) >> 5;
    const int lane = threadIdx.x & 31;
    if (warp >= N_TOK) return;
    const float* t = T + (size_t)warp * (DIM / 2);
    float s = 0.f;
#pragma unroll
    for (int j = 0; j < DIM / 2; j += 32) s = fmaf(t[j + lane], W2[j + lane], s);
#pragma unroll
    for (int off = 16; off; off >>= 1) s += __shfl_xor_sync(0xffffffffu, s, off);
    if (lane == 0) cw[warp] = s + b2[0];
}

// ===================== rel_pos mean =========================================
__global__ __launch_bounds__(128)
void relmean_kernel(const float* __restrict__ rel, float* __restrict__ out)
{
    const int n   = blockIdx.x;
    const int tid = threadIdx.x;
    const float* base = rel + (size_t)n * N_TOK * 3;
    float s0 = 0.f, s1 = 0.f, s2 = 0.f;
    for (int m = tid; m < N_TOK; m += 128) {
        s0 += base[m * 3 + 0];
        s1 += base[m * 3 + 1];
        s2 += base[m * 3 + 2];
    }
#pragma unroll
    for (int off = 16; off; off >>= 1) {
        s0 += __shfl_xor_sync(0xffffffffu, s0, off);
        s1 += __shfl_xor_sync(0xffffffffu, s1, off);
        s2 += __shfl_xor_sync(0xffffffffu, s2, off);
    }
    __shared__ float sm[3][4];
    if ((tid & 31) == 0) {
        sm[0][tid >> 5] = s0; sm[1][tid >> 5] = s1; sm[2][tid >> 5] = s2;
    }
    __syncthreads();
    if (tid == 0) {
        out[n * 3 + 0] = (sm[0][0] + sm[0][1] + sm[0][2] + sm[0][3]) * (1.f / N_TOK);
        out[n * 3 + 1] = (sm[1][0] + sm[1][1] + sm[1][2] + sm[1][3]) * (1.f / N_TOK);
        out[n * 3 + 2] = (sm[2][0] + sm[2][1] + sm[2][2] + sm[2][3]) * (1.f / N_TOK);
    }
}

// ===================== pos_update ===========================================
__global__ void posupd_kernel(const float* __restrict__ cw, const float* __restrict__ rm,
                              float* __restrict__ out)
{
    const int i = blockIdx.x * blockDim.x + threadIdx.x;
    if (i < N_TOK * 3) out[i] = cw[i / 3] * rm[i];
}

// ===================== launcher =============================================
extern "C" void kernel_launch(void* const* d_in, const int* in_sizes, int n_in,
                              void* d_out, int out_size)
{
    const float* h    = (const float*)d_in[0];
    const float* rel  = (const float*)d_in[1];
    const float* Wq   = (const float*)d_in[2];
    const float* bq   = (const float*)d_in[3];
    const float* Wk   = (const float*)d_in[4];
    const float* bk   = (const float*)d_in[5];
    const float* Wv   = (const float*)d_in[6];
    const float* bv   = (const float*)d_in[7];
    const float* Wo   = (const float*)d_in[8];
    const float* bo   = (const float*)d_in[9];
    const float* W1   = (const float*)d_in[10];
    const float* b1   = (const float*)d_in[11];
    const float* W2   = (const float*)d_in[12];
    const float* b2   = (const float*)d_in[13];
    const float* lnw  = (const float*)d_in[14];
    const float* lnb  = (const float*)d_in[15];
    float* out = (float*)d_out;

    float *attn, *x, *t, *cw, *rm;
    __half *s, *vq, *vtb;
    bf16 *ah, *al, *qh, *ql, *kh, *kl;
    bf16 *wqh, *wql, *wkh, *wkl, *wvh, *wvl, *woh, *wol, *w1h, *w1l;
    cudaGetSymbolAddress((void**)&attn, g_attn);
    cudaGetSymbolAddress((void**)&x,    g_x);
    cudaGetSymbolAddress((void**)&t,    g_t);
    cudaGetSymbolAddress((void**)&cw,   g_cw);
    cudaGetSymbolAddress((void**)&rm,   g_relmean);
    cudaGetSymbolAddress((void**)&s,    g_s);
    cudaGetSymbolAddress((void**)&vq,   g_vq);
    cudaGetSymbolAddress((void**)&vtb,  g_vtb);
    cudaGetSymbolAddress((void**)&ah,   g_ah);
    cudaGetSymbolAddress((void**)&al,   g_al);
    cudaGetSymbolAddress((void**)&qh,   g_qh);
    cudaGetSymbolAddress((void**)&ql,   g_ql);
    cudaGetSymbolAddress((void**)&kh,   g_kh);
    cudaGetSymbolAddress((void**)&kl,   g_kl);
    cudaGetSymbolAddress((void**)&wqh,  g_wqh);
    cudaGetSymbolAddress((void**)&wql,  g_wql);
    cudaGetSymbolAddress((void**)&wkh,  g_wkh);
    cudaGetSymbolAddress((void**)&wkl,  g_wkl);
    cudaGetSymbolAddress((void**)&wvh,  g_wvh);
    cudaGetSymbolAddress((void**)&wvl,  g_wvl);
    cudaGetSymbolAddress((void**)&woh,  g_woh);
    cudaGetSymbolAddress((void**)&wol,  g_wol);
    cudaGetSymbolAddress((void**)&w1h,  g_w1h);
    cudaGetSymbolAddress((void**)&w1l,  g_w1l);

    cudaFuncSetAttribute(pv_mma,      cudaFuncAttributeMaxDynamicSharedMemorySize, PV_SMEM);
    cudaFuncSetAttribute(scores2,     cudaFuncAttributeMaxDynamicSharedMemorySize, SC_SMEM);
    cudaFuncSetAttribute(gemm_mma<0>, cudaFuncAttributeMaxDynamicSharedMemorySize, GEMM_SMEM);
    cudaFuncSetAttribute(gemm_mma<1>, cudaFuncAttributeMaxDynamicSharedMemorySize, GEMM_SMEM);
    cudaFuncSetAttribute(gemm_mma<2>, cudaFuncAttributeMaxDynamicSharedMemorySize, GEMM_SMEM);
    cudaFuncSetAttribute(gemm_mma<3>, cudaFuncAttributeMaxDynamicSharedMemorySize, GEMM_SMEM);
    cudaFuncSetAttribute(gemm_mma<4>, cudaFuncAttributeMaxDynamicSharedMemorySize, GEMM_SMEM);

    // independent: rel_pos mean
    relmean_kernel<<<N_TOK, 128>>>(rel, rm);

    // weight prep: transpose + bf16 split
    trsplit<<<dim3(32, 32), dim3(32, 32)>>>(Wq, wqh, wql, DIM, DIM);
    trsplit<<<dim3(32, 32), dim3(32, 32)>>>(Wk, wkh, wkl, DIM, DIM);
    trsplit<<<dim3(32, 32), dim3(32, 32)>>>(Wv, wvh, wvl, DIM, DIM);
    trsplit<<<dim3(32, 32), dim3(32, 32)>>>(Wo, woh, wol, DIM, DIM);
    trsplit<<<dim3(16, 32), dim3(32, 32)>>>(W1, w1h, w1l, DIM, DIM / 2);

    // h split -> A operand
    split_f32<<<(N_TOK * DIM / 4 + 255) / 256, 256>>>(h, ah, al, N_TOK * DIM / 4);

    // QKV: Q,K bf16 hi/lo; V fp16 single
    gemm_mma<3><<<dim3(8, 32), 256, GEMM_SMEM>>>(ah, al, wqh, wql, bq, nullptr, nullptr, qh, ql, nullptr, N_TOK, DIM, DIM);
    gemm_mma<3><<<dim3(8, 32), 256, GEMM_SMEM>>>(ah, al, wkh, wkl, bk, nullptr, nullptr, kh, kl, nullptr, N_TOK, DIM, DIM);
    gemm_mma<4><<<dim3(8, 32), 256, GEMM_SMEM>>>(ah, al, wvh, wvl, bv, nullptr, nullptr, nullptr, nullptr, vq, N_TOK, DIM, DIM);

    // block V for pv_mma staging
    vblock<<<N_TOK / 16, 512>>>(vq, vtb);

    // attention phase A: raw scores -> fp16
    scores2<<<dim3(32, 16), 256, SC_SMEM>>>(qh, ql, kh, kl, s);

    // attention phase C: softmax over heads + PV (fp16 tensor cores)
    pv_mma<<<N_TOK / 32, 512, PV_SMEM>>>(s, vtb, attn);

    // O projection + residual
    split_f32<<<(N_TOK * DIM / 4 + 255) / 256, 256>>>(attn, ah, al, N_TOK * DIM / 4);
    gemm_mma<1><<<dim3(8, 32), 256, GEMM_SMEM>>>(ah, al, woh, wol, bo, h, x, nullptr, nullptr, nullptr, N_TOK, DIM, DIM);

    // layernorm -> hn
    ln_kernel<<<N_TOK, 256>>>(x, lnw, lnb, out);

    // coord MLP
    split_f32<<<(N_TOK * DIM / 4 + 255) / 256, 256>>>(out, ah, al, N_TOK * DIM / 4);
    gemm_mma<2><<<dim3(4, 32), 256, GEMM_SMEM>>>(ah, al, w1h, w1l, b1, nullptr, t, nullptr, nullptr, nullptr, N_TOK, DIM / 2, DIM);
    mlp2_kernel<<<(N_TOK * 32) / 256, 256>>>(t, W2, b2, cw);

    // pos_update
    posupd_kernel<<<(N_TOK * 3 + 255) / 256, 256>>>(cw, rm, out + (size_t)N_TOK * DIM);
}

// round 13
// speedup vs baseline: 5.4303x; 1.2145x over previous
#include <cuda_runtime.h>
#include <cuda_bf16.h>
#include <cuda_fp16.h>
#include <cstdint>
#include <math.h>

#define N_TOK 4096
#define DIM   1024
#define NH    16
#define HD    64

typedef unsigned long long ull;
typedef __nv_bfloat16 bf16;

// ===================== HMMA primitives (baseline PTX, no 'a' features) ======
__device__ __forceinline__ uint32_t smem_u32(const void* p) {
    uint32_t a;
    asm("{ .reg .u64 t; cvta.to.shared.u64 t, %1; cvt.u32.u64 %0, t; }"
        : "=r"(a) : "l"(p));
    return a;
}
__device__ __forceinline__ void ldmx4(uint32_t* r, uint32_t addr) {
    asm volatile("ldmatrix.sync.aligned.m8n8.x4.shared.b16 {%0,%1,%2,%3}, [%4];"
                 : "=r"(r[0]), "=r"(r[1]), "=r"(r[2]), "=r"(r[3]) : "r"(addr));
}
__device__ __forceinline__ void mma16816(float* c, const uint32_t* a, const uint32_t* b) {
    asm volatile(
        "mma.sync.aligned.m16n8k16.row.col.f32.bf16.bf16.f32 "
        "{%0,%1,%2,%3}, {%4,%5,%6,%7}, {%8,%9}, {%0,%1,%2,%3};"
        : "+f"(c[0]), "+f"(c[1]), "+f"(c[2]), "+f"(c[3])
        : "r"(a[0]), "r"(a[1]), "r"(a[2]), "r"(a[3]), "r"(b[0]), "r"(b[1]));
}
__device__ __forceinline__ void mma16816h(float* c, const uint32_t* a, const uint32_t* b) {
    asm volatile(
        "mma.sync.aligned.m16n8k16.row.col.f32.f16.f16.f32 "
        "{%0,%1,%2,%3}, {%4,%5,%6,%7}, {%8,%9}, {%0,%1,%2,%3};"
        : "+f"(c[0]), "+f"(c[1]), "+f"(c[2]), "+f"(c[3])
        : "r"(a[0]), "r"(a[1]), "r"(a[2]), "r"(a[3]), "r"(b[0]), "r"(b[1]));
}
__device__ __forceinline__ void cpa16(uint32_t dst, const void* src) {
    asm volatile("cp.async.cg.shared.global [%0], [%1], 16;"
                 :: "r"(dst), "l"(src) : "memory");
}
#define CP_COMMIT() asm volatile("cp.async.commit_group;" ::: "memory")
#define CP_WAIT(n)  asm volatile("cp.async.wait_group %0;" :: "n"(n) : "memory")

// dense GEMM smem tile: 128 rows x 32 bf16, row stride 40 (80 B)
#define TROW 40
#define TILE_ELEMS (128 * TROW)
#define GEMM_SMEM (2 * 4 * TILE_ELEMS * 2)      // 81920 B

// scores smem: Q persistent (fp16) + double-buffered K (fp16); stride 72
#define QROW 72
#define QTILE (128 * QROW)
#define SC_SMEM (3 * QTILE * 2)                  // 55296 B

// ===================== scratch globals ======================================
__device__ float g_attn[N_TOK * DIM];
__device__ float g_x[N_TOK * DIM];
__device__ float g_t[N_TOK * (DIM / 2)];
__device__ float g_cw[N_TOK];
__device__ float g_relmean[N_TOK * 3];
__device__ __half g_s[(size_t)NH * N_TOK * N_TOK];  // raw scores [h][n][m], fp16

__device__ bf16 g_ah[N_TOK * DIM], g_al[N_TOK * DIM];
__device__ __half g_qq[N_TOK * DIM];                // Q fp16 single
__device__ __half g_kq[N_TOK * DIM];                // K fp16 single
__device__ __half g_vq[N_TOK * DIM];                // V fp16 single
__device__ __half g_vtb[(size_t)256 * 16 * 64 * 16]; // blocked V [mb][h][d][16m]
__device__ bf16 g_wqh[DIM * DIM], g_wql[DIM * DIM];
__device__ bf16 g_wkh[DIM * DIM], g_wkl[DIM * DIM];
__device__ bf16 g_wvh[DIM * DIM], g_wvl[DIM * DIM];
__device__ bf16 g_woh[DIM * DIM], g_wol[DIM * DIM];
__device__ bf16 g_w1h[(DIM / 2) * DIM], g_w1l[(DIM / 2) * DIM];

// ===================== prep kernels =========================================
__global__ __launch_bounds__(256)
void split_f32(const float* __restrict__ X, bf16* __restrict__ hi,
               bf16* __restrict__ lo, int n4)
{
    const int i = blockIdx.x * blockDim.x + threadIdx.x;
    if (i >= n4) return;
    const float4 v = ((const float4*)X)[i];
    const bf16 h0 = __float2bfloat16(v.x), h1 = __float2bfloat16(v.y);
    const bf16 h2 = __float2bfloat16(v.z), h3 = __float2bfloat16(v.w);
    hi[4 * i + 0] = h0; hi[4 * i + 1] = h1; hi[4 * i + 2] = h2; hi[4 * i + 3] = h3;
    lo[4 * i + 0] = __float2bfloat16(v.x - __bfloat162float(h0));
    lo[4 * i + 1] = __float2bfloat16(v.y - __bfloat162float(h1));
    lo[4 * i + 2] = __float2bfloat16(v.z - __bfloat162float(h2));
    lo[4 * i + 3] = __float2bfloat16(v.w - __bfloat162float(h3));
}

__global__ void trsplit(const float* __restrict__ W, bf16* __restrict__ Thi,
                        bf16* __restrict__ Tlo, int K, int N)
{
    __shared__ float t[32][33];
    const int n = blockIdx.x * 32 + threadIdx.x;
    const int k = blockIdx.y * 32 + threadIdx.y;
    t[threadIdx.y][threadIdx.x] = W[(size_t)k * N + n];
    __syncthreads();
    const int nn = blockIdx.x * 32 + threadIdx.y;
    const int kk = blockIdx.y * 32 + threadIdx.x;
    const float v = t[threadIdx.x][threadIdx.y];
    const bf16 h = __float2bfloat16(v);
    Thi[(size_t)nn * K + kk] = h;
    Tlo[(size_t)nn * K + kk] = __float2bfloat16(v - __bfloat162float(h));
}

// block V fp16 [m][1024] -> [mb][h][d][16m]
__global__ __launch_bounds__(512)
void vblock(const __half* __restrict__ vq, __half* __restrict__ out)
{
    __shared__ __half sh[16 * 1024];
    const int mb  = blockIdx.x;
    const int tid = threadIdx.x;

#pragma unroll
    for (int j = 0; j < 4; j++) {
        const int e  = j * 512 + tid;
        const int mm = e >> 7;
        const int c8 = e & 127;
        ((uint4*)sh)[e] = *(const uint4*)&vq[(size_t)(mb * 16 + mm) * DIM + c8 * 8];
    }
    __syncthreads();

#pragma unroll
    for (int j = 0; j < 4; j++) {
        const int e    = j * 512 + tid;
        const int pl   = e >> 7;                // head
        const int d    = (e >> 1) & 63;
        const int half = e & 1;
        __half tmp[8];
#pragma unroll
        for (int k2 = 0; k2 < 8; k2++)
            tmp[k2] = sh[(half * 8 + k2) * 1024 + pl * 64 + d];
        *(uint4*)&out[(size_t)mb * 16384 + (size_t)e * 8] = *(uint4*)tmp;
    }
}

// ===================== bf16x2 HMMA GEMM (cp.async double-buffered) ==========
// EPI: 0 f32+bias, 1 f32+bias+res, 2 f32+bias+SiLU, 4 fp16 single
template <int EPI>
__global__ __launch_bounds__(256)
void gemm_mma(const bf16* __restrict__ Ahi, const bf16* __restrict__ Alo,
              const bf16* __restrict__ Bhi, const bf16* __restrict__ Blo,
              const float* __restrict__ bias, const float* __restrict__ res,
              float* __restrict__ Cf, __half* __restrict__ Cq, int M, int N, int K)
{
    extern __shared__ bf16 gsm[];
    const uint32_t base = smem_u32(gsm);

    const int tid  = threadIdx.x;
    const int wid  = tid >> 5, lane = tid & 31;
    const int m0   = blockIdx.y * 128, n0 = blockIdx.x * 128;
    const int wm   = (wid & 3) * 32;
    const int wn   = (wid >> 2) * 64;

    float acc[2][8][4];
#pragma unroll
    for (int i = 0; i < 2; i++)
#pragma unroll
        for (int j = 0; j < 8; j++)
#pragma unroll
            for (int r = 0; r < 4; r++) acc[i][j][r] = 0.f;

    const int la_rowA = (lane & 7) + ((lane >> 3) & 1) * 8;
    const int la_kA   = (lane >> 4) * 8;
    const int la_rowB = (lane & 7) + (lane >= 16 ? 8 : 0);
    const int la_kB   = ((lane >> 3) & 1) * 8;

    const int chunks = K >> 5;
    const int r_st  = tid >> 2;
    const int cs_st = (tid & 3) * 8;
#define G_STAGE(c, b) do { \
        const uint32_t bb = base + (uint32_t)(b) * 4 * TILE_ELEMS * 2; \
        _Pragma("unroll") \
        for (int t = 0; t < 2; t++) { \
            const int r = r_st + t * 64; \
            const uint32_t so = (uint32_t)(r * TROW + cs_st) * 2; \
            const size_t ga = (size_t)(m0 + r) * K + (c) * 32 + cs_st; \
            const size_t gb = (size_t)(n0 + r) * K + (c) * 32 + cs_st; \
            cpa16(bb + so,                      Ahi + ga); \
            cpa16(bb + TILE_ELEMS * 2 + so,     Alo + ga); \
            cpa16(bb + TILE_ELEMS * 4 + so,     Bhi + gb); \
            cpa16(bb + TILE_ELEMS * 6 + so,     Blo + gb); \
        } \
        CP_COMMIT(); \
    } while (0)

    G_STAGE(0, 0);

    for (int c = 0; c < chunks; c++) {
        if (c + 1 < chunks) { G_STAGE(c + 1, (c + 1) & 1); CP_WAIT(1); }
        else                { CP_WAIT(0); }
        __syncthreads();

        const uint32_t bb  = base + (uint32_t)(c & 1) * 4 * TILE_ELEMS * 2;
        const uint32_t aAh = bb;
        const uint32_t aAl = bb + TILE_ELEMS * 2;
        const uint32_t aBh = bb + TILE_ELEMS * 4;
        const uint32_t aBl = bb + TILE_ELEMS * 6;

#pragma unroll
        for (int ks = 0; ks < 32; ks += 16) {
            uint32_t ah[2][4], al[2][4];
#pragma unroll
            for (int mt = 0; mt < 2; mt++) {
                const uint32_t off =
                    (uint32_t)((wm + mt * 16 + la_rowA) * TROW + ks + la_kA) * 2;
                ldmx4(ah[mt], aAh + off);
                ldmx4(al[mt], aAl + off);
            }
#pragma unroll
            for (int nt2 = 0; nt2 < 4; nt2++) {
                uint32_t bh[4], bl[4];
                const uint32_t off =
                    (uint32_t)((wn + nt2 * 16 + la_rowB) * TROW + ks + la_kB) * 2;
                ldmx4(bh, aBh + off);
                ldmx4(bl, aBl + off);
#pragma unroll
                for (int sub = 0; sub < 2; sub++) {
#pragma unroll
                    for (int mt = 0; mt < 2; mt++) {
                        float* cc = acc[mt][nt2 * 2 + sub];
                        mma16816(cc, ah[mt], &bh[sub * 2]);
                        mma16816(cc, ah[mt], &bl[sub * 2]);
                        mma16816(cc, al[mt], &bh[sub * 2]);
                    }
                }
            }
        }
        __syncthreads();
    }
#undef G_STAGE

#pragma unroll
    for (int mt = 0; mt < 2; mt++) {
#pragma unroll
        for (int nt = 0; nt < 8; nt++) {
            const int row = m0 + wm + mt * 16 + (lane >> 2);
            const int col = n0 + wn + nt * 8 + (lane & 3) * 2;
#pragma unroll
            for (int half = 0; half < 2; half++) {
                const int rr = row + half * 8;
                float v0 = acc[mt][nt][half * 2 + 0] + bias[col + 0];
                float v1 = acc[mt][nt][half * 2 + 1] + bias[col + 1];
                if (EPI == 1) {
                    const float2 r2 = *(const float2*)&res[(size_t)rr * N + col];
                    v0 += r2.x; v1 += r2.y;
                }
                if (EPI == 2) {
                    v0 = v0 / (1.f + __expf(-v0));
                    v1 = v1 / (1.f + __expf(-v1));
                }
                if (EPI == 4) {
                    *(__half2*)&Cq[(size_t)rr * N + col] = __floats2half2_rn(v0, v1);
                } else {
                    *(float2*)&Cf[(size_t)rr * N + col] = make_float2(v0, v1);
                }
            }
        }
    }
}

// ===================== scores2: fp16 Q/K, 1 MMA pass ========================
__global__ __launch_bounds__(256)
void scores2(const __half* __restrict__ Q, const __half* __restrict__ K,
             __half* __restrict__ S)
{
    extern __shared__ __half ssm[];
    const uint32_t base = smem_u32(ssm);
    const uint32_t aQ  = base;
    const uint32_t aK0 = base + QTILE * 2;
    const uint32_t aK1 = base + QTILE * 4;

    const int tid  = threadIdx.x;
    const int wid  = tid >> 5, lane = tid & 31;
    const int nq0  = blockIdx.x * 128;
    const int h    = blockIdx.y;
    const int wm   = (wid & 3) * 32;
    const int wn   = (wid >> 2) * 64;

    const int r_st  = tid >> 1;
    const int c8_st = (tid & 1) * 4;

#pragma unroll
    for (int u = 0; u < 4; u++) {
        const int seg = c8_st + u;
        const uint32_t so = (uint32_t)(r_st * QROW + seg * 8) * 2;
        cpa16(aQ  + so, Q + (size_t)(nq0 + r_st) * DIM + h * 64 + seg * 8);
        cpa16(aK0 + so, K + (size_t)r_st * DIM + h * 64 + seg * 8);
    }
    CP_COMMIT();

    const int la_rowA = (lane & 7) + ((lane >> 3) & 1) * 8;
    const int la_kA   = (lane >> 4) * 8;
    const int la_rowB = (lane & 7) + (lane >= 16 ? 8 : 0);
    const int la_kB   = ((lane >> 3) & 1) * 8;

    __half* Sp = S + (size_t)h * N_TOK * N_TOK;

    for (int mb = 0; mb < 32; mb++) {
        if (mb + 1 < 32) {
            const uint32_t kb = ((mb + 1) & 1) ? aK1 : aK0;
#pragma unroll
            for (int u = 0; u < 4; u++) {
                const int seg = c8_st + u;
                const uint32_t so = (uint32_t)(r_st * QROW + seg * 8) * 2;
                cpa16(kb + so,
                      K + (size_t)((mb + 1) * 128 + r_st) * DIM + h * 64 + seg * 8);
            }
            CP_COMMIT();
            CP_WAIT(1);
        } else {
            CP_WAIT(0);
        }
        __syncthreads();

        const uint32_t aK = (mb & 1) ? aK1 : aK0;

        float acc[2][8][4];
#pragma unroll
        for (int i = 0; i < 2; i++)
#pragma unroll
            for (int j = 0; j < 8; j++)
#pragma unroll
                for (int r = 0; r < 4; r++) acc[i][j][r] = 0.f;

#pragma unroll
        for (int ks = 0; ks < 64; ks += 16) {
            uint32_t aq[2][4];
#pragma unroll
            for (int mt = 0; mt < 2; mt++) {
                const uint32_t off =
                    (uint32_t)((wm + mt * 16 + la_rowA) * QROW + ks + la_kA) * 2;
                ldmx4(aq[mt], aQ + off);
            }
#pragma unroll
            for (int nt2 = 0; nt2 < 4; nt2++) {
                uint32_t bk[4];
                const uint32_t off =
                    (uint32_t)((wn + nt2 * 16 + la_rowB) * QROW + ks + la_kB) * 2;
                ldmx4(bk, aK + off);
#pragma unroll
                for (int sub = 0; sub < 2; sub++) {
#pragma unroll
                    for (int mt = 0; mt < 2; mt++)
                        mma16816h(acc[mt][nt2 * 2 + sub], aq[mt], &bk[sub * 2]);
                }
            }
        }

#pragma unroll
        for (int mt = 0; mt < 2; mt++) {
#pragma unroll
            for (int nt = 0; nt < 8; nt++) {
                const int row = nq0 + wm + mt * 16 + (lane >> 2);
                const int col = mb * 128 + wn + nt * 8 + (lane & 3) * 2;
#pragma unroll
                for (int half = 0; half < 2; half++) {
                    *(__half2*)&Sp[(size_t)(row + half * 8) * N_TOK + col] =
                        __floats2half2_rn(acc[mt][nt][half * 2 + 0],
                                          acc[mt][nt][half * 2 + 1]);
                }
            }
        }
        __syncthreads();
    }
}

// ===================== Phase C: softmax-over-heads + PV (fp16, 1 pass) ======
// P: fp16 planes [16h][32n][24m]; V: fp16 planes [16h][64d][40m].
#define P_PLANE 768                 // 32 * 24
#define V_PLANE 2560                // 64 * 40
#define PV_SMEM ((16 * P_PLANE + 16 * V_PLANE) * 2)   // 106496 B

__global__ __launch_bounds__(512, 1)
void pv_mma(const __half* __restrict__ S, const __half* __restrict__ Vtb,
            float* __restrict__ O)
{
    extern __shared__ __half smh[];
    __half* ps = smh;                     // 16 planes x 768
    __half* vs = smh + 16 * P_PLANE;      // 16 planes x 2560

    const int tid  = threadIdx.x;
    const int wid  = tid >> 5;            // = head
    const int lane = tid & 31;
    const int n0   = blockIdx.x * 32;
    const int nn   = tid >> 4;
    const int mmq  = tid & 15;

    const uint32_t psb = smem_u32(ps);
    const uint32_t vsb = smem_u32(vs);

    float acc[2][8][4];
#pragma unroll
    for (int i = 0; i < 2; i++)
#pragma unroll
        for (int j = 0; j < 8; j++)
#pragma unroll
            for (int r = 0; r < 4; r++) acc[i][j][r] = 0.f;

    const int la_rowA = (lane & 7) + ((lane >> 3) & 1) * 8;
    const int la_kA   = (lane >> 4) * 8;
    const int la_rowB = (lane & 7) + (lane >= 16 ? 8 : 0);
    const int la_kB   = ((lane >> 3) & 1) * 8;

    const size_t N2 = (size_t)N_TOK * N_TOK;
    const __half* sp0 = S + (size_t)(n0 + nn) * N_TOK + mmq;

    for (int mt0 = 0; mt0 < N_TOK / 16; mt0++) {
        const int m0 = mt0 * 16;

        const uint4* vsrc = (const uint4*)(Vtb + (size_t)mt0 * 16384);
#pragma unroll
        for (int j = 0; j < 4; j++) {
            const int e    = j * 512 + tid;
            const int pl   = e >> 7;
            const int d    = (e >> 1) & 63;
            const int half = e & 1;
            *(uint4*)&vs[pl * V_PLANE + d * 40 + half * 8] = vsrc[e];
        }

        {
            const __half* sp = sp0 + m0;
            float sv[16];
#pragma unroll
            for (int q = 0; q < 16; q++)
                sv[q] = __half2float(sp[(size_t)q * N2]) * 0.125f;
            float mx = sv[0];
#pragma unroll
            for (int q = 1; q < 16; q++) mx = fmaxf(mx, sv[q]);
            float ssum = 0.f;
#pragma unroll
            for (int q = 0; q < 16; q++) { sv[q] = __expf(sv[q] - mx); ssum += sv[q]; }
            const float rinv = __fdividef(1.f, ssum);
#pragma unroll
            for (int q = 0; q < 16; q++)
                ps[q * P_PLANE + nn * 24 + mmq] = __float2half_rn(sv[q] * rinv);
        }
        __syncthreads();

        {
            const uint32_t pb = psb + (uint32_t)wid * P_PLANE * 2;
            const uint32_t vb = vsb + (uint32_t)wid * V_PLANE * 2;

            uint32_t ap[2][4];
#pragma unroll
            for (int mt = 0; mt < 2; mt++) {
                const uint32_t off =
                    (uint32_t)((mt * 16 + la_rowA) * 24 + la_kA) * 2;
                ldmx4(ap[mt], pb + off);
            }
#pragma unroll
            for (int nt2 = 0; nt2 < 4; nt2++) {
                uint32_t bv[4];
                const uint32_t off =
                    (uint32_t)((nt2 * 16 + la_rowB) * 40 + la_kB) * 2;
                ldmx4(bv, vb + off);
#pragma unroll
                for (int sub = 0; sub < 2; sub++) {
#pragma unroll
                    for (int mt = 0; mt < 2; mt++)
                        mma16816h(acc[mt][nt2 * 2 + sub], ap[mt], &bv[sub * 2]);
                }
            }
        }
        __syncthreads();
    }

#pragma unroll
    for (int mt = 0; mt < 2; mt++) {
#pragma unroll
        for (int nt = 0; nt < 8; nt++) {
            const int row = n0 + mt * 16 + (lane >> 2);
            const int col = wid * 64 + nt * 8 + (lane & 3) * 2;
#pragma unroll
            for (int half = 0; half < 2; half++) {
                *(float2*)&O[(size_t)(row + half * 8) * DIM + col] =
                    make_float2(acc[mt][nt][half * 2 + 0], acc[mt][nt][half * 2 + 1]);
            }
        }
    }
}

// ===================== LayerNorm ============================================
__global__ __launch_bounds__(256)
void ln_kernel(const float* __restrict__ X, const float* __restrict__ w,
               const float* __restrict__ b, float* __restrict__ out)
{
    const int n   = blockIdx.x;
    const int tid = threadIdx.x;
    const float4 x = ((const float4*)(X + (size_t)n * DIM))[tid];

    float s  = x.x + x.y + x.z + x.w;
    float ss = x.x * x.x + x.y * x.y + x.z * x.z + x.w * x.w;
#pragma unroll
    for (int off = 16; off; off >>= 1) {
        s  += __shfl_xor_sync(0xffffffffu, s, off);
        ss += __shfl_xor_sync(0xffffffffu, ss, off);
    }
    __shared__ float rs[8], rss[8], stat[2];
    if ((tid & 31) == 0) { rs[tid >> 5] = s; rss[tid >> 5] = ss; }
    __syncthreads();
    if (tid == 0) {
        float S = 0.f, SS = 0.f;
#pragma unroll
        for (int i = 0; i < 8; i++) { S += rs[i]; SS += rss[i]; }
        const float mean = S * (1.f / DIM);
        const float var  = SS * (1.f / DIM) - mean * mean;
        stat[0] = mean;
        stat[1] = rsqrtf(var + 1e-5f);
    }
    __syncthreads();
    const float mean = stat[0], inv = stat[1];
    const int col = tid * 4;
    const float4 wv = *(const float4*)&w[col];
    const float4 bv = *(const float4*)&b[col];
    float4 o;
    o.x = (x.x - mean) * inv * wv.x + bv.x;
    o.y = (x.y - mean) * inv * wv.y + bv.y;
    o.z = (x.z - mean) * inv * wv.z + bv.z;
    o.w = (x.w - mean) * inv * wv.w + bv.w;
    ((float4*)(out + (size_t)n * DIM))[tid] = o;
}

// ===================== coord MLP layer 2 ====================================
__global__ void mlp2_kernel(const float* __restrict__ T, const float* __restrict__ W2,
                            const float* __restrict__ b2, float* __restrict__ cw)
{
    const int warp = (blockIdx.x * blockDim.x + threadIdx.x) >> 5;
    const int lane = threadIdx.x & 31;
    if (warp >= N_TOK) return;
    const float* t = T + (size_t)warp * (DIM / 2);
    float s = 0.f;
#pragma unroll
    for (int j = 0; j < DIM / 2; j += 32) s = fmaf(t[j + lane], W2[j + lane], s);
#pragma unroll
    for (int off = 16; off; off >>= 1) s += __shfl_xor_sync(0xffffffffu, s, off);
    if (lane == 0) cw[warp] = s + b2[0];
}

// ===================== rel_pos mean =========================================
__global__ __launch_bounds__(128)
void relmean_kernel(const float* __restrict__ rel, float* __restrict__ out)
{
    const int n   = blockIdx.x;
    const int tid = threadIdx.x;
    const float* base = rel + (size_t)n * N_TOK * 3;
    float s0 = 0.f, s1 = 0.f, s2 = 0.f;
    for (int m = tid; m < N_TOK; m += 128) {
        s0 += base[m * 3 + 0];
        s1 += base[m * 3 + 1];
        s2 += base[m * 3 + 2];
    }
#pragma unroll
    for (int off = 16; off; off >>= 1) {
        s0 += __shfl_xor_sync(0xffffffffu, s0, off);
        s1 += __shfl_xor_sync(0xffffffffu, s1, off);
        s2 += __shfl_xor_sync(0xffffffffu, s2, off);
    }
    __shared__ float sm[3][4];
    if ((tid & 31) == 0) {
        sm[0][tid >> 5] = s0; sm[1][tid >> 5] = s1; sm[2][tid >> 5] = s2;
    }
    __syncthreads();
    if (tid == 0) {
        out[n * 3 + 0] = (sm[0][0] + sm[0][1] + sm[0][2] + sm[0][3]) * (1.f / N_TOK);
        out[n * 3 + 1] = (sm[1][0] + sm[1][1] + sm[1][2] + sm[1][3]) * (1.f / N_TOK);
        out[n * 3 + 2] = (sm[2][0] + sm[2][1] + sm[2][2] + sm[2][3]) * (1.f / N_TOK);
    }
}

// ===================== pos_update ===========================================
__global__ void posupd_kernel(const float* __restrict__ cw, const float* __restrict__ rm,
                              float* __restrict__ out)
{
    const int i = blockIdx.x * blockDim.x + threadIdx.x;
    if (i < N_TOK * 3) out[i] = cw[i / 3] * rm[i];
}

// ===================== launcher =============================================
extern "C" void kernel_launch(void* const* d_in, const int* in_sizes, int n_in,
                              void* d_out, int out_size)
{
    const float* h    = (const float*)d_in[0];
    const float* rel  = (const float*)d_in[1];
    const float* Wq   = (const float*)d_in[2];
    const float* bq   = (const float*)d_in[3];
    const float* Wk   = (const float*)d_in[4];
    const float* bk   = (const float*)d_in[5];
    const float* Wv   = (const float*)d_in[6];
    const float* bv   = (const float*)d_in[7];
    const float* Wo   = (const float*)d_in[8];
    const float* bo   = (const float*)d_in[9];
    const float* W1   = (const float*)d_in[10];
    const float* b1   = (const float*)d_in[11];
    const float* W2   = (const float*)d_in[12];
    const float* b2   = (const float*)d_in[13];
    const float* lnw  = (const float*)d_in[14];
    const float* lnb  = (const float*)d_in[15];
    float* out = (float*)d_out;

    float *attn, *x, *t, *cw, *rm;
    __half *s, *qq, *kq, *vq, *vtb;
    bf16 *ah, *al;
    bf16 *wqh, *wql, *wkh, *wkl, *wvh, *wvl, *woh, *wol, *w1h, *w1l;
    cudaGetSymbolAddress((void**)&attn, g_attn);
    cudaGetSymbolAddress((void**)&x,    g_x);
    cudaGetSymbolAddress((void**)&t,    g_t);
    cudaGetSymbolAddress((void**)&cw,   g_cw);
    cudaGetSymbolAddress((void**)&rm,   g_relmean);
    cudaGetSymbolAddress((void**)&s,    g_s);
    cudaGetSymbolAddress((void**)&qq,   g_qq);
    cudaGetSymbolAddress((void**)&kq,   g_kq);
    cudaGetSymbolAddress((void**)&vq,   g_vq);
    cudaGetSymbolAddress((void**)&vtb,  g_vtb);
    cudaGetSymbolAddress((void**)&ah,   g_ah);
    cudaGetSymbolAddress((void**)&al,   g_al);
    cudaGetSymbolAddress((void**)&wqh,  g_wqh);
    cudaGetSymbolAddress((void**)&wql,  g_wql);
    cudaGetSymbolAddress((void**)&wkh,  g_wkh);
    cudaGetSymbolAddress((void**)&wkl,  g_wkl);
    cudaGetSymbolAddress((void**)&wvh,  g_wvh);
    cudaGetSymbolAddress((void**)&wvl,  g_wvl);
    cudaGetSymbolAddress((void**)&woh,  g_woh);
    cudaGetSymbolAddress((void**)&wol,  g_wol);
    cudaGetSymbolAddress((void**)&w1h,  g_w1h);
    cudaGetSymbolAddress((void**)&w1l,  g_w1l);

    cudaFuncSetAttribute(pv_mma,      cudaFuncAttributeMaxDynamicSharedMemorySize, PV_SMEM);
    cudaFuncSetAttribute(scores2,     cudaFuncAttributeMaxDynamicSharedMemorySize, SC_SMEM);
    cudaFuncSetAttribute(gemm_mma<0>, cudaFuncAttributeMaxDynamicSharedMemorySize, GEMM_SMEM);
    cudaFuncSetAttribute(gemm_mma<1>, cudaFuncAttributeMaxDynamicSharedMemorySize, GEMM_SMEM);
    cudaFuncSetAttribute(gemm_mma<2>, cudaFuncAttributeMaxDynamicSharedMemorySize, GEMM_SMEM);
    cudaFuncSetAttribute(gemm_mma<4>, cudaFuncAttributeMaxDynamicSharedMemorySize, GEMM_SMEM);

    // independent: rel_pos mean
    relmean_kernel<<<N_TOK, 128>>>(rel, rm);

    // weight prep: transpose + bf16 split
    trsplit<<<dim3(32, 32), dim3(32, 32)>>>(Wq, wqh, wql, DIM, DIM);
    trsplit<<<dim3(32, 32), dim3(32, 32)>>>(Wk, wkh, wkl, DIM, DIM);
    trsplit<<<dim3(32, 32), dim3(32, 32)>>>(Wv, wvh, wvl, DIM, DIM);
    trsplit<<<dim3(32, 32), dim3(32, 32)>>>(Wo, woh, wol, DIM, DIM);
    trsplit<<<dim3(16, 32), dim3(32, 32)>>>(W1, w1h, w1l, DIM, DIM / 2);

    // h split -> A operand
    split_f32<<<(N_TOK * DIM / 4 + 255) / 256, 256>>>(h, ah, al, N_TOK * DIM / 4);

    // QKV: all fp16 single-plane outputs
    gemm_mma<4><<<dim3(8, 32), 256, GEMM_SMEM>>>(ah, al, wqh, wql, bq, nullptr, nullptr, qq, N_TOK, DIM, DIM);
    gemm_mma<4><<<dim3(8, 32), 256, GEMM_SMEM>>>(ah, al, wkh, wkl, bk, nullptr, nullptr, kq, N_TOK, DIM, DIM);
    gemm_mma<4><<<dim3(8, 32), 256, GEMM_SMEM>>>(ah, al, wvh, wvl, bv, nullptr, nullptr, vq, N_TOK, DIM, DIM);

    // block V for pv_mma staging
    vblock<<<N_TOK / 16, 512>>>(vq, vtb);

    // attention phase A: raw scores -> fp16 (1-pass fp16 MMA)
    scores2<<<dim3(32, 16), 256, SC_SMEM>>>(qq, kq, s);

    // attention phase C: softmax over heads + PV (1-pass fp16 MMA)
    pv_mma<<<N_TOK / 32, 512, PV_SMEM>>>(s, vtb, attn);

    // O projection + residual
    split_f32<<<(N_TOK * DIM / 4 + 255) / 256, 256>>>(attn, ah, al, N_TOK * DIM / 4);
    gemm_mma<1><<<dim3(8, 32), 256, GEMM_SMEM>>>(ah, al, woh, wol, bo, h, x, nullptr, N_TOK, DIM, DIM);

    // layernorm -> hn
    ln_kernel<<<N_TOK, 256>>>(x, lnw, lnb, out);

    // coord MLP
    split_f32<<<(N_TOK * DIM / 4 + 255) / 256, 256>>>(out, ah, al, N_TOK * DIM / 4);
    gemm_mma<2><<<dim3(4, 32), 256, GEMM_SMEM>>>(ah, al, w1h, w1l, b1, nullptr, t, nullptr, N_TOK, DIM / 2, DIM);
    mlp2_kernel<<<(N_TOK * 32) / 256, 256>>>(t, W2, b2, cw);

    // pos_update
    posupd_kernel<<<(N_TOK * 3 + 255) / 256, 256>>>(cw, rm, out + (size_t)N_TOK * DIM);
}

// round 14
// speedup vs baseline: 6.6350x; 1.2218x over previous
#include <cuda_runtime.h>
#include <cuda_bf16.h>
#include <cuda_fp16.h>
#include <cstdint>
#include <math.h>

#define N_TOK 4096
#define DIM   1024
#define NH    16
#define HD    64

typedef unsigned long long ull;

// ===================== HMMA primitives (baseline PTX, no 'a' features) ======
__device__ __forceinline__ uint32_t smem_u32(const void* p) {
    uint32_t a;
    asm("{ .reg .u64 t; cvta.to.shared.u64 t, %1; cvt.u32.u64 %0, t; }"
        : "=r"(a) : "l"(p));
    return a;
}
__device__ __forceinline__ void ldmx4(uint32_t* r, uint32_t addr) {
    asm volatile("ldmatrix.sync.aligned.m8n8.x4.shared.b16 {%0,%1,%2,%3}, [%4];"
                 : "=r"(r[0]), "=r"(r[1]), "=r"(r[2]), "=r"(r[3]) : "r"(addr));
}
__device__ __forceinline__ void mma16816h(float* c, const uint32_t* a, const uint32_t* b) {
    asm volatile(
        "mma.sync.aligned.m16n8k16.row.col.f32.f16.f16.f32 "
        "{%0,%1,%2,%3}, {%4,%5,%6,%7}, {%8,%9}, {%0,%1,%2,%3};"
        : "+f"(c[0]), "+f"(c[1]), "+f"(c[2]), "+f"(c[3])
        : "r"(a[0]), "r"(a[1]), "r"(a[2]), "r"(a[3]), "r"(b[0]), "r"(b[1]));
}
__device__ __forceinline__ void cpa16(uint32_t dst, const void* src) {
    asm volatile("cp.async.cg.shared.global [%0], [%1], 16;"
                 :: "r"(dst), "l"(src) : "memory");
}
#define CP_COMMIT() asm volatile("cp.async.commit_group;" ::: "memory")
#define CP_WAIT(n)  asm volatile("cp.async.wait_group %0;" :: "n"(n) : "memory")

// dense GEMM smem tile: 128 rows x 32 fp16, row stride 40 (80 B)
#define TROW 40
#define TILE_ELEMS (128 * TROW)
#define GEMM_SMEM (2 * 2 * TILE_ELEMS * 2)      // 40960 B (2 buffers x 2 tiles)

// scores smem: Q persistent (fp16) + double-buffered K (fp16); stride 72
#define QROW 72
#define QTILE (128 * QROW)
#define SC_SMEM (3 * QTILE * 2)                  // 55296 B

// ===================== scratch globals ======================================
__device__ float g_attn[N_TOK * DIM];
__device__ float g_x[N_TOK * DIM];
__device__ float g_t[N_TOK * (DIM / 2)];
__device__ float g_cw[N_TOK];
__device__ float g_relmean[N_TOK * 3];
__device__ __half g_s[(size_t)NH * N_TOK * N_TOK];  // raw scores [h][n][m], fp16

__device__ __half g_aq[N_TOK * DIM];                // A operand fp16 (reused)
__device__ __half g_qq[N_TOK * DIM];
__device__ __half g_kq[N_TOK * DIM];
__device__ __half g_vq[N_TOK * DIM];
__device__ __half g_vtb[(size_t)256 * 16 * 64 * 16]; // blocked V [mb][h][d][16m]
__device__ __half g_wq16[DIM * DIM];
__device__ __half g_wk16[DIM * DIM];
__device__ __half g_wv16[DIM * DIM];
__device__ __half g_wo16[DIM * DIM];
__device__ __half g_w116[(DIM / 2) * DIM];

// ===================== prep kernels =========================================
__global__ __launch_bounds__(256)
void cvt16(const float* __restrict__ X, __half* __restrict__ Y, int n4)
{
    const int i = blockIdx.x * blockDim.x + threadIdx.x;
    if (i >= n4) return;
    const float4 v = ((const float4*)X)[i];
    *(__half2*)&Y[4 * i + 0] = __floats2half2_rn(v.x, v.y);
    *(__half2*)&Y[4 * i + 2] = __floats2half2_rn(v.z, v.w);
}

// transpose W[K][N] -> T[N][K], fp16
__global__ void trcvt(const float* __restrict__ W, __half* __restrict__ T, int K, int N)
{
    __shared__ float t[32][33];
    const int n = blockIdx.x * 32 + threadIdx.x;
    const int k = blockIdx.y * 32 + threadIdx.y;
    t[threadIdx.y][threadIdx.x] = W[(size_t)k * N + n];
    __syncthreads();
    const int nn = blockIdx.x * 32 + threadIdx.y;
    const int kk = blockIdx.y * 32 + threadIdx.x;
    T[(size_t)nn * K + kk] = __float2half_rn(t[threadIdx.x][threadIdx.y]);
}

// block V fp16 [m][1024] -> [mb][h][d][16m]
__global__ __launch_bounds__(512)
void vblock(const __half* __restrict__ vq, __half* __restrict__ out)
{
    __shared__ __half sh[16 * 1024];
    const int mb  = blockIdx.x;
    const int tid = threadIdx.x;

#pragma unroll
    for (int j = 0; j < 4; j++) {
        const int e  = j * 512 + tid;
        const int mm = e >> 7;
        const int c8 = e & 127;
        ((uint4*)sh)[e] = *(const uint4*)&vq[(size_t)(mb * 16 + mm) * DIM + c8 * 8];
    }
    __syncthreads();

#pragma unroll
    for (int j = 0; j < 4; j++) {
        const int e    = j * 512 + tid;
        const int pl   = e >> 7;                // head
        const int d    = (e >> 1) & 63;
        const int half = e & 1;
        __half tmp[8];
#pragma unroll
        for (int k2 = 0; k2 < 8; k2++)
            tmp[k2] = sh[(half * 8 + k2) * 1024 + pl * 64 + d];
        *(uint4*)&out[(size_t)mb * 16384 + (size_t)e * 8] = *(uint4*)tmp;
    }
}

// ===================== fp16 HMMA GEMM (cp.async double-buffered, 1 pass) ====
// D[M,N] = A[M,K] @ Bt[N,K]^T + bias
// EPI: 0 f32+bias, 1 f32+bias+res, 2 f32+bias+SiLU, 4 fp16 single
template <int EPI>
__global__ __launch_bounds__(256)
void gemm_mma(const __half* __restrict__ A, const __half* __restrict__ B,
              const float* __restrict__ bias, const float* __restrict__ res,
              float* __restrict__ Cf, __half* __restrict__ Cq, int M, int N, int K)
{
    extern __shared__ __half gsm[];
    const uint32_t base = smem_u32(gsm);

    const int tid  = threadIdx.x;
    const int wid  = tid >> 5, lane = tid & 31;
    const int m0   = blockIdx.y * 128, n0 = blockIdx.x * 128;
    const int wm   = (wid & 3) * 32;
    const int wn   = (wid >> 2) * 64;

    float acc[2][8][4];
#pragma unroll
    for (int i = 0; i < 2; i++)
#pragma unroll
        for (int j = 0; j < 8; j++)
#pragma unroll
            for (int r = 0; r < 4; r++) acc[i][j][r] = 0.f;

    const int la_rowA = (lane & 7) + ((lane >> 3) & 1) * 8;
    const int la_kA   = (lane >> 4) * 8;
    const int la_rowB = (lane & 7) + (lane >= 16 ? 8 : 0);
    const int la_kB   = ((lane >> 3) & 1) * 8;

    const int chunks = K >> 5;
    const int r_st  = tid >> 2;
    const int cs_st = (tid & 3) * 8;
#define G_STAGE(c, b) do { \
        const uint32_t bb = base + (uint32_t)(b) * 2 * TILE_ELEMS * 2; \
        _Pragma("unroll") \
        for (int t = 0; t < 2; t++) { \
            const int r = r_st + t * 64; \
            const uint32_t so = (uint32_t)(r * TROW + cs_st) * 2; \
            cpa16(bb + so,                  A + (size_t)(m0 + r) * K + (c) * 32 + cs_st); \
            cpa16(bb + TILE_ELEMS * 2 + so, B + (size_t)(n0 + r) * K + (c) * 32 + cs_st); \
        } \
        CP_COMMIT(); \
    } while (0)

    G_STAGE(0, 0);

    for (int c = 0; c < chunks; c++) {
        if (c + 1 < chunks) { G_STAGE(c + 1, (c + 1) & 1); CP_WAIT(1); }
        else                { CP_WAIT(0); }
        __syncthreads();

        const uint32_t bb = base + (uint32_t)(c & 1) * 2 * TILE_ELEMS * 2;
        const uint32_t aA = bb;
        const uint32_t aB = bb + TILE_ELEMS * 2;

#pragma unroll
        for (int ks = 0; ks < 32; ks += 16) {
            uint32_t af[2][4];
#pragma unroll
            for (int mt = 0; mt < 2; mt++) {
                const uint32_t off =
                    (uint32_t)((wm + mt * 16 + la_rowA) * TROW + ks + la_kA) * 2;
                ldmx4(af[mt], aA + off);
            }
#pragma unroll
            for (int nt2 = 0; nt2 < 4; nt2++) {
                uint32_t bf[4];
                const uint32_t off =
                    (uint32_t)((wn + nt2 * 16 + la_rowB) * TROW + ks + la_kB) * 2;
                ldmx4(bf, aB + off);
#pragma unroll
                for (int sub = 0; sub < 2; sub++) {
#pragma unroll
                    for (int mt = 0; mt < 2; mt++)
                        mma16816h(acc[mt][nt2 * 2 + sub], af[mt], &bf[sub * 2]);
                }
            }
        }
        __syncthreads();
    }
#undef G_STAGE

#pragma unroll
    for (int mt = 0; mt < 2; mt++) {
#pragma unroll
        for (int nt = 0; nt < 8; nt++) {
            const int row = m0 + wm + mt * 16 + (lane >> 2);
            const int col = n0 + wn + nt * 8 + (lane & 3) * 2;
#pragma unroll
            for (int half = 0; half < 2; half++) {
                const int rr = row + half * 8;
                float v0 = acc[mt][nt][half * 2 + 0] + bias[col + 0];
                float v1 = acc[mt][nt][half * 2 + 1] + bias[col + 1];
                if (EPI == 1) {
                    const float2 r2 = *(const float2*)&res[(size_t)rr * N + col];
                    v0 += r2.x; v1 += r2.y;
                }
                if (EPI == 2) {
                    v0 = v0 / (1.f + __expf(-v0));
                    v1 = v1 / (1.f + __expf(-v1));
                }
                if (EPI == 4) {
                    *(__half2*)&Cq[(size_t)rr * N + col] = __floats2half2_rn(v0, v1);
                } else {
                    *(float2*)&Cf[(size_t)rr * N + col] = make_float2(v0, v1);
                }
            }
        }
    }
}

// ===================== scores2: fp16 Q/K, 1 MMA pass ========================
__global__ __launch_bounds__(256)
void scores2(const __half* __restrict__ Q, const __half* __restrict__ K,
             __half* __restrict__ S)
{
    extern __shared__ __half ssm[];
    const uint32_t base = smem_u32(ssm);
    const uint32_t aQ  = base;
    const uint32_t aK0 = base + QTILE * 2;
    const uint32_t aK1 = base + QTILE * 4;

    const int tid  = threadIdx.x;
    const int wid  = tid >> 5, lane = tid & 31;
    const int nq0  = blockIdx.x * 128;
    const int h    = blockIdx.y;
    const int wm   = (wid & 3) * 32;
    const int wn   = (wid >> 2) * 64;

    const int r_st  = tid >> 1;
    const int c8_st = (tid & 1) * 4;

#pragma unroll
    for (int u = 0; u < 4; u++) {
        const int seg = c8_st + u;
        const uint32_t so = (uint32_t)(r_st * QROW + seg * 8) * 2;
        cpa16(aQ  + so, Q + (size_t)(nq0 + r_st) * DIM + h * 64 + seg * 8);
        cpa16(aK0 + so, K + (size_t)r_st * DIM + h * 64 + seg * 8);
    }
    CP_COMMIT();

    const int la_rowA = (lane & 7) + ((lane >> 3) & 1) * 8;
    const int la_kA   = (lane >> 4) * 8;
    const int la_rowB = (lane & 7) + (lane >= 16 ? 8 : 0);
    const int la_kB   = ((lane >> 3) & 1) * 8;

    __half* Sp = S + (size_t)h * N_TOK * N_TOK;

    for (int mb = 0; mb < 32; mb++) {
        if (mb + 1 < 32) {
            const uint32_t kb = ((mb + 1) & 1) ? aK1 : aK0;
#pragma unroll
            for (int u = 0; u < 4; u++) {
                const int seg = c8_st + u;
                const uint32_t so = (uint32_t)(r_st * QROW + seg * 8) * 2;
                cpa16(kb + so,
                      K + (size_t)((mb + 1) * 128 + r_st) * DIM + h * 64 + seg * 8);
            }
            CP_COMMIT();
            CP_WAIT(1);
        } else {
            CP_WAIT(0);
        }
        __syncthreads();

        const uint32_t aK = (mb & 1) ? aK1 : aK0;

        float acc[2][8][4];
#pragma unroll
        for (int i = 0; i < 2; i++)
#pragma unroll
            for (int j = 0; j < 8; j++)
#pragma unroll
                for (int r = 0; r < 4; r++) acc[i][j][r] = 0.f;

#pragma unroll
        for (int ks = 0; ks < 64; ks += 16) {
            uint32_t aq[2][4];
#pragma unroll
            for (int mt = 0; mt < 2; mt++) {
                const uint32_t off =
                    (uint32_t)((wm + mt * 16 + la_rowA) * QROW + ks + la_kA) * 2;
                ldmx4(aq[mt], aQ + off);
            }
#pragma unroll
            for (int nt2 = 0; nt2 < 4; nt2++) {
                uint32_t bk[4];
                const uint32_t off =
                    (uint32_t)((wn + nt2 * 16 + la_rowB) * QROW + ks + la_kB) * 2;
                ldmx4(bk, aK + off);
#pragma unroll
                for (int sub = 0; sub < 2; sub++) {
#pragma unroll
                    for (int mt = 0; mt < 2; mt++)
                        mma16816h(acc[mt][nt2 * 2 + sub], aq[mt], &bk[sub * 2]);
                }
            }
        }

#pragma unroll
        for (int mt = 0; mt < 2; mt++) {
#pragma unroll
            for (int nt = 0; nt < 8; nt++) {
                const int row = nq0 + wm + mt * 16 + (lane >> 2);
                const int col = mb * 128 + wn + nt * 8 + (lane & 3) * 2;
#pragma unroll
                for (int half = 0; half < 2; half++) {
                    *(__half2*)&Sp[(size_t)(row + half * 8) * N_TOK + col] =
                        __floats2half2_rn(acc[mt][nt][half * 2 + 0],
                                          acc[mt][nt][half * 2 + 1]);
                }
            }
        }
        __syncthreads();
    }
}

// ===================== Phase C: softmax-over-heads + PV (fp16, 1 pass) ======
#define P_PLANE 768                 // 32 * 24
#define V_PLANE 2560                // 64 * 40
#define PV_SMEM ((16 * P_PLANE + 16 * V_PLANE) * 2)   // 106496 B

__global__ __launch_bounds__(512, 1)
void pv_mma(const __half* __restrict__ S, const __half* __restrict__ Vtb,
            float* __restrict__ O)
{
    extern __shared__ __half smh[];
    __half* ps = smh;
    __half* vs = smh + 16 * P_PLANE;

    const int tid  = threadIdx.x;
    const int wid  = tid >> 5;            // = head
    const int lane = tid & 31;
    const int n0   = blockIdx.x * 32;
    const int nn   = tid >> 4;
    const int mmq  = tid & 15;

    const uint32_t psb = smem_u32(ps);
    const uint32_t vsb = smem_u32(vs);

    float acc[2][8][4];
#pragma unroll
    for (int i = 0; i < 2; i++)
#pragma unroll
        for (int j = 0; j < 8; j++)
#pragma unroll
            for (int r = 0; r < 4; r++) acc[i][j][r] = 0.f;

    const int la_rowA = (lane & 7) + ((lane >> 3) & 1) * 8;
    const int la_kA   = (lane >> 4) * 8;
    const int la_rowB = (lane & 7) + (lane >= 16 ? 8 : 0);
    const int la_kB   = ((lane >> 3) & 1) * 8;

    const size_t N2 = (size_t)N_TOK * N_TOK;
    const __half* sp0 = S + (size_t)(n0 + nn) * N_TOK + mmq;

    for (int mt0 = 0; mt0 < N_TOK / 16; mt0++) {
        const int m0 = mt0 * 16;

        const uint4* vsrc = (const uint4*)(Vtb + (size_t)mt0 * 16384);
#pragma unroll
        for (int j = 0; j < 4; j++) {
            const int e    = j * 512 + tid;
            const int pl   = e >> 7;
            const int d    = (e >> 1) & 63;
            const int half = e & 1;
            *(uint4*)&vs[pl * V_PLANE + d * 40 + half * 8] = vsrc[e];
        }

        {
            const __half* sp = sp0 + m0;
            float sv[16];
#pragma unroll
            for (int q = 0; q < 16; q++)
                sv[q] = __half2float(sp[(size_t)q * N2]) * 0.125f;
            float mx = sv[0];
#pragma unroll
            for (int q = 1; q < 16; q++) mx = fmaxf(mx, sv[q]);
            float ssum = 0.f;
#pragma unroll
            for (int q = 0; q < 16; q++) { sv[q] = __expf(sv[q] - mx); ssum += sv[q]; }
            const float rinv = __fdividef(1.f, ssum);
#pragma unroll
            for (int q = 0; q < 16; q++)
                ps[q * P_PLANE + nn * 24 + mmq] = __float2half_rn(sv[q] * rinv);
        }
        __syncthreads();

        {
            const uint32_t pb = psb + (uint32_t)wid * P_PLANE * 2;
            const uint32_t vb = vsb + (uint32_t)wid * V_PLANE * 2;

            uint32_t ap[2][4];
#pragma unroll
            for (int mt = 0; mt < 2; mt++) {
                const uint32_t off =
                    (uint32_t)((mt * 16 + la_rowA) * 24 + la_kA) * 2;
                ldmx4(ap[mt], pb + off);
            }
#pragma unroll
            for (int nt2 = 0; nt2 < 4; nt2++) {
                uint32_t bv[4];
                const uint32_t off =
                    (uint32_t)((nt2 * 16 + la_rowB) * 40 + la_kB) * 2;
                ldmx4(bv, vb + off);
#pragma unroll
                for (int sub = 0; sub < 2; sub++) {
#pragma unroll
                    for (int mt = 0; mt < 2; mt++)
                        mma16816h(acc[mt][nt2 * 2 + sub], ap[mt], &bv[sub * 2]);
                }
            }
        }
        __syncthreads();
    }

#pragma unroll
    for (int mt = 0; mt < 2; mt++) {
#pragma unroll
        for (int nt = 0; nt < 8; nt++) {
            const int row = n0 + mt * 16 + (lane >> 2);
            const int col = wid * 64 + nt * 8 + (lane & 3) * 2;
#pragma unroll
            for (int half = 0; half < 2; half++) {
                *(float2*)&O[(size_t)(row + half * 8) * DIM + col] =
                    make_float2(acc[mt][nt][half * 2 + 0], acc[mt][nt][half * 2 + 1]);
            }
        }
    }
}

// ===================== LayerNorm ============================================
__global__ __launch_bounds__(256)
void ln_kernel(const float* __restrict__ X, const float* __restrict__ w,
               const float* __restrict__ b, float* __restrict__ out)
{
    const int n   = blockIdx.x;
    const int tid = threadIdx.x;
    const float4 x = ((const float4*)(X + (size_t)n * DIM))[tid];

    float s  = x.x + x.y + x.z + x.w;
    float ss = x.x * x.x + x.y * x.y + x.z * x.z + x.w * x.w;
#pragma unroll
    for (int off = 16; off; off >>= 1) {
        s  += __shfl_xor_sync(0xffffffffu, s, off);
        ss += __shfl_xor_sync(0xffffffffu, ss, off);
    }
    __shared__ float rs[8], rss[8], stat[2];
    if ((tid & 31) == 0) { rs[tid >> 5] = s; rss[tid >> 5] = ss; }
    __syncthreads();
    if (tid == 0) {
        float S = 0.f, SS = 0.f;
#pragma unroll
        for (int i = 0; i < 8; i++) { S += rs[i]; SS += rss[i]; }
        const float mean = S * (1.f / DIM);
        const float var  = SS * (1.f / DIM) - mean * mean;
        stat[0] = mean;
        stat[1] = rsqrtf(var + 1e-5f);
    }
    __syncthreads();
    const float mean = stat[0], inv = stat[1];
    const int col = tid * 4;
    const float4 wv = *(const float4*)&w[col];
    const float4 bv = *(const float4*)&b[col];
    float4 o;
    o.x = (x.x - mean) * inv * wv.x + bv.x;
    o.y = (x.y - mean) * inv * wv.y + bv.y;
    o.z = (x.z - mean) * inv * wv.z + bv.z;
    o.w = (x.w - mean) * inv * wv.w + bv.w;
    ((float4*)(out + (size_t)n * DIM))[tid] = o;
}

// ===================== coord MLP layer 2 ====================================
__global__ void mlp2_kernel(const float* __restrict__ T, const float* __restrict__ W2,
                            const float* __restrict__ b2, float* __restrict__ cw)
{
    const int warp = (blockIdx.x * blockDim.x + threadIdx.x) >> 5;
    const int lane = threadIdx.x & 31;
    if (warp >= N_TOK) return;
    const float* t = T + (size_t)warp * (DIM / 2);
    float s = 0.f;
#pragma unroll
    for (int j = 0; j < DIM / 2; j += 32) s = fmaf(t[j + lane], W2[j + lane], s);
#pragma unroll
    for (int off = 16; off; off >>= 1) s += __shfl_xor_sync(0xffffffffu, s, off);
    if (lane == 0) cw[warp] = s + b2[0];
}

// ===================== rel_pos mean =========================================
__global__ __launch_bounds__(128)
void relmean_kernel(const float* __restrict__ rel, float* __restrict__ out)
{
    const int n   = blockIdx.x;
    const int tid = threadIdx.x;
    const float* base = rel + (size_t)n * N_TOK * 3;
    float s0 = 0.f, s1 = 0.f, s2 = 0.f;
    for (int m = tid; m < N_TOK; m += 128) {
        s0 += base[m * 3 + 0];
        s1 += base[m * 3 + 1];
        s2 += base[m * 3 + 2];
    }
#pragma unroll
    for (int off = 16; off; off >>= 1) {
        s0 += __shfl_xor_sync(0xffffffffu, s0, off);
        s1 += __shfl_xor_sync(0xffffffffu, s1, off);
        s2 += __shfl_xor_sync(0xffffffffu, s2, off);
    }
    __shared__ float sm[3][4];
    if ((tid & 31) == 0) {
        sm[0][tid >> 5] = s0; sm[1][tid >> 5] = s1; sm[2][tid >> 5] = s2;
    }
    __syncthreads();
    if (tid == 0) {
        out[n * 3 + 0] = (sm[0][0] + sm[0][1] + sm[0][2] + sm[0][3]) * (1.f / N_TOK);
        out[n * 3 + 1] = (sm[1][0] + sm[1][1] + sm[1][2] + sm[1][3]) * (1.f / N_TOK);
        out[n * 3 + 2] = (sm[2][0] + sm[2][1] + sm[2][2] + sm[2][3]) * (1.f / N_TOK);
    }
}

// ===================== pos_update ===========================================
__global__ void posupd_kernel(const float* __restrict__ cw, const float* __restrict__ rm,
                              float* __restrict__ out)
{
    const int i = blockIdx.x * blockDim.x + threadIdx.x;
    if (i < N_TOK * 3) out[i] = cw[i / 3] * rm[i];
}

// ===================== launcher =============================================
extern "C" void kernel_launch(void* const* d_in, const int* in_sizes, int n_in,
                              void* d_out, int out_size)
{
    const float* h    = (const float*)d_in[0];
    const float* rel  = (const float*)d_in[1];
    const float* Wq   = (const float*)d_in[2];
    const float* bq   = (const float*)d_in[3];
    const float* Wk   = (const float*)d_in[4];
    const float* bk   = (const float*)d_in[5];
    const float* Wv   = (const float*)d_in[6];
    const float* bv   = (const float*)d_in[7];
    const float* Wo   = (const float*)d_in[8];
    const float* bo   = (const float*)d_in[9];
    const float* W1   = (const float*)d_in[10];
    const float* b1   = (const float*)d_in[11];
    const float* W2   = (const float*)d_in[12];
    const float* b2   = (const float*)d_in[13];
    const float* lnw  = (const float*)d_in[14];
    const float* lnb  = (const float*)d_in[15];
    float* out = (float*)d_out;

    float *attn, *x, *t, *cw, *rm;
    __half *s, *aq, *qq, *kq, *vq, *vtb;
    __half *wq16, *wk16, *wv16, *wo16, *w116;
    cudaGetSymbolAddress((void**)&attn, g_attn);
    cudaGetSymbolAddress((void**)&x,    g_x);
    cudaGetSymbolAddress((void**)&t,    g_t);
    cudaGetSymbolAddress((void**)&cw,   g_cw);
    cudaGetSymbolAddress((void**)&rm,   g_relmean);
    cudaGetSymbolAddress((void**)&s,    g_s);
    cudaGetSymbolAddress((void**)&aq,   g_aq);
    cudaGetSymbolAddress((void**)&qq,   g_qq);
    cudaGetSymbolAddress((void**)&kq,   g_kq);
    cudaGetSymbolAddress((void**)&vq,   g_vq);
    cudaGetSymbolAddress((void**)&vtb,  g_vtb);
    cudaGetSymbolAddress((void**)&wq16, g_wq16);
    cudaGetSymbolAddress((void**)&wk16, g_wk16);
    cudaGetSymbolAddress((void**)&wv16, g_wv16);
    cudaGetSymbolAddress((void**)&wo16, g_wo16);
    cudaGetSymbolAddress((void**)&w116, g_w116);

    cudaFuncSetAttribute(pv_mma,      cudaFuncAttributeMaxDynamicSharedMemorySize, PV_SMEM);
    cudaFuncSetAttribute(scores2,     cudaFuncAttributeMaxDynamicSharedMemorySize, SC_SMEM);
    cudaFuncSetAttribute(gemm_mma<1>, cudaFuncAttributeMaxDynamicSharedMemorySize, GEMM_SMEM);
    cudaFuncSetAttribute(gemm_mma<2>, cudaFuncAttributeMaxDynamicSharedMemorySize, GEMM_SMEM);
    cudaFuncSetAttribute(gemm_mma<4>, cudaFuncAttributeMaxDynamicSharedMemorySize, GEMM_SMEM);

    // independent: rel_pos mean
    relmean_kernel<<<N_TOK, 128>>>(rel, rm);

    // weight prep: transpose + fp16 convert
    trcvt<<<dim3(32, 32), dim3(32, 32)>>>(Wq, wq16, DIM, DIM);
    trcvt<<<dim3(32, 32), dim3(32, 32)>>>(Wk, wk16, DIM, DIM);
    trcvt<<<dim3(32, 32), dim3(32, 32)>>>(Wv, wv16, DIM, DIM);
    trcvt<<<dim3(32, 32), dim3(32, 32)>>>(Wo, wo16, DIM, DIM);
    trcvt<<<dim3(16, 32), dim3(32, 32)>>>(W1, w116, DIM, DIM / 2);

    // h -> fp16 A operand
    cvt16<<<(N_TOK * DIM / 4 + 255) / 256, 256>>>(h, aq, N_TOK * DIM / 4);

    // QKV: all fp16 single-plane, 1-pass
    gemm_mma<4><<<dim3(8, 32), 256, GEMM_SMEM>>>(aq, wq16, bq, nullptr, nullptr, qq, N_TOK, DIM, DIM);
    gemm_mma<4><<<dim3(8, 32), 256, GEMM_SMEM>>>(aq, wk16, bk, nullptr, nullptr, kq, N_TOK, DIM, DIM);
    gemm_mma<4><<<dim3(8, 32), 256, GEMM_SMEM>>>(aq, wv16, bv, nullptr, nullptr, vq, N_TOK, DIM, DIM);

    // block V for pv_mma staging
    vblock<<<N_TOK / 16, 512>>>(vq, vtb);

    // attention phase A: raw scores -> fp16 (1-pass fp16 MMA)
    scores2<<<dim3(32, 16), 256, SC_SMEM>>>(qq, kq, s);

    // attention phase C: softmax over heads + PV (1-pass fp16 MMA)
    pv_mma<<<N_TOK / 32, 512, PV_SMEM>>>(s, vtb, attn);

    // O projection + residual (fp16 A, fp16 W, fp32 out)
    cvt16<<<(N_TOK * DIM / 4 + 255) / 256, 256>>>(attn, aq, N_TOK * DIM / 4);
    gemm_mma<1><<<dim3(8, 32), 256, GEMM_SMEM>>>(aq, wo16, bo, h, x, nullptr, N_TOK, DIM, DIM);

    // layernorm -> hn
    ln_kernel<<<N_TOK, 256>>>(x, lnw, lnb, out);

    // coord MLP
    cvt16<<<(N_TOK * DIM / 4 + 255) / 256, 256>>>(out, aq, N_TOK * DIM / 4);
    gemm_mma<2><<<dim3(4, 32), 256, GEMM_SMEM>>>(aq, w116, b1, nullptr, t, nullptr, N_TOK, DIM / 2, DIM);
    mlp2_kernel<<<(N_TOK * 32) / 256, 256>>>(t, W2, b2, cw);

    // pos_update
    posupd_kernel<<<(N_TOK * 3 + 255) / 256, 256>>>(cw, rm, out + (size_t)N_TOK * DIM);
}